// round 8
// baseline (speedup 1.0000x reference)
#include <cuda_runtime.h>
#include <cuda_bf16.h>
#include <math.h>
#include <stdint.h>

#define H     2048
#define DIN   784
#define OUTR  9
#define KTOT  2048
#define KC    32
#define NCHUNK (KTOT / KC)          // 64
#define TILEB  8192                 // 128 rows * 64B (128x32 bf16)
#define STAGEB (4 * TILEB)          // 32KB: Ahi,Alo,Bhi,Blo
#define NSTAGE 3
#define DSMEM  (NSTAGE * STAGEB + 1024)
#define NPAD1  896                  // DIN padded to 128-multiple

// ---------------- scratch (device globals) ----------------------------------
__device__ float g_T[H * H];        // reused as 2x bf16 [H*H] for stage-3 split
__device__ __nv_bfloat16 g_Ahi[H * H], g_Alo[H * H];
__device__ __nv_bfloat16 g_W1t_hi[NPAD1 * KTOT], g_W1t_lo[NPAD1 * KTOT];  // pad rows stay 0
__device__ __nv_bfloat16 g_W2t_hi[H * KTOT], g_W2t_lo[H * KTOT];
__device__ float g_w1[H], g_bl1[H], g_bu1[H];
__device__ float g_w2[H], g_bl2[H], g_bu2[H];
__device__ float g_w3[H], g_bl3[H], g_bu3[H];
__device__ float g_cl[H], g_cu[H];
__device__ float g_m4a[OUTR * H], g_m4b[OUTR * H], g_m4c[OUTR * H], g_m4d[OUTR * H];
__device__ float g_bias4[OUTR];

// ---------------- PTX helpers ------------------------------------------------
__device__ __forceinline__ uint32_t smem_u32(const void* p) {
    uint32_t a;
    asm("{ .reg .u64 t; cvta.to.shared.u64 t, %1; cvt.u32.u64 %0, t; }" : "=r"(a) : "l"(p));
    return a;
}
#define SWZ64(o)   ((o) ^ (((o) >> 3) & 0x30))
#define CP_ASYNC16(dst, gsrc) \
    asm volatile("cp.async.cg.shared.global [%0], [%1], 16;" :: "r"(dst), "l"(gsrc))
#define CP_COMMIT() asm volatile("cp.async.commit_group;" ::: "memory")
#define CP_WAIT(n)  asm volatile("cp.async.wait_group %0;" :: "n"(n) : "memory")
#define LDSM_X4(r0, r1, r2, r3, addr) \
    asm volatile("ldmatrix.sync.aligned.m8n8.x4.shared.b16 {%0,%1,%2,%3}, [%4];" \
        : "=r"(r0), "=r"(r1), "=r"(r2), "=r"(r3) : "r"(addr))
#define MMA16816(d, a, b) \
    asm volatile("mma.sync.aligned.m16n8k16.row.col.f32.bf16.bf16.f32 " \
        "{%0,%1,%2,%3}, {%4,%5,%6,%7}, {%8,%9}, {%0,%1,%2,%3};" \
        : "+f"((d)[0]), "+f"((d)[1]), "+f"((d)[2]), "+f"((d)[3]) \
        : "r"((a)[0]), "r"((a)[1]), "r"((a)[2]), "r"((a)[3]), "r"((b)[0]), "r"((b)[1]))

// ---------------- misc helpers ----------------------------------------------
__device__ __forceinline__ float spu_f(float x) {
    if (x >= 0.f) return x * x - 0.5f;
    float s = 1.f / (1.f + expf(x));
    return s - 1.f;
}
__device__ __forceinline__ float dspu_f(float x) {
    if (x >= 0.f) return 2.f * x;
    float s = 1.f / (1.f + expf(x));
    return -s * (1.f - s);
}
// compute SPU relaxation params for bounds [l,u] with learned params pl,pu
__device__ __forceinline__ void spu_relax(float l, float u, float pl, float pu,
                                          float &w_, float &bl_, float &bu_) {
    float k1 = dspu_f(l), k2 = dspu_f(u);
    float klo = fminf(k1, k2), khi = fmaxf(k1, k2);
    float wl = fminf(fmaxf(pl, klo), khi);
    float wu = fminf(fmaxf(pu, klo), khi);
    float p0 = l, p1 = u, p2 = 0.5f * (l + u), p3 = fminf(fmaxf(0.f, l), u);
    float s0 = spu_f(p0), s1 = spu_f(p1), s2 = spu_f(p2), s3 = spu_f(p3);
    bl_ = fminf(fminf(s0 - wl * p0, s1 - wl * p1), fminf(s2 - wl * p2, s3 - wl * p3));
    bu_ = fmaxf(fmaxf(s0 - wu * p0, s1 - wu * p1), fmaxf(s2 - wu * p2, s3 - wu * p3));
    w_ = wl;
}
__device__ __forceinline__ void blk_reduce2(float &a, float &b) {
    const unsigned m = 0xffffffffu;
    #pragma unroll
    for (int o = 16; o > 0; o >>= 1) {
        a += __shfl_down_sync(m, a, o);
        b += __shfl_down_sync(m, b, o);
    }
    __shared__ float sa[8], sb[8];
    int w = threadIdx.x >> 5, l = threadIdx.x & 31;
    int nw = blockDim.x >> 5;
    if (l == 0) { sa[w] = a; sb[w] = b; }
    __syncthreads();
    if (w == 0) {
        a = (l < nw) ? sa[l] : 0.f;
        b = (l < nw) ? sb[l] : 0.f;
        #pragma unroll
        for (int o = 4; o > 0; o >>= 1) {
            a += __shfl_down_sync(m, a, o);
            b += __shfl_down_sync(m, b, o);
        }
    }
}

// ---------------- fused stage-1: concretize W1 row + SPU params --------------
__global__ void concretize_spu_k(const float* __restrict__ W1v,
                                 const float* __restrict__ lin, const float* __restrict__ uin,
                                 const float* __restrict__ b1v,
                                 const float* __restrict__ pl, const float* __restrict__ pu,
                                 float* __restrict__ w, float* __restrict__ bl,
                                 float* __restrict__ bu) {
    int row = blockIdx.x;
    const float* a = W1v + (size_t)row * DIN;
    float al = 0.f, au = 0.f;
    for (int j = threadIdx.x; j < DIN; j += blockDim.x) {
        float v = a[j], l = lin[j], u = uin[j];
        float p = fmaxf(v, 0.f), n = fminf(v, 0.f);
        al += p * l + n * u;
        au += p * u + n * l;
    }
    blk_reduce2(al, au);
    if (threadIdx.x == 0) {
        float l = al + b1v[row], u = au + b1v[row];
        float w_, bl_, bu_;
        spu_relax(l, u, pl[row], pu[row], w_, bl_, bu_);
        w[row] = w_; bl[row] = bl_; bu[row] = bu_;
    }
}

__global__ void spu_params_k(const float* __restrict__ lf, const float* __restrict__ uf,
                             const float* __restrict__ pl, const float* __restrict__ pu,
                             float* __restrict__ w, float* __restrict__ bl,
                             float* __restrict__ bu, int n) {
    int i = blockIdx.x * blockDim.x + threadIdx.x;
    if (i >= n) return;
    float w_, bl_, bu_;
    spu_relax(lf[i], uf[i], pl[i], pu[i], w_, bl_, bu_);
    w[i] = w_; bl[i] = bl_; bu[i] = bu_;
}

// bias for (W .* wprev) stage, fused with bf16 hi/lo split of M = W .* wprev
__global__ void bias2conv_k(const float* __restrict__ W,
                            const float* __restrict__ wprev,
                            const float* __restrict__ blprev, const float* __restrict__ buprev,
                            const float* __restrict__ bthis, const float* __restrict__ bprev,
                            float* __restrict__ cl, float* __restrict__ cu,
                            __nv_bfloat16* __restrict__ hi, __nv_bfloat16* __restrict__ lo) {
    int row = blockIdx.x;
    const float* wr = W + (size_t)row * H;
    __nv_bfloat16* hr = hi + (size_t)row * H;
    __nv_bfloat16* lr = lo + (size_t)row * H;
    float al = 0.f, au = 0.f;
    for (int j = threadIdx.x; j < H; j += blockDim.x) {
        float v = wr[j];
        float p = fmaxf(v, 0.f), n = fminf(v, 0.f);
        float m = v * wprev[j];
        al += p * blprev[j] + n * buprev[j] + m * bprev[j];
        au += p * buprev[j] + n * blprev[j] + m * bprev[j];
        __nv_bfloat16 h = __float2bfloat16(m);
        hr[j] = h;
        lr[j] = __float2bfloat16(m - __bfloat162float(h));
    }
    blk_reduce2(al, au);
    if (threadIdx.x == 0) { cl[row] = bthis[row] + al; cu[row] = bthis[row] + au; }
}

// B [K x N] fp32 row-major -> Bt_hi/lo [Npad x K] bf16 (rows >= N stay zero)
__global__ void transp_conv_k(const float* __restrict__ B, int N,
                              __nv_bfloat16* __restrict__ thi, __nv_bfloat16* __restrict__ tlo) {
    __shared__ float t[32][33];
    int k0 = blockIdx.x * 32, n0 = blockIdx.y * 32;
    int x = threadIdx.x, y = threadIdx.y;       // 32 x 8
    for (int yy = y; yy < 32; yy += 8) {
        int n = n0 + x;
        t[yy][x] = (n < N) ? B[(size_t)(k0 + yy) * N + n] : 0.f;
    }
    __syncthreads();
    for (int yy = y; yy < 32; yy += 8) {
        int n = n0 + yy, k = k0 + x;
        if (n < N) {
            float v = t[x][yy];
            __nv_bfloat16 h = __float2bfloat16(v);
            thi[(size_t)n * KTOT + k] = h;
            tlo[(size_t)n * KTOT + k] = __float2bfloat16(v - __bfloat162float(h));
        }
    }
}

// ---------------- mma.sync split-bf16 GEMM, 3-stage cp.async pipeline --------
template <int MODE>
__global__ __launch_bounds__(256, 2)
void gemm_mma_k(const __nv_bfloat16* __restrict__ Ahi, const __nv_bfloat16* __restrict__ Alo,
                const __nv_bfloat16* __restrict__ Bhi, const __nv_bfloat16* __restrict__ Blo,
                __nv_bfloat16* __restrict__ Ohi, __nv_bfloat16* __restrict__ Olo,
                const float* __restrict__ scale, const float* __restrict__ bvec,
                const float* __restrict__ blv, const float* __restrict__ buv,
                float* __restrict__ cl, float* __restrict__ cu,
                const float* __restrict__ lin, const float* __restrict__ uin) {
    extern __shared__ char dsm[];
    uint32_t raw = smem_u32(dsm);
    uint32_t dbase = (raw + 1023) & ~1023u;

    int tid = threadIdx.x, wid = tid >> 5, lane = tid & 31;
    int brow = blockIdx.y * 128, bcol = blockIdx.x * 128;
    int wm = (wid >> 2) * 64, wn = (wid & 3) * 32;

    const __nv_bfloat16* gbase[4] = {
        Ahi + (size_t)brow * KTOT, Alo + (size_t)brow * KTOT,
        Bhi + (size_t)bcol * KTOT, Blo + (size_t)bcol * KTOT };
    const __nv_bfloat16* gsrc[8];
    uint32_t sdst[8];
    #pragma unroll
    for (int i = 0; i < 8; i++) {
        int s = i * 256 + tid;
        int t = s >> 9, row = (s >> 2) & 127, sg = s & 3;
        gsrc[i] = gbase[t] + (size_t)row * KTOT + sg * 8;
        sdst[i] = (uint32_t)(t * TILEB) + SWZ64((uint32_t)(row * 64 + sg * 16));
    }

    float acc[4][4][4];
    #pragma unroll
    for (int mt = 0; mt < 4; mt++)
        #pragma unroll
        for (int nt = 0; nt < 4; nt++)
            #pragma unroll
            for (int q = 0; q < 4; q++) acc[mt][nt][q] = 0.f;

    int l15 = lane & 15, lhi = lane >> 4;

    #pragma unroll
    for (int st = 0; st < 2; st++) {
        uint32_t sb = dbase + st * STAGEB;
        int k0 = st * KC;
        #pragma unroll
        for (int i = 0; i < 8; i++) CP_ASYNC16(sb + sdst[i], gsrc[i] + k0);
        CP_COMMIT();
    }

    int stage = 0;
    for (int chunk = 0; chunk < NCHUNK; chunk++) {
        if (chunk + 2 < NCHUNK) {
            int ns = stage + 2; if (ns >= NSTAGE) ns -= NSTAGE;
            uint32_t sb = dbase + ns * STAGEB;
            int k0 = (chunk + 2) * KC;
            #pragma unroll
            for (int i = 0; i < 8; i++) CP_ASYNC16(sb + sdst[i], gsrc[i] + k0);
            CP_COMMIT();
            CP_WAIT(2);
        } else if (chunk + 1 < NCHUNK) {
            CP_WAIT(1);
        } else {
            CP_WAIT(0);
        }
        __syncthreads();

        uint32_t ah_b = dbase + stage * STAGEB;
        uint32_t al_b = ah_b + TILEB, bh_b = ah_b + 2 * TILEB, bl_b = ah_b + 3 * TILEB;

        #pragma unroll
        for (int kb = 0; kb < 2; kb++) {
            uint32_t kbyte = (uint32_t)(kb * 32 + lhi * 16);
            uint32_t ahi_f[4][4], alo_f[4][4];
            #pragma unroll
            for (int mt = 0; mt < 4; mt++) {
                uint32_t off = SWZ64((uint32_t)((wm + mt * 16 + l15) * 64) + kbyte);
                LDSM_X4(ahi_f[mt][0], ahi_f[mt][1], ahi_f[mt][2], ahi_f[mt][3], ah_b + off);
                LDSM_X4(alo_f[mt][0], alo_f[mt][1], alo_f[mt][2], alo_f[mt][3], al_b + off);
            }
            #pragma unroll
            for (int p = 0; p < 2; p++) {
                uint32_t off = SWZ64((uint32_t)((wn + p * 16 + l15) * 64) + kbyte);
                uint32_t r0, r1, r2, r3;
                uint32_t bhi0[2], bhi1[2], blo0[2], blo1[2];
                LDSM_X4(r0, r1, r2, r3, bh_b + off);
                bhi0[0] = r0; bhi0[1] = r2; bhi1[0] = r1; bhi1[1] = r3;
                LDSM_X4(r0, r1, r2, r3, bl_b + off);
                blo0[0] = r0; blo0[1] = r2; blo1[0] = r1; blo1[1] = r3;
                #pragma unroll
                for (int mt = 0; mt < 4; mt++) {
                    MMA16816(acc[mt][2 * p], ahi_f[mt], bhi0);
                    MMA16816(acc[mt][2 * p], ahi_f[mt], blo0);
                    MMA16816(acc[mt][2 * p], alo_f[mt], bhi0);
                    MMA16816(acc[mt][2 * p + 1], ahi_f[mt], bhi1);
                    MMA16816(acc[mt][2 * p + 1], ahi_f[mt], blo1);
                    MMA16816(acc[mt][2 * p + 1], alo_f[mt], bhi1);
                }
            }
        }
        __syncthreads();
        stage++; if (stage >= NSTAGE) stage -= NSTAGE;
    }

    // ---- fused epilogue ----
    #pragma unroll
    for (int mt = 0; mt < 4; mt++) {
        #pragma unroll
        for (int q = 0; q < 2; q++) {
            int gr = brow + wm + mt * 16 + (lane >> 2) + q * 8;
            float pl = 0.f, pu = 0.f;
            #pragma unroll
            for (int nt = 0; nt < 4; nt++) {
                int gc = bcol + wn + nt * 8 + (lane & 3) * 2;
                float v0 = acc[mt][nt][q * 2 + 0];
                float v1 = acc[mt][nt][q * 2 + 1];
                if (MODE == 0) {
                    float m0 = v0 * scale[gc], m1 = v1 * scale[gc + 1];
                    __nv_bfloat16 h0 = __float2bfloat16(m0);
                    __nv_bfloat16 h1 = __float2bfloat16(m1);
                    __nv_bfloat162 hv; hv.x = h0; hv.y = h1;
                    *(__nv_bfloat162*)(Ohi + (size_t)gr * H + gc) = hv;
                    __nv_bfloat162 lv;
                    lv.x = __float2bfloat16(m0 - __bfloat162float(h0));
                    lv.y = __float2bfloat16(m1 - __bfloat162float(h1));
                    *(__nv_bfloat162*)(Olo + (size_t)gr * H + gc) = lv;
                    float p0 = fmaxf(v0, 0.f), n0 = fminf(v0, 0.f);
                    float p1 = fmaxf(v1, 0.f), n1 = fminf(v1, 0.f);
                    float sb = m0 * bvec[gc] + m1 * bvec[gc + 1];
                    pl += p0 * blv[gc] + n0 * buv[gc] + p1 * blv[gc + 1] + n1 * buv[gc + 1] + sb;
                    pu += p0 * buv[gc] + n0 * blv[gc] + p1 * buv[gc + 1] + n1 * blv[gc + 1] + sb;
                } else {
                    if (gc < DIN) {
                        float l0 = lin[gc], u0 = uin[gc];
                        float l1 = lin[gc + 1], u1 = uin[gc + 1];
                        float p0 = fmaxf(v0, 0.f), n0 = fminf(v0, 0.f);
                        float p1 = fmaxf(v1, 0.f), n1 = fminf(v1, 0.f);
                        pl += p0 * l0 + n0 * u0 + p1 * l1 + n1 * u1;
                        pu += p0 * u0 + n0 * l0 + p1 * u1 + n1 * l1;
                    }
                }
            }
            pl += __shfl_xor_sync(0xffffffffu, pl, 1);
            pl += __shfl_xor_sync(0xffffffffu, pl, 2);
            pu += __shfl_xor_sync(0xffffffffu, pu, 1);
            pu += __shfl_xor_sync(0xffffffffu, pu, 2);
            if ((lane & 3) == 0) {
                atomicAdd(&cl[gr], pl);
                atomicAdd(&cu[gr], pu);
            }
        }
    }
}

// ---------------- output stage (9 rows) ---------------------------------------
__global__ void build_m4_k(const float* __restrict__ W4, const float* __restrict__ b4,
                           const int* __restrict__ tl, float* __restrict__ M,
                           float* __restrict__ bias) {
    int t = *tl;
    int idx = blockIdx.x * blockDim.x + threadIdx.x;
    if (idx < OUTR * H) {
        int r = idx / H, j = idx % H;
        int c = (r < t) ? r : r + 1;
        M[idx] = W4[(size_t)c * H + j] - W4[(size_t)t * H + j];
    }
    if (idx < OUTR) {
        int c = (idx < t) ? idx : idx + 1;
        bias[idx] = b4[c] - b4[t];
    }
}

__global__ void zero_all_k(float* __restrict__ a, float* __restrict__ b,
                           float* __restrict__ c, int n) {
    int i = blockIdx.x * blockDim.x + threadIdx.x;
    if (i < n) { a[i] = 0.f; b[i] = 0.f; c[i] = 0.f; }
}

// C[OUTR x N] += (A .* ascale) @ B, split-K; blockIdx.x==0 CTAs also accumulate
// bias4[r] += sum_k pos(a)*bu[k] + neg(a)*bl[k] + a*ascale[k]*bvec[k]
#define SG_CHUNK 256
__global__ void small_gemm_k(int K, int N, const float* __restrict__ A,
                             const float* __restrict__ ascale,
                             const float* __restrict__ B, float* __restrict__ C,
                             const float* __restrict__ blv, const float* __restrict__ buv,
                             const float* __restrict__ bvec, float* __restrict__ bias4) {
    __shared__ float sA[OUTR * SG_CHUNK];
    __shared__ float sbias[OUTR];
    int k0 = blockIdx.y * SG_CHUNK;
    int n = blockIdx.x * blockDim.x + threadIdx.x;
    bool do_bias = (blockIdx.x == 0);
    if (do_bias && threadIdx.x < OUTR) sbias[threadIdx.x] = 0.f;
    if (do_bias) __syncthreads();
    for (int idx = threadIdx.x; idx < OUTR * SG_CHUNK; idx += blockDim.x) {
        int r = idx / SG_CHUNK, kk = idx % SG_CHUNK;
        int k = k0 + kk;
        float a = A[(size_t)r * K + k];
        float s = a * ascale[k];
        sA[idx] = s;
        if (do_bias) {
            float p = fmaxf(a, 0.f), ng = fminf(a, 0.f);
            atomicAdd(&sbias[r], p * buv[k] + ng * blv[k] + s * bvec[k]);
        }
    }
    __syncthreads();
    if (do_bias && threadIdx.x < OUTR)
        atomicAdd(&bias4[threadIdx.x], sbias[threadIdx.x]);
    if (n >= N) return;
    float acc[OUTR];
    #pragma unroll
    for (int r = 0; r < OUTR; r++) acc[r] = 0.f;
    #pragma unroll 4
    for (int kk = 0; kk < SG_CHUNK; kk++) {
        float bv = B[(size_t)(k0 + kk) * N + n];
        #pragma unroll
        for (int r = 0; r < OUTR; r++) acc[r] += sA[r * SG_CHUNK + kk] * bv;
    }
    #pragma unroll
    for (int r = 0; r < OUTR; r++) atomicAdd(&C[(size_t)r * N + n], acc[r]);
}

__global__ void final_k(const float* __restrict__ M, const float* __restrict__ lin,
                        const float* __restrict__ uin, const float* __restrict__ bias,
                        float* __restrict__ out) {
    int r = blockIdx.x;
    const float* a = M + (size_t)r * DIN;
    float au = 0.f, dummy = 0.f;
    for (int j = threadIdx.x; j < DIN; j += blockDim.x) {
        float v = a[j];
        au += fmaxf(v, 0.f) * uin[j] + fminf(v, 0.f) * lin[j];
    }
    blk_reduce2(au, dummy);
    if (threadIdx.x == 0) out[r] = au + bias[r];
}

// ---------------- launch ------------------------------------------------------
extern "C" void kernel_launch(void* const* d_in, const int* in_sizes, int n_in,
                              void* d_out, int out_size) {
    const float* W1 = (const float*)d_in[0];
    const float* b1 = (const float*)d_in[1];
    const float* W2 = (const float*)d_in[2];
    const float* b2 = (const float*)d_in[3];
    const float* W3 = (const float*)d_in[4];
    const float* b3 = (const float*)d_in[5];
    const float* W4 = (const float*)d_in[6];
    const float* b4 = (const float*)d_in[7];
    const float* l_in = (const float*)d_in[8];
    const float* u_in = (const float*)d_in[9];
    const float* p_l1 = (const float*)d_in[10];
    const float* p_u1 = (const float*)d_in[11];
    const float* p_l2 = (const float*)d_in[12];
    const float* p_u2 = (const float*)d_in[13];
    const float* p_l3 = (const float*)d_in[14];
    const float* p_u3 = (const float*)d_in[15];
    const int* tl = (const int*)d_in[16];
    float* out = (float*)d_out;

    cudaFuncSetAttribute(gemm_mma_k<0>, cudaFuncAttributeMaxDynamicSharedMemorySize, DSMEM);
    cudaFuncSetAttribute(gemm_mma_k<1>, cudaFuncAttributeMaxDynamicSharedMemorySize, DSMEM);

    float *T, *w1, *bl1, *bu1, *w2, *bl2, *bu2, *w3, *bl3, *bu3, *cl, *cu;
    float *m4a, *m4b, *m4c, *m4d, *bias4;
    __nv_bfloat16 *Ahi, *Alo, *W1th, *W1tl, *W2th, *W2tl;
    cudaGetSymbolAddress((void**)&T, g_T);
    cudaGetSymbolAddress((void**)&Ahi, g_Ahi);   cudaGetSymbolAddress((void**)&Alo, g_Alo);
    cudaGetSymbolAddress((void**)&W1th, g_W1t_hi); cudaGetSymbolAddress((void**)&W1tl, g_W1t_lo);
    cudaGetSymbolAddress((void**)&W2th, g_W2t_hi); cudaGetSymbolAddress((void**)&W2tl, g_W2t_lo);
    cudaGetSymbolAddress((void**)&w1, g_w1);   cudaGetSymbolAddress((void**)&bl1, g_bl1);
    cudaGetSymbolAddress((void**)&bu1, g_bu1);
    cudaGetSymbolAddress((void**)&w2, g_w2);   cudaGetSymbolAddress((void**)&bl2, g_bl2);
    cudaGetSymbolAddress((void**)&bu2, g_bu2);
    cudaGetSymbolAddress((void**)&w3, g_w3);   cudaGetSymbolAddress((void**)&bl3, g_bl3);
    cudaGetSymbolAddress((void**)&bu3, g_bu3);
    cudaGetSymbolAddress((void**)&cl, g_cl);   cudaGetSymbolAddress((void**)&cu, g_cu);
    cudaGetSymbolAddress((void**)&m4a, g_m4a); cudaGetSymbolAddress((void**)&m4b, g_m4b);
    cudaGetSymbolAddress((void**)&m4c, g_m4c); cudaGetSymbolAddress((void**)&m4d, g_m4d);
    cudaGetSymbolAddress((void**)&bias4, g_bias4);

    __nv_bfloat16* Thi = (__nv_bfloat16*)T;
    __nv_bfloat16* Tlo = ((__nv_bfloat16*)T) + (size_t)H * H;

    // ---- up-front: scratch zeroing, output-row build, B transposes ----
    zero_all_k<<<(OUTR * H + 255) / 256, 256>>>(m4b, m4c, m4d, OUTR * H);
    build_m4_k<<<(OUTR * H + 255) / 256, 256>>>(W4, b4, tl, m4a, bias4);
    transp_conv_k<<<dim3(KTOT / 32, (DIN + 31) / 32), dim3(32, 8)>>>(W1, DIN, W1th, W1tl);
    transp_conv_k<<<dim3(KTOT / 32, H / 32), dim3(32, 8)>>>(W2, H, W2th, W2tl);

    dim3 gmid(NPAD1 / 128, H / 128);         // 7 x 16
    dim3 gbig(H / 128, H / 128);             // 16 x 16

    // ---- stage 1 (fused concretize + spu) ----
    concretize_spu_k<<<H, 256>>>(W1, l_in, u_in, b1, p_l1, p_u1, w1, bl1, bu1);

    // ---- stage 2 ----
    bias2conv_k<<<H, 256>>>(W2, w1, bl1, bu1, b2, b1, cl, cu, Ahi, Alo);
    gemm_mma_k<1><<<gmid, 256, DSMEM>>>(Ahi, Alo, W1th, W1tl, nullptr, nullptr,
                                        nullptr, nullptr, nullptr, nullptr,
                                        cl, cu, l_in, u_in);
    spu_params_k<<<(H + 63) / 64, 64>>>(cl, cu, p_l2, p_u2, w2, bl2, bu2, H);

    // ---- stage 3 ----
    bias2conv_k<<<H, 256>>>(W3, w2, bl2, bu2, b3, b2, cl, cu, Ahi, Alo);
    gemm_mma_k<0><<<gbig, 256, DSMEM>>>(Ahi, Alo, W2th, W2tl, Thi, Tlo,
                                        w1, b1, bl1, bu1, cl, cu, nullptr, nullptr);
    gemm_mma_k<1><<<gmid, 256, DSMEM>>>(Thi, Tlo, W1th, W1tl, nullptr, nullptr,
                                        nullptr, nullptr, nullptr, nullptr,
                                        cl, cu, l_in, u_in);
    spu_params_k<<<(H + 63) / 64, 64>>>(cl, cu, p_l3, p_u3, w3, bl3, bu3, H);

    // ---- stage 4: output chain (9 rows), bias fused into split-K GEMMs ----
    small_gemm_k<<<dim3((H + 127) / 128, H / SG_CHUNK), 128>>>(
        H, H, m4a, w3, W3, m4b, bl3, bu3, b3, bias4);
    small_gemm_k<<<dim3((H + 127) / 128, H / SG_CHUNK), 128>>>(
        H, H, m4b, w2, W2, m4c, bl2, bu2, b2, bias4);
    small_gemm_k<<<dim3((DIN + 127) / 128, H / SG_CHUNK), 128>>>(
        H, DIN, m4c, w1, W1, m4d, bl1, bu1, b1, bias4);
    final_k<<<OUTR, 256>>>(m4d, l_in, u_in, bias4, out);
}

// round 9
// speedup vs baseline: 1.3224x; 1.3224x over previous
#include <cuda_runtime.h>
#include <cuda_bf16.h>
#include <math.h>
#include <stdint.h>

#define H     2048
#define DIN   784
#define OUTR  9
#define KTOT  2048
#define KC    32
#define NCHUNK (KTOT / KC)          // 64
#define TILEB  8192                 // 128 rows * 64B (128x32 bf16)
#define STAGEB (4 * TILEB)          // 32KB: Ahi,Alo,Bhi,Blo
#define NSTAGE 3
#define DSMEM  (NSTAGE * STAGEB + 1024)
#define NPAD1  896                  // DIN padded to 128-multiple

// ---------------- scratch (device globals) ----------------------------------
__device__ float g_T[H * H];        // reused as 2x bf16 [H*H] for stage-3 split
__device__ __nv_bfloat16 g_Ahi[H * H], g_Alo[H * H];
__device__ __nv_bfloat16 g_W1t_hi[NPAD1 * KTOT], g_W1t_lo[NPAD1 * KTOT];  // pad rows stay 0
__device__ __nv_bfloat16 g_W2t_hi[H * KTOT], g_W2t_lo[H * KTOT];
__device__ float g_w1[H], g_bl1[H], g_bu1[H];
__device__ float g_w2[H], g_bl2[H], g_bu2[H];
__device__ float g_w3[H], g_bl3[H], g_bu3[H];
__device__ float g_cl[H], g_cu[H];
__device__ float g_m4a[OUTR * H], g_m4b[OUTR * H];
__device__ float g_bias4[OUTR];

// ---------------- PTX helpers ------------------------------------------------
__device__ __forceinline__ uint32_t smem_u32(const void* p) {
    uint32_t a;
    asm("{ .reg .u64 t; cvta.to.shared.u64 t, %1; cvt.u32.u64 %0, t; }" : "=r"(a) : "l"(p));
    return a;
}
#define SWZ64(o)   ((o) ^ (((o) >> 3) & 0x30))
#define CP_ASYNC16(dst, gsrc) \
    asm volatile("cp.async.cg.shared.global [%0], [%1], 16;" :: "r"(dst), "l"(gsrc))
#define CP_COMMIT() asm volatile("cp.async.commit_group;" ::: "memory")
#define CP_WAIT(n)  asm volatile("cp.async.wait_group %0;" :: "n"(n) : "memory")
#define LDSM_X4(r0, r1, r2, r3, addr) \
    asm volatile("ldmatrix.sync.aligned.m8n8.x4.shared.b16 {%0,%1,%2,%3}, [%4];" \
        : "=r"(r0), "=r"(r1), "=r"(r2), "=r"(r3) : "r"(addr))
#define MMA16816(d, a, b) \
    asm volatile("mma.sync.aligned.m16n8k16.row.col.f32.bf16.bf16.f32 " \
        "{%0,%1,%2,%3}, {%4,%5,%6,%7}, {%8,%9}, {%0,%1,%2,%3};" \
        : "+f"((d)[0]), "+f"((d)[1]), "+f"((d)[2]), "+f"((d)[3]) \
        : "r"((a)[0]), "r"((a)[1]), "r"((a)[2]), "r"((a)[3]), "r"((b)[0]), "r"((b)[1]))

// ---------------- misc helpers ----------------------------------------------
__device__ __forceinline__ float spu_f(float x) {
    if (x >= 0.f) return x * x - 0.5f;
    float s = 1.f / (1.f + expf(x));
    return s - 1.f;
}
__device__ __forceinline__ float dspu_f(float x) {
    if (x >= 0.f) return 2.f * x;
    float s = 1.f / (1.f + expf(x));
    return -s * (1.f - s);
}
__device__ __forceinline__ void spu_relax(float l, float u, float pl, float pu,
                                          float &w_, float &bl_, float &bu_) {
    float k1 = dspu_f(l), k2 = dspu_f(u);
    float klo = fminf(k1, k2), khi = fmaxf(k1, k2);
    float wl = fminf(fmaxf(pl, klo), khi);
    float wu = fminf(fmaxf(pu, klo), khi);
    float p0 = l, p1 = u, p2 = 0.5f * (l + u), p3 = fminf(fmaxf(0.f, l), u);
    float s0 = spu_f(p0), s1 = spu_f(p1), s2 = spu_f(p2), s3 = spu_f(p3);
    bl_ = fminf(fminf(s0 - wl * p0, s1 - wl * p1), fminf(s2 - wl * p2, s3 - wl * p3));
    bu_ = fmaxf(fmaxf(s0 - wu * p0, s1 - wu * p1), fmaxf(s2 - wu * p2, s3 - wu * p3));
    w_ = wl;
}
__device__ __forceinline__ void blk_reduce2(float &a, float &b) {
    const unsigned m = 0xffffffffu;
    #pragma unroll
    for (int o = 16; o > 0; o >>= 1) {
        a += __shfl_down_sync(m, a, o);
        b += __shfl_down_sync(m, b, o);
    }
    __shared__ float sa[8], sb[8];
    int w = threadIdx.x >> 5, l = threadIdx.x & 31;
    int nw = blockDim.x >> 5;
    if (l == 0) { sa[w] = a; sb[w] = b; }
    __syncthreads();
    if (w == 0) {
        a = (l < nw) ? sa[l] : 0.f;
        b = (l < nw) ? sb[l] : 0.f;
        #pragma unroll
        for (int o = 4; o > 0; o >>= 1) {
            a += __shfl_down_sync(m, a, o);
            b += __shfl_down_sync(m, b, o);
        }
    }
}

// ---------------- fused stage-1: concretize W1 row + SPU params --------------
__global__ void concretize_spu_k(const float* __restrict__ W1v,
                                 const float* __restrict__ lin, const float* __restrict__ uin,
                                 const float* __restrict__ b1v,
                                 const float* __restrict__ pl, const float* __restrict__ pu,
                                 float* __restrict__ w, float* __restrict__ bl,
                                 float* __restrict__ bu) {
    int row = blockIdx.x;
    const float* a = W1v + (size_t)row * DIN;
    float al = 0.f, au = 0.f;
    for (int j = threadIdx.x; j < DIN; j += blockDim.x) {
        float v = a[j], l = lin[j], u = uin[j];
        float p = fmaxf(v, 0.f), n = fminf(v, 0.f);
        al += p * l + n * u;
        au += p * u + n * l;
    }
    blk_reduce2(al, au);
    if (threadIdx.x == 0) {
        float l = al + b1v[row], u = au + b1v[row];
        float w_, bl_, bu_;
        spu_relax(l, u, pl[row], pu[row], w_, bl_, bu_);
        w[row] = w_; bl[row] = bl_; bu[row] = bu_;
    }
}

__global__ void spu_params_k(const float* __restrict__ lf, const float* __restrict__ uf,
                             const float* __restrict__ pl, const float* __restrict__ pu,
                             float* __restrict__ w, float* __restrict__ bl,
                             float* __restrict__ bu, int n) {
    int i = blockIdx.x * blockDim.x + threadIdx.x;
    if (i >= n) return;
    float w_, bl_, bu_;
    spu_relax(lf[i], uf[i], pl[i], pu[i], w_, bl_, bu_);
    w[i] = w_; bl[i] = bl_; bu[i] = bu_;
}

// bias for (W .* wprev) stage, fused with bf16 hi/lo split of M = W .* wprev
__global__ void bias2conv_k(const float* __restrict__ W,
                            const float* __restrict__ wprev,
                            const float* __restrict__ blprev, const float* __restrict__ buprev,
                            const float* __restrict__ bthis, const float* __restrict__ bprev,
                            float* __restrict__ cl, float* __restrict__ cu,
                            __nv_bfloat16* __restrict__ hi, __nv_bfloat16* __restrict__ lo) {
    int row = blockIdx.x;
    const float* wr = W + (size_t)row * H;
    __nv_bfloat16* hr = hi + (size_t)row * H;
    __nv_bfloat16* lr = lo + (size_t)row * H;
    float al = 0.f, au = 0.f;
    for (int j = threadIdx.x; j < H; j += blockDim.x) {
        float v = wr[j];
        float p = fmaxf(v, 0.f), n = fminf(v, 0.f);
        float m = v * wprev[j];
        al += p * blprev[j] + n * buprev[j] + m * bprev[j];
        au += p * buprev[j] + n * blprev[j] + m * bprev[j];
        __nv_bfloat16 h = __float2bfloat16(m);
        hr[j] = h;
        lr[j] = __float2bfloat16(m - __bfloat162float(h));
    }
    blk_reduce2(al, au);
    if (threadIdx.x == 0) { cl[row] = bthis[row] + al; cu[row] = bthis[row] + au; }
}

// B [K x N] fp32 row-major -> Bt_hi/lo [Npad x K] bf16 (rows >= N stay zero)
__global__ void transp_conv_k(const float* __restrict__ B, int N,
                              __nv_bfloat16* __restrict__ thi, __nv_bfloat16* __restrict__ tlo) {
    __shared__ float t[32][33];
    int k0 = blockIdx.x * 32, n0 = blockIdx.y * 32;
    int x = threadIdx.x, y = threadIdx.y;       // 32 x 8
    for (int yy = y; yy < 32; yy += 8) {
        int n = n0 + x;
        t[yy][x] = (n < N) ? B[(size_t)(k0 + yy) * N + n] : 0.f;
    }
    __syncthreads();
    for (int yy = y; yy < 32; yy += 8) {
        int n = n0 + yy, k = k0 + x;
        if (n < N) {
            float v = t[x][yy];
            __nv_bfloat16 h = __float2bfloat16(v);
            thi[(size_t)n * KTOT + k] = h;
            tlo[(size_t)n * KTOT + k] = __float2bfloat16(v - __bfloat162float(h));
        }
    }
}

// ---------------- mma.sync split-bf16 GEMM, 3-stage cp.async pipeline --------
// wait -> barrier -> issue-next -> compute : single __syncthreads per chunk.
template <int MODE>
__global__ __launch_bounds__(256, 2)
void gemm_mma_k(const __nv_bfloat16* __restrict__ Ahi, const __nv_bfloat16* __restrict__ Alo,
                const __nv_bfloat16* __restrict__ Bhi, const __nv_bfloat16* __restrict__ Blo,
                __nv_bfloat16* __restrict__ Ohi, __nv_bfloat16* __restrict__ Olo,
                const float* __restrict__ scale, const float* __restrict__ bvec,
                const float* __restrict__ blv, const float* __restrict__ buv,
                float* __restrict__ cl, float* __restrict__ cu,
                const float* __restrict__ lin, const float* __restrict__ uin) {
    extern __shared__ char dsm[];
    uint32_t raw = smem_u32(dsm);
    uint32_t dbase = (raw + 1023) & ~1023u;

    int tid = threadIdx.x, wid = tid >> 5, lane = tid & 31;
    int brow = blockIdx.y * 128, bcol = blockIdx.x * 128;
    int wm = (wid >> 2) * 64, wn = (wid & 3) * 32;

    const __nv_bfloat16* gbase[4] = {
        Ahi + (size_t)brow * KTOT, Alo + (size_t)brow * KTOT,
        Bhi + (size_t)bcol * KTOT, Blo + (size_t)bcol * KTOT };
    const __nv_bfloat16* gsrc[8];
    uint32_t sdst[8];
    #pragma unroll
    for (int i = 0; i < 8; i++) {
        int s = i * 256 + tid;
        int t = s >> 9, row = (s >> 2) & 127, sg = s & 3;
        gsrc[i] = gbase[t] + (size_t)row * KTOT + sg * 8;
        sdst[i] = (uint32_t)(t * TILEB) + SWZ64((uint32_t)(row * 64 + sg * 16));
    }

    float acc[4][4][4];
    #pragma unroll
    for (int mt = 0; mt < 4; mt++)
        #pragma unroll
        for (int nt = 0; nt < 4; nt++)
            #pragma unroll
            for (int q = 0; q < 4; q++) acc[mt][nt][q] = 0.f;

    int l15 = lane & 15, lhi = lane >> 4;

    // prologue: stages 0,1 (one commit group each)
    #pragma unroll
    for (int st = 0; st < 2; st++) {
        uint32_t sb = dbase + st * STAGEB;
        int k0 = st * KC;
        #pragma unroll
        for (int i = 0; i < 8; i++) CP_ASYNC16(sb + sdst[i], gsrc[i] + k0);
        CP_COMMIT();
    }

    int stage = 0;
    for (int chunk = 0; chunk < NCHUNK; chunk++) {
        if (chunk + 1 < NCHUNK) CP_WAIT(1); else CP_WAIT(0);
        __syncthreads();           // all warps done with prev chunk + data visible

        if (chunk + 2 < NCHUNK) {  // safe: target stage fully consumed at chunk-1
            int ns = stage + 2; if (ns >= NSTAGE) ns -= NSTAGE;
            uint32_t sb = dbase + ns * STAGEB;
            int k0 = (chunk + 2) * KC;
            #pragma unroll
            for (int i = 0; i < 8; i++) CP_ASYNC16(sb + sdst[i], gsrc[i] + k0);
            CP_COMMIT();
        }

        uint32_t ah_b = dbase + stage * STAGEB;
        uint32_t al_b = ah_b + TILEB, bh_b = ah_b + 2 * TILEB, bl_b = ah_b + 3 * TILEB;

        #pragma unroll
        for (int kb = 0; kb < 2; kb++) {
            uint32_t kbyte = (uint32_t)(kb * 32 + lhi * 16);
            uint32_t ahi_f[4][4], alo_f[4][4];
            #pragma unroll
            for (int mt = 0; mt < 4; mt++) {
                uint32_t off = SWZ64((uint32_t)((wm + mt * 16 + l15) * 64) + kbyte);
                LDSM_X4(ahi_f[mt][0], ahi_f[mt][1], ahi_f[mt][2], ahi_f[mt][3], ah_b + off);
                LDSM_X4(alo_f[mt][0], alo_f[mt][1], alo_f[mt][2], alo_f[mt][3], al_b + off);
            }
            #pragma unroll
            for (int p = 0; p < 2; p++) {
                uint32_t off = SWZ64((uint32_t)((wn + p * 16 + l15) * 64) + kbyte);
                uint32_t r0, r1, r2, r3;
                uint32_t bhi0[2], bhi1[2], blo0[2], blo1[2];
                LDSM_X4(r0, r1, r2, r3, bh_b + off);
                bhi0[0] = r0; bhi0[1] = r2; bhi1[0] = r1; bhi1[1] = r3;
                LDSM_X4(r0, r1, r2, r3, bl_b + off);
                blo0[0] = r0; blo0[1] = r2; blo1[0] = r1; blo1[1] = r3;
                #pragma unroll
                for (int mt = 0; mt < 4; mt++) {
                    MMA16816(acc[mt][2 * p], ahi_f[mt], bhi0);
                    MMA16816(acc[mt][2 * p], ahi_f[mt], blo0);
                    MMA16816(acc[mt][2 * p], alo_f[mt], bhi0);
                    MMA16816(acc[mt][2 * p + 1], ahi_f[mt], bhi1);
                    MMA16816(acc[mt][2 * p + 1], ahi_f[mt], blo1);
                    MMA16816(acc[mt][2 * p + 1], alo_f[mt], bhi1);
                }
            }
        }
        stage++; if (stage >= NSTAGE) stage -= NSTAGE;
    }

    // ---- fused epilogue ----
    #pragma unroll
    for (int mt = 0; mt < 4; mt++) {
        #pragma unroll
        for (int q = 0; q < 2; q++) {
            int gr = brow + wm + mt * 16 + (lane >> 2) + q * 8;
            float pl = 0.f, pu = 0.f;
            #pragma unroll
            for (int nt = 0; nt < 4; nt++) {
                int gc = bcol + wn + nt * 8 + (lane & 3) * 2;
                float v0 = acc[mt][nt][q * 2 + 0];
                float v1 = acc[mt][nt][q * 2 + 1];
                if (MODE == 0) {
                    float m0 = v0 * scale[gc], m1 = v1 * scale[gc + 1];
                    __nv_bfloat16 h0 = __float2bfloat16(m0);
                    __nv_bfloat16 h1 = __float2bfloat16(m1);
                    __nv_bfloat162 hv; hv.x = h0; hv.y = h1;
                    *(__nv_bfloat162*)(Ohi + (size_t)gr * H + gc) = hv;
                    __nv_bfloat162 lv;
                    lv.x = __float2bfloat16(m0 - __bfloat162float(h0));
                    lv.y = __float2bfloat16(m1 - __bfloat162float(h1));
                    *(__nv_bfloat162*)(Olo + (size_t)gr * H + gc) = lv;
                    float p0 = fmaxf(v0, 0.f), n0 = fminf(v0, 0.f);
                    float p1 = fmaxf(v1, 0.f), n1 = fminf(v1, 0.f);
                    float sb = m0 * bvec[gc] + m1 * bvec[gc + 1];
                    pl += p0 * blv[gc] + n0 * buv[gc] + p1 * blv[gc + 1] + n1 * buv[gc + 1] + sb;
                    pu += p0 * buv[gc] + n0 * blv[gc] + p1 * buv[gc + 1] + n1 * blv[gc + 1] + sb;
                } else {
                    if (gc < DIN) {
                        float l0 = lin[gc], u0 = uin[gc];
                        float l1 = lin[gc + 1], u1 = uin[gc + 1];
                        float p0 = fmaxf(v0, 0.f), n0 = fminf(v0, 0.f);
                        float p1 = fmaxf(v1, 0.f), n1 = fminf(v1, 0.f);
                        pl += p0 * l0 + n0 * u0 + p1 * l1 + n1 * u1;
                        pu += p0 * u0 + n0 * l0 + p1 * u1 + n1 * l1;
                    }
                }
            }
            pl += __shfl_xor_sync(0xffffffffu, pl, 1);
            pl += __shfl_xor_sync(0xffffffffu, pl, 2);
            pu += __shfl_xor_sync(0xffffffffu, pu, 1);
            pu += __shfl_xor_sync(0xffffffffu, pu, 2);
            if ((lane & 3) == 0) {
                atomicAdd(&cl[gr], pl);
                atomicAdd(&cu[gr], pu);
            }
        }
    }
}

// ---------------- output stage (9 rows) ---------------------------------------
__global__ void build_m4_k(const float* __restrict__ W4, const float* __restrict__ b4,
                           const int* __restrict__ tl, float* __restrict__ M,
                           float* __restrict__ bias) {
    int t = *tl;
    int idx = blockIdx.x * blockDim.x + threadIdx.x;
    if (idx < OUTR * H) {
        int r = idx / H, j = idx % H;
        int c = (r < t) ? r : r + 1;
        M[idx] = W4[(size_t)c * H + j] - W4[(size_t)t * H + j];
    }
    if (idx < OUTR) {
        int c = (idx < t) ? idx : idx + 1;
        bias[idx] = b4[c] - b4[t];
    }
}

__global__ void small_bias_k(const float* __restrict__ A,
                             const float* __restrict__ w, const float* __restrict__ bl,
                             const float* __restrict__ bu, const float* __restrict__ bnext,
                             float* __restrict__ bias) {
    int r = blockIdx.x;
    const float* a = A + (size_t)r * H;
    float au = 0.f, dummy = 0.f;
    for (int j = threadIdx.x; j < H; j += blockDim.x) {
        float v = a[j];
        float p = fmaxf(v, 0.f), n = fminf(v, 0.f);
        au += p * bu[j] + n * bl[j] + v * w[j] * bnext[j];
    }
    blk_reduce2(au, dummy);
    if (threadIdx.x == 0) bias[r] += au;
}

__global__ void zero_k(float* __restrict__ p, int n) {
    int i = blockIdx.x * blockDim.x + threadIdx.x;
    if (i < n) p[i] = 0.f;
}

#define SG_CHUNK 256
__global__ void small_gemm_k(int K, int N, const float* __restrict__ A,
                             const float* __restrict__ ascale,
                             const float* __restrict__ B, float* __restrict__ C) {
    __shared__ float sA[OUTR * SG_CHUNK];
    int k0 = blockIdx.y * SG_CHUNK;
    int n = blockIdx.x * blockDim.x + threadIdx.x;
    for (int idx = threadIdx.x; idx < OUTR * SG_CHUNK; idx += blockDim.x) {
        int r = idx / SG_CHUNK, kk = idx % SG_CHUNK;
        sA[idx] = A[(size_t)r * K + k0 + kk] * ascale[k0 + kk];
    }
    __syncthreads();
    if (n >= N) return;
    float acc[OUTR];
    #pragma unroll
    for (int r = 0; r < OUTR; r++) acc[r] = 0.f;
    #pragma unroll 4
    for (int kk = 0; kk < SG_CHUNK; kk++) {
        float bv = B[(size_t)(k0 + kk) * N + n];
        #pragma unroll
        for (int r = 0; r < OUTR; r++) acc[r] += sA[r * SG_CHUNK + kk] * bv;
    }
    #pragma unroll
    for (int r = 0; r < OUTR; r++) atomicAdd(&C[(size_t)r * N + n], acc[r]);
}

__global__ void final_k(const float* __restrict__ M, const float* __restrict__ lin,
                        const float* __restrict__ uin, const float* __restrict__ bias,
                        float* __restrict__ out) {
    int r = blockIdx.x;
    const float* a = M + (size_t)r * DIN;
    float au = 0.f, dummy = 0.f;
    for (int j = threadIdx.x; j < DIN; j += blockDim.x) {
        float v = a[j];
        au += fmaxf(v, 0.f) * uin[j] + fminf(v, 0.f) * lin[j];
    }
    blk_reduce2(au, dummy);
    if (threadIdx.x == 0) out[r] = au + bias[r];
}

// ---------------- launch ------------------------------------------------------
extern "C" void kernel_launch(void* const* d_in, const int* in_sizes, int n_in,
                              void* d_out, int out_size) {
    const float* W1 = (const float*)d_in[0];
    const float* b1 = (const float*)d_in[1];
    const float* W2 = (const float*)d_in[2];
    const float* b2 = (const float*)d_in[3];
    const float* W3 = (const float*)d_in[4];
    const float* b3 = (const float*)d_in[5];
    const float* W4 = (const float*)d_in[6];
    const float* b4 = (const float*)d_in[7];
    const float* l_in = (const float*)d_in[8];
    const float* u_in = (const float*)d_in[9];
    const float* p_l1 = (const float*)d_in[10];
    const float* p_u1 = (const float*)d_in[11];
    const float* p_l2 = (const float*)d_in[12];
    const float* p_u2 = (const float*)d_in[13];
    const float* p_l3 = (const float*)d_in[14];
    const float* p_u3 = (const float*)d_in[15];
    const int* tl = (const int*)d_in[16];
    float* out = (float*)d_out;

    cudaFuncSetAttribute(gemm_mma_k<0>, cudaFuncAttributeMaxDynamicSharedMemorySize, DSMEM);
    cudaFuncSetAttribute(gemm_mma_k<1>, cudaFuncAttributeMaxDynamicSharedMemorySize, DSMEM);

    float *T, *w1, *bl1, *bu1, *w2, *bl2, *bu2, *w3, *bl3, *bu3, *cl, *cu;
    float *m4a, *m4b, *bias4;
    __nv_bfloat16 *Ahi, *Alo, *W1th, *W1tl, *W2th, *W2tl;
    cudaGetSymbolAddress((void**)&T, g_T);
    cudaGetSymbolAddress((void**)&Ahi, g_Ahi);   cudaGetSymbolAddress((void**)&Alo, g_Alo);
    cudaGetSymbolAddress((void**)&W1th, g_W1t_hi); cudaGetSymbolAddress((void**)&W1tl, g_W1t_lo);
    cudaGetSymbolAddress((void**)&W2th, g_W2t_hi); cudaGetSymbolAddress((void**)&W2tl, g_W2t_lo);
    cudaGetSymbolAddress((void**)&w1, g_w1);   cudaGetSymbolAddress((void**)&bl1, g_bl1);
    cudaGetSymbolAddress((void**)&bu1, g_bu1);
    cudaGetSymbolAddress((void**)&w2, g_w2);   cudaGetSymbolAddress((void**)&bl2, g_bl2);
    cudaGetSymbolAddress((void**)&bu2, g_bu2);
    cudaGetSymbolAddress((void**)&w3, g_w3);   cudaGetSymbolAddress((void**)&bl3, g_bl3);
    cudaGetSymbolAddress((void**)&bu3, g_bu3);
    cudaGetSymbolAddress((void**)&cl, g_cl);   cudaGetSymbolAddress((void**)&cu, g_cu);
    cudaGetSymbolAddress((void**)&m4a, g_m4a); cudaGetSymbolAddress((void**)&m4b, g_m4b);
    cudaGetSymbolAddress((void**)&bias4, g_bias4);

    __nv_bfloat16* Thi = (__nv_bfloat16*)T;
    __nv_bfloat16* Tlo = ((__nv_bfloat16*)T) + (size_t)H * H;

    // one-time (per launch) B transpose+split
    transp_conv_k<<<dim3(KTOT / 32, (DIN + 31) / 32), dim3(32, 8)>>>(W1, DIN, W1th, W1tl);
    transp_conv_k<<<dim3(KTOT / 32, H / 32), dim3(32, 8)>>>(W2, H, W2th, W2tl);

    dim3 gmid(NPAD1 / 128, H / 128);         // 7 x 16
    dim3 gbig(H / 128, H / 128);             // 16 x 16

    // ---- stage 1 (fused concretize + spu) ----
    concretize_spu_k<<<H, 256>>>(W1, l_in, u_in, b1, p_l1, p_u1, w1, bl1, bu1);

    // ---- stage 2 ----
    bias2conv_k<<<H, 256>>>(W2, w1, bl1, bu1, b2, b1, cl, cu, Ahi, Alo);
    gemm_mma_k<1><<<gmid, 256, DSMEM>>>(Ahi, Alo, W1th, W1tl, nullptr, nullptr,
                                        nullptr, nullptr, nullptr, nullptr,
                                        cl, cu, l_in, u_in);
    spu_params_k<<<(H + 63) / 64, 64>>>(cl, cu, p_l2, p_u2, w2, bl2, bu2, H);

    // ---- stage 3 ----
    bias2conv_k<<<H, 256>>>(W3, w2, bl2, bu2, b3, b2, cl, cu, Ahi, Alo);
    gemm_mma_k<0><<<gbig, 256, DSMEM>>>(Ahi, Alo, W2th, W2tl, Thi, Tlo,
                                        w1, b1, bl1, bu1, cl, cu, nullptr, nullptr);
    gemm_mma_k<1><<<gmid, 256, DSMEM>>>(Thi, Tlo, W1th, W1tl, nullptr, nullptr,
                                        nullptr, nullptr, nullptr, nullptr,
                                        cl, cu, l_in, u_in);
    spu_params_k<<<(H + 63) / 64, 64>>>(cl, cu, p_l3, p_u3, w3, bl3, bu3, H);

    // ---- stage 4: output chain (9 rows) — R6 structure ----
    build_m4_k<<<(OUTR * H + 255) / 256, 256>>>(W4, b4, tl, m4a, bias4);
    small_bias_k<<<OUTR, 256>>>(m4a, w3, bl3, bu3, b3, bias4);
    zero_k<<<(OUTR * H + 255) / 256, 256>>>(m4b, OUTR * H);
    small_gemm_k<<<dim3((H + 127) / 128, H / SG_CHUNK), 128>>>(H, H, m4a, w3, W3, m4b);
    small_bias_k<<<OUTR, 256>>>(m4b, w2, bl2, bu2, b2, bias4);
    zero_k<<<(OUTR * H + 255) / 256, 256>>>(m4a, OUTR * H);
    small_gemm_k<<<dim3((H + 127) / 128, H / SG_CHUNK), 128>>>(H, H, m4b, w2, W2, m4a);
    small_bias_k<<<OUTR, 256>>>(m4a, w1, bl1, bu1, b1, bias4);
    zero_k<<<(OUTR * DIN + 255) / 256, 256>>>(m4b, OUTR * DIN);
    small_gemm_k<<<dim3((DIN + 127) / 128, H / SG_CHUNK), 128>>>(H, DIN, m4a, w1, W1, m4b);
    final_k<<<OUTR, 256>>>(m4b, l_in, u_in, bias4, out);
}

// round 10
// speedup vs baseline: 1.3546x; 1.0243x over previous
#include <cuda_runtime.h>
#include <cuda_bf16.h>
#include <math.h>
#include <stdint.h>

#define H     2048
#define DIN   784
#define OUTR  9
#define KTOT  2048
#define KC    32
#define NCHUNK (KTOT / KC)          // 64
#define TILEB  8192                 // 128 rows * 64B
#define STAGEB (4 * TILEB)          // 32KB
#define NSTAGE 3
#define DSMEM  (NSTAGE * STAGEB + 1024)
// mid-GEMM (64x128 tile) sizes
#define MTILEA 4096                 // 64 rows * 64B
#define MTILEB 8192                 // 128 rows * 64B
#define MSTAGE (2 * MTILEA + 2 * MTILEB)   // 24576
#define MDSMEM (NSTAGE * MSTAGE + 1024)
#define NPAD1  896

// ---------------- scratch (device globals) ----------------------------------
__device__ float g_T[H * H];        // reused as 2x bf16 [H*H] for stage-3 split
__device__ __nv_bfloat16 g_Ahi[H * H], g_Alo[H * H];
__device__ __nv_bfloat16 g_W1t_hi[NPAD1 * KTOT], g_W1t_lo[NPAD1 * KTOT];  // pad rows stay 0
__device__ __nv_bfloat16 g_W2t_hi[H * KTOT], g_W2t_lo[H * KTOT];
__device__ float g_w1[H], g_bl1[H], g_bu1[H];
__device__ float g_w2[H], g_bl2[H], g_bu2[H];
__device__ float g_w3[H], g_bl3[H], g_bu3[H];
__device__ float g_cl[H], g_cu[H];
__device__ float g_m4a[OUTR * H], g_m4b[OUTR * H];
__device__ float g_bias4[OUTR];

// ---------------- PTX helpers ------------------------------------------------
__device__ __forceinline__ uint32_t smem_u32(const void* p) {
    uint32_t a;
    asm("{ .reg .u64 t; cvta.to.shared.u64 t, %1; cvt.u32.u64 %0, t; }" : "=r"(a) : "l"(p));
    return a;
}
#define SWZ64(o)   ((o) ^ (((o) >> 3) & 0x30))
#define CP_ASYNC16(dst, gsrc) \
    asm volatile("cp.async.cg.shared.global [%0], [%1], 16;" :: "r"(dst), "l"(gsrc))
#define CP_COMMIT() asm volatile("cp.async.commit_group;" ::: "memory")
#define CP_WAIT(n)  asm volatile("cp.async.wait_group %0;" :: "n"(n) : "memory")
#define LDSM_X4(r0, r1, r2, r3, addr) \
    asm volatile("ldmatrix.sync.aligned.m8n8.x4.shared.b16 {%0,%1,%2,%3}, [%4];" \
        : "=r"(r0), "=r"(r1), "=r"(r2), "=r"(r3) : "r"(addr))
#define MMA16816(d, a, b) \
    asm volatile("mma.sync.aligned.m16n8k16.row.col.f32.bf16.bf16.f32 " \
        "{%0,%1,%2,%3}, {%4,%5,%6,%7}, {%8,%9}, {%0,%1,%2,%3};" \
        : "+f"((d)[0]), "+f"((d)[1]), "+f"((d)[2]), "+f"((d)[3]) \
        : "r"((a)[0]), "r"((a)[1]), "r"((a)[2]), "r"((a)[3]), "r"((b)[0]), "r"((b)[1]))

// ---------------- misc helpers ----------------------------------------------
__device__ __forceinline__ float spu_f(float x) {
    if (x >= 0.f) return x * x - 0.5f;
    float s = 1.f / (1.f + expf(x));
    return s - 1.f;
}
__device__ __forceinline__ float dspu_f(float x) {
    if (x >= 0.f) return 2.f * x;
    float s = 1.f / (1.f + expf(x));
    return -s * (1.f - s);
}
__device__ __forceinline__ void spu_relax(float l, float u, float pl, float pu,
                                          float &w_, float &bl_, float &bu_) {
    float k1 = dspu_f(l), k2 = dspu_f(u);
    float klo = fminf(k1, k2), khi = fmaxf(k1, k2);
    float wl = fminf(fmaxf(pl, klo), khi);
    float wu = fminf(fmaxf(pu, klo), khi);
    float p0 = l, p1 = u, p2 = 0.5f * (l + u), p3 = fminf(fmaxf(0.f, l), u);
    float s0 = spu_f(p0), s1 = spu_f(p1), s2 = spu_f(p2), s3 = spu_f(p3);
    bl_ = fminf(fminf(s0 - wl * p0, s1 - wl * p1), fminf(s2 - wl * p2, s3 - wl * p3));
    bu_ = fmaxf(fmaxf(s0 - wu * p0, s1 - wu * p1), fmaxf(s2 - wu * p2, s3 - wu * p3));
    w_ = wl;
}
__device__ __forceinline__ void blk_reduce2(float &a, float &b) {
    const unsigned m = 0xffffffffu;
    #pragma unroll
    for (int o = 16; o > 0; o >>= 1) {
        a += __shfl_down_sync(m, a, o);
        b += __shfl_down_sync(m, b, o);
    }
    __shared__ float sa[8], sb[8];
    int w = threadIdx.x >> 5, l = threadIdx.x & 31;
    int nw = blockDim.x >> 5;
    if (l == 0) { sa[w] = a; sb[w] = b; }
    __syncthreads();
    if (w == 0) {
        a = (l < nw) ? sa[l] : 0.f;
        b = (l < nw) ? sb[l] : 0.f;
        #pragma unroll
        for (int o = 4; o > 0; o >>= 1) {
            a += __shfl_down_sync(m, a, o);
            b += __shfl_down_sync(m, b, o);
        }
    }
}

// ---------------- fused stage-1: concretize W1 row + SPU params --------------
__global__ void concretize_spu_k(const float* __restrict__ W1v,
                                 const float* __restrict__ lin, const float* __restrict__ uin,
                                 const float* __restrict__ b1v,
                                 const float* __restrict__ pl, const float* __restrict__ pu,
                                 float* __restrict__ w, float* __restrict__ bl,
                                 float* __restrict__ bu) {
    int row = blockIdx.x;
    const float* a = W1v + (size_t)row * DIN;
    float al = 0.f, au = 0.f;
    for (int j = threadIdx.x; j < DIN; j += blockDim.x) {
        float v = a[j], l = lin[j], u = uin[j];
        float p = fmaxf(v, 0.f), n = fminf(v, 0.f);
        al += p * l + n * u;
        au += p * u + n * l;
    }
    blk_reduce2(al, au);
    if (threadIdx.x == 0) {
        float l = al + b1v[row], u = au + b1v[row];
        float w_, bl_, bu_;
        spu_relax(l, u, pl[row], pu[row], w_, bl_, bu_);
        w[row] = w_; bl[row] = bl_; bu[row] = bu_;
    }
}

__global__ void spu_params_k(const float* __restrict__ lf, const float* __restrict__ uf,
                             const float* __restrict__ pl, const float* __restrict__ pu,
                             float* __restrict__ w, float* __restrict__ bl,
                             float* __restrict__ bu, int n) {
    int i = blockIdx.x * blockDim.x + threadIdx.x;
    if (i >= n) return;
    float w_, bl_, bu_;
    spu_relax(lf[i], uf[i], pl[i], pu[i], w_, bl_, bu_);
    w[i] = w_; bl[i] = bl_; bu[i] = bu_;
}

// bias + bf16 split, float4-vectorized (H=2048 divisible by 4*blockDim)
__global__ void bias2conv_k(const float* __restrict__ W,
                            const float* __restrict__ wprev,
                            const float* __restrict__ blprev, const float* __restrict__ buprev,
                            const float* __restrict__ bthis, const float* __restrict__ bprev,
                            float* __restrict__ cl, float* __restrict__ cu,
                            __nv_bfloat16* __restrict__ hi, __nv_bfloat16* __restrict__ lo) {
    int row = blockIdx.x;
    const float* wr = W + (size_t)row * H;
    __nv_bfloat16* hr = hi + (size_t)row * H;
    __nv_bfloat16* lr = lo + (size_t)row * H;
    float al = 0.f, au = 0.f;
    for (int j = threadIdx.x * 4; j < H; j += blockDim.x * 4) {
        float4 v  = *(const float4*)(wr + j);
        float4 wp = *(const float4*)(wprev + j);
        float4 bp = *(const float4*)(bprev + j);
        float4 bL = *(const float4*)(blprev + j);
        float4 bU = *(const float4*)(buprev + j);
        float m0 = v.x * wp.x, m1 = v.y * wp.y, m2 = v.z * wp.z, m3 = v.w * wp.w;
        float sb = m0 * bp.x + m1 * bp.y + m2 * bp.z + m3 * bp.w;
        float pA = fmaxf(v.x, 0.f), nA = fminf(v.x, 0.f);
        float pB = fmaxf(v.y, 0.f), nB = fminf(v.y, 0.f);
        float pC = fmaxf(v.z, 0.f), nC = fminf(v.z, 0.f);
        float pD = fmaxf(v.w, 0.f), nD = fminf(v.w, 0.f);
        al += pA * bL.x + nA * bU.x + pB * bL.y + nB * bU.y
            + pC * bL.z + nC * bU.z + pD * bL.w + nD * bU.w + sb;
        au += pA * bU.x + nA * bL.x + pB * bU.y + nB * bL.y
            + pC * bU.z + nC * bL.z + pD * bU.w + nD * bL.w + sb;
        __nv_bfloat16 h0 = __float2bfloat16(m0), h1 = __float2bfloat16(m1);
        __nv_bfloat16 h2 = __float2bfloat16(m2), h3 = __float2bfloat16(m3);
        __nv_bfloat162 hv0; hv0.x = h0; hv0.y = h1;
        __nv_bfloat162 hv1; hv1.x = h2; hv1.y = h3;
        *(__nv_bfloat162*)(hr + j)     = hv0;
        *(__nv_bfloat162*)(hr + j + 2) = hv1;
        __nv_bfloat162 lv0, lv1;
        lv0.x = __float2bfloat16(m0 - __bfloat162float(h0));
        lv0.y = __float2bfloat16(m1 - __bfloat162float(h1));
        lv1.x = __float2bfloat16(m2 - __bfloat162float(h2));
        lv1.y = __float2bfloat16(m3 - __bfloat162float(h3));
        *(__nv_bfloat162*)(lr + j)     = lv0;
        *(__nv_bfloat162*)(lr + j + 2) = lv1;
    }
    blk_reduce2(al, au);
    if (threadIdx.x == 0) { cl[row] = bthis[row] + al; cu[row] = bthis[row] + au; }
}

// B [K x N] fp32 row-major -> Bt_hi/lo [Npad x K] bf16 (rows >= N stay zero)
__global__ void transp_conv_k(const float* __restrict__ B, int N,
                              __nv_bfloat16* __restrict__ thi, __nv_bfloat16* __restrict__ tlo) {
    __shared__ float t[32][33];
    int k0 = blockIdx.x * 32, n0 = blockIdx.y * 32;
    int x = threadIdx.x, y = threadIdx.y;       // 32 x 8
    for (int yy = y; yy < 32; yy += 8) {
        int n = n0 + x;
        t[yy][x] = (n < N) ? B[(size_t)(k0 + yy) * N + n] : 0.f;
    }
    __syncthreads();
    for (int yy = y; yy < 32; yy += 8) {
        int n = n0 + yy, k = k0 + x;
        if (n < N) {
            float v = t[x][yy];
            __nv_bfloat16 h = __float2bfloat16(v);
            thi[(size_t)n * KTOT + k] = h;
            tlo[(size_t)n * KTOT + k] = __float2bfloat16(v - __bfloat162float(h));
        }
    }
}

// ---------------- big GEMM: 128x128 tile, MODE 0 fused epilogue ---------------
__global__ __launch_bounds__(256, 2)
void gemm_mma_k(const __nv_bfloat16* __restrict__ Ahi, const __nv_bfloat16* __restrict__ Alo,
                const __nv_bfloat16* __restrict__ Bhi, const __nv_bfloat16* __restrict__ Blo,
                __nv_bfloat16* __restrict__ Ohi, __nv_bfloat16* __restrict__ Olo,
                const float* __restrict__ scale, const float* __restrict__ bvec,
                const float* __restrict__ blv, const float* __restrict__ buv,
                float* __restrict__ cl, float* __restrict__ cu) {
    extern __shared__ char dsm[];
    uint32_t raw = smem_u32(dsm);
    uint32_t dbase = (raw + 1023) & ~1023u;

    int tid = threadIdx.x, wid = tid >> 5, lane = tid & 31;
    int brow = blockIdx.y * 128, bcol = blockIdx.x * 128;
    int wm = (wid >> 2) * 64, wn = (wid & 3) * 32;

    const __nv_bfloat16* gbase[4] = {
        Ahi + (size_t)brow * KTOT, Alo + (size_t)brow * KTOT,
        Bhi + (size_t)bcol * KTOT, Blo + (size_t)bcol * KTOT };
    const __nv_bfloat16* gsrc[8];
    uint32_t sdst[8];
    #pragma unroll
    for (int i = 0; i < 8; i++) {
        int s = i * 256 + tid;
        int t = s >> 9, row = (s >> 2) & 127, sg = s & 3;
        gsrc[i] = gbase[t] + (size_t)row * KTOT + sg * 8;
        sdst[i] = (uint32_t)(t * TILEB) + SWZ64((uint32_t)(row * 64 + sg * 16));
    }

    float acc[4][4][4];
    #pragma unroll
    for (int mt = 0; mt < 4; mt++)
        #pragma unroll
        for (int nt = 0; nt < 4; nt++)
            #pragma unroll
            for (int q = 0; q < 4; q++) acc[mt][nt][q] = 0.f;

    int l15 = lane & 15, lhi = lane >> 4;

    #pragma unroll
    for (int st = 0; st < 2; st++) {
        uint32_t sb = dbase + st * STAGEB;
        int k0 = st * KC;
        #pragma unroll
        for (int i = 0; i < 8; i++) CP_ASYNC16(sb + sdst[i], gsrc[i] + k0);
        CP_COMMIT();
    }

    int stage = 0;
    for (int chunk = 0; chunk < NCHUNK; chunk++) {
        if (chunk + 1 < NCHUNK) CP_WAIT(1); else CP_WAIT(0);
        __syncthreads();
        if (chunk + 2 < NCHUNK) {
            int ns = stage + 2; if (ns >= NSTAGE) ns -= NSTAGE;
            uint32_t sb = dbase + ns * STAGEB;
            int k0 = (chunk + 2) * KC;
            #pragma unroll
            for (int i = 0; i < 8; i++) CP_ASYNC16(sb + sdst[i], gsrc[i] + k0);
            CP_COMMIT();
        }
        uint32_t ah_b = dbase + stage * STAGEB;
        uint32_t al_b = ah_b + TILEB, bh_b = ah_b + 2 * TILEB, bl_b = ah_b + 3 * TILEB;
        #pragma unroll
        for (int kb = 0; kb < 2; kb++) {
            uint32_t kbyte = (uint32_t)(kb * 32 + lhi * 16);
            uint32_t ahi_f[4][4], alo_f[4][4];
            #pragma unroll
            for (int mt = 0; mt < 4; mt++) {
                uint32_t off = SWZ64((uint32_t)((wm + mt * 16 + l15) * 64) + kbyte);
                LDSM_X4(ahi_f[mt][0], ahi_f[mt][1], ahi_f[mt][2], ahi_f[mt][3], ah_b + off);
                LDSM_X4(alo_f[mt][0], alo_f[mt][1], alo_f[mt][2], alo_f[mt][3], al_b + off);
            }
            #pragma unroll
            for (int p = 0; p < 2; p++) {
                uint32_t off = SWZ64((uint32_t)((wn + p * 16 + l15) * 64) + kbyte);
                uint32_t r0, r1, r2, r3;
                uint32_t bhi0[2], bhi1[2], blo0[2], blo1[2];
                LDSM_X4(r0, r1, r2, r3, bh_b + off);
                bhi0[0] = r0; bhi0[1] = r2; bhi1[0] = r1; bhi1[1] = r3;
                LDSM_X4(r0, r1, r2, r3, bl_b + off);
                blo0[0] = r0; blo0[1] = r2; blo1[0] = r1; blo1[1] = r3;
                #pragma unroll
                for (int mt = 0; mt < 4; mt++) {
                    MMA16816(acc[mt][2 * p], ahi_f[mt], bhi0);
                    MMA16816(acc[mt][2 * p], ahi_f[mt], blo0);
                    MMA16816(acc[mt][2 * p], alo_f[mt], bhi0);
                    MMA16816(acc[mt][2 * p + 1], ahi_f[mt], bhi1);
                    MMA16816(acc[mt][2 * p + 1], ahi_f[mt], blo1);
                    MMA16816(acc[mt][2 * p + 1], alo_f[mt], bhi1);
                }
            }
        }
        stage++; if (stage >= NSTAGE) stage -= NSTAGE;
    }

    #pragma unroll
    for (int mt = 0; mt < 4; mt++) {
        #pragma unroll
        for (int q = 0; q < 2; q++) {
            int gr = brow + wm + mt * 16 + (lane >> 2) + q * 8;
            float pl = 0.f, pu = 0.f;
            #pragma unroll
            for (int nt = 0; nt < 4; nt++) {
                int gc = bcol + wn + nt * 8 + (lane & 3) * 2;
                float v0 = acc[mt][nt][q * 2 + 0];
                float v1 = acc[mt][nt][q * 2 + 1];
                float m0 = v0 * scale[gc], m1 = v1 * scale[gc + 1];
                __nv_bfloat16 h0 = __float2bfloat16(m0);
                __nv_bfloat16 h1 = __float2bfloat16(m1);
                __nv_bfloat162 hv; hv.x = h0; hv.y = h1;
                *(__nv_bfloat162*)(Ohi + (size_t)gr * H + gc) = hv;
                __nv_bfloat162 lv;
                lv.x = __float2bfloat16(m0 - __bfloat162float(h0));
                lv.y = __float2bfloat16(m1 - __bfloat162float(h1));
                *(__nv_bfloat162*)(Olo + (size_t)gr * H + gc) = lv;
                float p0 = fmaxf(v0, 0.f), n0 = fminf(v0, 0.f);
                float p1 = fmaxf(v1, 0.f), n1 = fminf(v1, 0.f);
                float sb = m0 * bvec[gc] + m1 * bvec[gc + 1];
                pl += p0 * blv[gc] + n0 * buv[gc] + p1 * blv[gc + 1] + n1 * buv[gc + 1] + sb;
                pu += p0 * buv[gc] + n0 * blv[gc] + p1 * buv[gc + 1] + n1 * blv[gc + 1] + sb;
            }
            pl += __shfl_xor_sync(0xffffffffu, pl, 1);
            pl += __shfl_xor_sync(0xffffffffu, pl, 2);
            pu += __shfl_xor_sync(0xffffffffu, pu, 1);
            pu += __shfl_xor_sync(0xffffffffu, pu, 2);
            if ((lane & 3) == 0) {
                atomicAdd(&cl[gr], pl);
                atomicAdd(&cu[gr], pu);
            }
        }
    }
}

// ---------------- mid GEMM: 64x128 tile, MODE 1 (concretize) epilogue ---------
__global__ __launch_bounds__(256, 2)
void gemm_mid_mma_k(const __nv_bfloat16* __restrict__ Ahi, const __nv_bfloat16* __restrict__ Alo,
                    const __nv_bfloat16* __restrict__ Bhi, const __nv_bfloat16* __restrict__ Blo,
                    float* __restrict__ cl, float* __restrict__ cu,
                    const float* __restrict__ lin, const float* __restrict__ uin) {
    extern __shared__ char dsm[];
    uint32_t raw = smem_u32(dsm);
    uint32_t dbase = (raw + 1023) & ~1023u;

    int tid = threadIdx.x, wid = tid >> 5, lane = tid & 31;
    int brow = blockIdx.y * 64, bcol = blockIdx.x * 128;
    int wm = (wid >> 2) * 32, wn = (wid & 3) * 32;   // warp tile 32x32

    // staging: 1536 segs per chunk, 6 per thread
    const __nv_bfloat16* gsrc[6];
    uint32_t sdst[6];
    #pragma unroll
    for (int i = 0; i < 6; i++) {
        int s = i * 256 + tid;          // 0..1535
        int rowg = s >> 2, sg = s & 3;
        if (rowg < 128) {               // A tiles: 64 hi + 64 lo
            int t = rowg >> 6, r = rowg & 63;
            gsrc[i] = (t ? Alo : Ahi) + (size_t)(brow + r) * KTOT + sg * 8;
            sdst[i] = (uint32_t)(t * MTILEA) + SWZ64((uint32_t)(r * 64 + sg * 16));
        } else {                        // B tiles: 128 hi + 128 lo
            int rr = rowg - 128;
            int t = rr >> 7, r = rr & 127;
            gsrc[i] = (t ? Blo : Bhi) + (size_t)(bcol + r) * KTOT + sg * 8;
            sdst[i] = (uint32_t)(2 * MTILEA + t * MTILEB) + SWZ64((uint32_t)(r * 64 + sg * 16));
        }
    }

    float acc[2][4][4];
    #pragma unroll
    for (int mt = 0; mt < 2; mt++)
        #pragma unroll
        for (int nt = 0; nt < 4; nt++)
            #pragma unroll
            for (int q = 0; q < 4; q++) acc[mt][nt][q] = 0.f;

    int l15 = lane & 15, lhi = lane >> 4;

    #pragma unroll
    for (int st = 0; st < 2; st++) {
        uint32_t sb = dbase + st * MSTAGE;
        int k0 = st * KC;
        #pragma unroll
        for (int i = 0; i < 6; i++) CP_ASYNC16(sb + sdst[i], gsrc[i] + k0);
        CP_COMMIT();
    }

    int stage = 0;
    for (int chunk = 0; chunk < NCHUNK; chunk++) {
        if (chunk + 1 < NCHUNK) CP_WAIT(1); else CP_WAIT(0);
        __syncthreads();
        if (chunk + 2 < NCHUNK) {
            int ns = stage + 2; if (ns >= NSTAGE) ns -= NSTAGE;
            uint32_t sb = dbase + ns * MSTAGE;
            int k0 = (chunk + 2) * KC;
            #pragma unroll
            for (int i = 0; i < 6; i++) CP_ASYNC16(sb + sdst[i], gsrc[i] + k0);
            CP_COMMIT();
        }
        uint32_t ah_b = dbase + stage * MSTAGE;
        uint32_t al_b = ah_b + MTILEA;
        uint32_t bh_b = ah_b + 2 * MTILEA, bl_b = bh_b + MTILEB;
        #pragma unroll
        for (int kb = 0; kb < 2; kb++) {
            uint32_t kbyte = (uint32_t)(kb * 32 + lhi * 16);
            uint32_t ahi_f[2][4], alo_f[2][4];
            #pragma unroll
            for (int mt = 0; mt < 2; mt++) {
                uint32_t off = SWZ64((uint32_t)((wm + mt * 16 + l15) * 64) + kbyte);
                LDSM_X4(ahi_f[mt][0], ahi_f[mt][1], ahi_f[mt][2], ahi_f[mt][3], ah_b + off);
                LDSM_X4(alo_f[mt][0], alo_f[mt][1], alo_f[mt][2], alo_f[mt][3], al_b + off);
            }
            #pragma unroll
            for (int p = 0; p < 2; p++) {
                uint32_t off = SWZ64((uint32_t)((wn + p * 16 + l15) * 64) + kbyte);
                uint32_t r0, r1, r2, r3;
                uint32_t bhi0[2], bhi1[2], blo0[2], blo1[2];
                LDSM_X4(r0, r1, r2, r3, bh_b + off);
                bhi0[0] = r0; bhi0[1] = r2; bhi1[0] = r1; bhi1[1] = r3;
                LDSM_X4(r0, r1, r2, r3, bl_b + off);
                blo0[0] = r0; blo0[1] = r2; blo1[0] = r1; blo1[1] = r3;
                #pragma unroll
                for (int mt = 0; mt < 2; mt++) {
                    MMA16816(acc[mt][2 * p], ahi_f[mt], bhi0);
                    MMA16816(acc[mt][2 * p], ahi_f[mt], blo0);
                    MMA16816(acc[mt][2 * p], alo_f[mt], bhi0);
                    MMA16816(acc[mt][2 * p + 1], ahi_f[mt], bhi1);
                    MMA16816(acc[mt][2 * p + 1], ahi_f[mt], blo1);
                    MMA16816(acc[mt][2 * p + 1], alo_f[mt], bhi1);
                }
            }
        }
        stage++; if (stage >= NSTAGE) stage -= NSTAGE;
    }

    // MODE1 epilogue: row-reduce pos/neg with lin/uin weights, atomic into cl/cu
    #pragma unroll
    for (int mt = 0; mt < 2; mt++) {
        #pragma unroll
        for (int q = 0; q < 2; q++) {
            int gr = brow + wm + mt * 16 + (lane >> 2) + q * 8;
            float pl = 0.f, pu = 0.f;
            #pragma unroll
            for (int nt = 0; nt < 4; nt++) {
                int gc = bcol + wn + nt * 8 + (lane & 3) * 2;
                if (gc < DIN) {
                    float v0 = acc[mt][nt][q * 2 + 0];
                    float v1 = acc[mt][nt][q * 2 + 1];
                    float l0 = lin[gc], u0 = uin[gc];
                    float l1 = lin[gc + 1], u1 = uin[gc + 1];
                    float p0 = fmaxf(v0, 0.f), n0 = fminf(v0, 0.f);
                    float p1 = fmaxf(v1, 0.f), n1 = fminf(v1, 0.f);
                    pl += p0 * l0 + n0 * u0 + p1 * l1 + n1 * u1;
                    pu += p0 * u0 + n0 * l0 + p1 * u1 + n1 * l1;
                }
            }
            pl += __shfl_xor_sync(0xffffffffu, pl, 1);
            pl += __shfl_xor_sync(0xffffffffu, pl, 2);
            pu += __shfl_xor_sync(0xffffffffu, pu, 1);
            pu += __shfl_xor_sync(0xffffffffu, pu, 2);
            if ((lane & 3) == 0) {
                atomicAdd(&cl[gr], pl);
                atomicAdd(&cu[gr], pu);
            }
        }
    }
}

// ---------------- output stage (9 rows) ---------------------------------------
__global__ void build_m4_k(const float* __restrict__ W4, const float* __restrict__ b4,
                           const int* __restrict__ tl, float* __restrict__ M,
                           float* __restrict__ bias) {
    int t = *tl;
    int idx = blockIdx.x * blockDim.x + threadIdx.x;
    if (idx < OUTR * H) {
        int r = idx / H, j = idx % H;
        int c = (r < t) ? r : r + 1;
        M[idx] = W4[(size_t)c * H + j] - W4[(size_t)t * H + j];
    }
    if (idx < OUTR) {
        int c = (idx < t) ? idx : idx + 1;
        bias[idx] = b4[c] - b4[t];
    }
}

__global__ void small_bias_k(const float* __restrict__ A,
                             const float* __restrict__ w, const float* __restrict__ bl,
                             const float* __restrict__ bu, const float* __restrict__ bnext,
                             float* __restrict__ bias) {
    int r = blockIdx.x;
    const float* a = A + (size_t)r * H;
    float au = 0.f, dummy = 0.f;
    for (int j = threadIdx.x; j < H; j += blockDim.x) {
        float v = a[j];
        float p = fmaxf(v, 0.f), n = fminf(v, 0.f);
        au += p * bu[j] + n * bl[j] + v * w[j] * bnext[j];
    }
    blk_reduce2(au, dummy);
    if (threadIdx.x == 0) bias[r] += au;
}

__global__ void zero_k(float* __restrict__ p, int n) {
    int i = blockIdx.x * blockDim.x + threadIdx.x;
    if (i < n) p[i] = 0.f;
}

#define SG_CHUNK 256
__global__ void small_gemm_k(int K, int N, const float* __restrict__ A,
                             const float* __restrict__ ascale,
                             const float* __restrict__ B, float* __restrict__ C) {
    __shared__ float sA[OUTR * SG_CHUNK];
    int k0 = blockIdx.y * SG_CHUNK;
    int n = blockIdx.x * blockDim.x + threadIdx.x;
    for (int idx = threadIdx.x; idx < OUTR * SG_CHUNK; idx += blockDim.x) {
        int r = idx / SG_CHUNK, kk = idx % SG_CHUNK;
        sA[idx] = A[(size_t)r * K + k0 + kk] * ascale[k0 + kk];
    }
    __syncthreads();
    if (n >= N) return;
    float acc[OUTR];
    #pragma unroll
    for (int r = 0; r < OUTR; r++) acc[r] = 0.f;
    #pragma unroll 4
    for (int kk = 0; kk < SG_CHUNK; kk++) {
        float bv = B[(size_t)(k0 + kk) * N + n];
        #pragma unroll
        for (int r = 0; r < OUTR; r++) acc[r] += sA[r * SG_CHUNK + kk] * bv;
    }
    #pragma unroll
    for (int r = 0; r < OUTR; r++) atomicAdd(&C[(size_t)r * N + n], acc[r]);
}

__global__ void final_k(const float* __restrict__ M, const float* __restrict__ lin,
                        const float* __restrict__ uin, const float* __restrict__ bias,
                        float* __restrict__ out) {
    int r = blockIdx.x;
    const float* a = M + (size_t)r * DIN;
    float au = 0.f, dummy = 0.f;
    for (int j = threadIdx.x; j < DIN; j += blockDim.x) {
        float v = a[j];
        au += fmaxf(v, 0.f) * uin[j] + fminf(v, 0.f) * lin[j];
    }
    blk_reduce2(au, dummy);
    if (threadIdx.x == 0) out[r] = au + bias[r];
}

// ---------------- launch ------------------------------------------------------
extern "C" void kernel_launch(void* const* d_in, const int* in_sizes, int n_in,
                              void* d_out, int out_size) {
    const float* W1 = (const float*)d_in[0];
    const float* b1 = (const float*)d_in[1];
    const float* W2 = (const float*)d_in[2];
    const float* b2 = (const float*)d_in[3];
    const float* W3 = (const float*)d_in[4];
    const float* b3 = (const float*)d_in[5];
    const float* W4 = (const float*)d_in[6];
    const float* b4 = (const float*)d_in[7];
    const float* l_in = (const float*)d_in[8];
    const float* u_in = (const float*)d_in[9];
    const float* p_l1 = (const float*)d_in[10];
    const float* p_u1 = (const float*)d_in[11];
    const float* p_l2 = (const float*)d_in[12];
    const float* p_u2 = (const float*)d_in[13];
    const float* p_l3 = (const float*)d_in[14];
    const float* p_u3 = (const float*)d_in[15];
    const int* tl = (const int*)d_in[16];
    float* out = (float*)d_out;

    cudaFuncSetAttribute(gemm_mma_k, cudaFuncAttributeMaxDynamicSharedMemorySize, DSMEM);
    cudaFuncSetAttribute(gemm_mid_mma_k, cudaFuncAttributeMaxDynamicSharedMemorySize, MDSMEM);

    float *T, *w1, *bl1, *bu1, *w2, *bl2, *bu2, *w3, *bl3, *bu3, *cl, *cu;
    float *m4a, *m4b, *bias4;
    __nv_bfloat16 *Ahi, *Alo, *W1th, *W1tl, *W2th, *W2tl;
    cudaGetSymbolAddress((void**)&T, g_T);
    cudaGetSymbolAddress((void**)&Ahi, g_Ahi);   cudaGetSymbolAddress((void**)&Alo, g_Alo);
    cudaGetSymbolAddress((void**)&W1th, g_W1t_hi); cudaGetSymbolAddress((void**)&W1tl, g_W1t_lo);
    cudaGetSymbolAddress((void**)&W2th, g_W2t_hi); cudaGetSymbolAddress((void**)&W2tl, g_W2t_lo);
    cudaGetSymbolAddress((void**)&w1, g_w1);   cudaGetSymbolAddress((void**)&bl1, g_bl1);
    cudaGetSymbolAddress((void**)&bu1, g_bu1);
    cudaGetSymbolAddress((void**)&w2, g_w2);   cudaGetSymbolAddress((void**)&bl2, g_bl2);
    cudaGetSymbolAddress((void**)&bu2, g_bu2);
    cudaGetSymbolAddress((void**)&w3, g_w3);   cudaGetSymbolAddress((void**)&bl3, g_bl3);
    cudaGetSymbolAddress((void**)&bu3, g_bu3);
    cudaGetSymbolAddress((void**)&cl, g_cl);   cudaGetSymbolAddress((void**)&cu, g_cu);
    cudaGetSymbolAddress((void**)&m4a, g_m4a); cudaGetSymbolAddress((void**)&m4b, g_m4b);
    cudaGetSymbolAddress((void**)&bias4, g_bias4);

    __nv_bfloat16* Thi = (__nv_bfloat16*)T;
    __nv_bfloat16* Tlo = ((__nv_bfloat16*)T) + (size_t)H * H;

    // one-time (per launch) B transpose+split
    transp_conv_k<<<dim3(KTOT / 32, (DIN + 31) / 32), dim3(32, 8)>>>(W1, DIN, W1th, W1tl);
    transp_conv_k<<<dim3(KTOT / 32, H / 32), dim3(32, 8)>>>(W2, H, W2th, W2tl);

    dim3 gmid(NPAD1 / 128, H / 64);          // 7 x 32 = 224 CTAs
    dim3 gbig(H / 128, H / 128);             // 16 x 16 = 256 CTAs

    // ---- stage 1 (fused concretize + spu) ----
    concretize_spu_k<<<H, 256>>>(W1, l_in, u_in, b1, p_l1, p_u1, w1, bl1, bu1);

    // ---- stage 2 ----
    bias2conv_k<<<H, 256>>>(W2, w1, bl1, bu1, b2, b1, cl, cu, Ahi, Alo);
    gemm_mid_mma_k<<<gmid, 256, MDSMEM>>>(Ahi, Alo, W1th, W1tl, cl, cu, l_in, u_in);
    spu_params_k<<<(H + 63) / 64, 64>>>(cl, cu, p_l2, p_u2, w2, bl2, bu2, H);

    // ---- stage 3 ----
    bias2conv_k<<<H, 256>>>(W3, w2, bl2, bu2, b3, b2, cl, cu, Ahi, Alo);
    gemm_mma_k<<<gbig, 256, DSMEM>>>(Ahi, Alo, W2th, W2tl, Thi, Tlo,
                                     w1, b1, bl1, bu1, cl, cu);
    gemm_mid_mma_k<<<gmid, 256, MDSMEM>>>(Thi, Tlo, W1th, W1tl, cl, cu, l_in, u_in);
    spu_params_k<<<(H + 63) / 64, 64>>>(cl, cu, p_l3, p_u3, w3, bl3, bu3, H);

    // ---- stage 4: output chain (9 rows) ----
    build_m4_k<<<(OUTR * H + 255) / 256, 256>>>(W4, b4, tl, m4a, bias4);
    small_bias_k<<<OUTR, 256>>>(m4a, w3, bl3, bu3, b3, bias4);
    zero_k<<<(OUTR * H + 255) / 256, 256>>>(m4b, OUTR * H);
    small_gemm_k<<<dim3((H + 127) / 128, H / SG_CHUNK), 128>>>(H, H, m4a, w3, W3, m4b);
    small_bias_k<<<OUTR, 256>>>(m4b, w2, bl2, bu2, b2, bias4);
    zero_k<<<(OUTR * H + 255) / 256, 256>>>(m4a, OUTR * H);
    small_gemm_k<<<dim3((H + 127) / 128, H / SG_CHUNK), 128>>>(H, H, m4b, w2, W2, m4a);
    small_bias_k<<<OUTR, 256>>>(m4a, w1, bl1, bu1, b1, bias4);
    zero_k<<<(OUTR * DIN + 255) / 256, 256>>>(m4b, OUTR * DIN);
    small_gemm_k<<<dim3((DIN + 127) / 128, H / SG_CHUNK), 128>>>(H, DIN, m4a, w1, W1, m4b);
    final_k<<<OUTR, 256>>>(m4b, l_in, u_in, bias4, out);
}

// round 11
// speedup vs baseline: 1.3677x; 1.0097x over previous
#include <cuda_runtime.h>
#include <cuda_bf16.h>
#include <math.h>
#include <stdint.h>

#define H     2048
#define DIN   784
#define OUTR  9
#define KTOT  2048
#define KC    32
#define NCHUNK (KTOT / KC)          // 64
#define TILEB  8192                 // 128 rows * 64B
#define STAGEB (4 * TILEB)          // 32KB
#define NSTAGE 3
#define DSMEM  (NSTAGE * STAGEB + 1024)
// mid-GEMM (64x128 tile) sizes
#define MTILEA 4096                 // 64 rows * 64B
#define MTILEB 8192                 // 128 rows * 64B
#define MSTAGE (2 * MTILEA + 2 * MTILEB)   // 24576
#define MDSMEM (NSTAGE * MSTAGE + 1024)
#define NPAD1  896

// ---------------- scratch (device globals) ----------------------------------
__device__ float g_T[H * H];        // reused as 2x bf16 [H*H] for stage-3 split
__device__ __nv_bfloat16 g_Ahi[H * H], g_Alo[H * H];
__device__ __nv_bfloat16 g_W1t_hi[NPAD1 * KTOT], g_W1t_lo[NPAD1 * KTOT];  // pad rows stay 0
__device__ __nv_bfloat16 g_W2t_hi[H * KTOT], g_W2t_lo[H * KTOT];
__device__ float g_w1[H], g_bl1[H], g_bu1[H];
__device__ float g_w2[H], g_bl2[H], g_bu2[H];
__device__ float g_w3[H], g_bl3[H], g_bu3[H];
__device__ float g_cl[H], g_cu[H];
__device__ float g_m4a[OUTR * H], g_m4b[OUTR * H];
__device__ float g_bias4[OUTR];

// ---------------- PTX helpers ------------------------------------------------
__device__ __forceinline__ uint32_t smem_u32(const void* p) {
    uint32_t a;
    asm("{ .reg .u64 t; cvta.to.shared.u64 t, %1; cvt.u32.u64 %0, t; }" : "=r"(a) : "l"(p));
    return a;
}
#define SWZ64(o)   ((o) ^ (((o) >> 3) & 0x30))
#define CP_ASYNC16(dst, gsrc) \
    asm volatile("cp.async.cg.shared.global [%0], [%1], 16;" :: "r"(dst), "l"(gsrc))
#define CP_COMMIT() asm volatile("cp.async.commit_group;" ::: "memory")
#define CP_WAIT(n)  asm volatile("cp.async.wait_group %0;" :: "n"(n) : "memory")
#define LDSM_X4(r0, r1, r2, r3, addr) \
    asm volatile("ldmatrix.sync.aligned.m8n8.x4.shared.b16 {%0,%1,%2,%3}, [%4];" \
        : "=r"(r0), "=r"(r1), "=r"(r2), "=r"(r3) : "r"(addr))
#define MMA16816(d, a, b) \
    asm volatile("mma.sync.aligned.m16n8k16.row.col.f32.bf16.bf16.f32 " \
        "{%0,%1,%2,%3}, {%4,%5,%6,%7}, {%8,%9}, {%0,%1,%2,%3};" \
        : "+f"((d)[0]), "+f"((d)[1]), "+f"((d)[2]), "+f"((d)[3]) \
        : "r"((a)[0]), "r"((a)[1]), "r"((a)[2]), "r"((a)[3]), "r"((b)[0]), "r"((b)[1]))

// ---------------- misc helpers ----------------------------------------------
__device__ __forceinline__ float spu_f(float x) {
    if (x >= 0.f) return x * x - 0.5f;
    float s = 1.f / (1.f + expf(x));
    return s - 1.f;
}
__device__ __forceinline__ float dspu_f(float x) {
    if (x >= 0.f) return 2.f * x;
    float s = 1.f / (1.f + expf(x));
    return -s * (1.f - s);
}
__device__ __forceinline__ void spu_relax(float l, float u, float pl, float pu,
                                          float &w_, float &bl_, float &bu_) {
    float k1 = dspu_f(l), k2 = dspu_f(u);
    float klo = fminf(k1, k2), khi = fmaxf(k1, k2);
    float wl = fminf(fmaxf(pl, klo), khi);
    float wu = fminf(fmaxf(pu, klo), khi);
    float p0 = l, p1 = u, p2 = 0.5f * (l + u), p3 = fminf(fmaxf(0.f, l), u);
    float s0 = spu_f(p0), s1 = spu_f(p1), s2 = spu_f(p2), s3 = spu_f(p3);
    bl_ = fminf(fminf(s0 - wl * p0, s1 - wl * p1), fminf(s2 - wl * p2, s3 - wl * p3));
    bu_ = fmaxf(fmaxf(s0 - wu * p0, s1 - wu * p1), fmaxf(s2 - wu * p2, s3 - wu * p3));
    w_ = wl;
}
// block reduce, supports up to 16 warps (blockDim <= 512)
__device__ __forceinline__ void blk_reduce2(float &a, float &b) {
    const unsigned m = 0xffffffffu;
    #pragma unroll
    for (int o = 16; o > 0; o >>= 1) {
        a += __shfl_down_sync(m, a, o);
        b += __shfl_down_sync(m, b, o);
    }
    __shared__ float sa[16], sb[16];
    int w = threadIdx.x >> 5, l = threadIdx.x & 31;
    int nw = blockDim.x >> 5;
    if (l == 0) { sa[w] = a; sb[w] = b; }
    __syncthreads();
    if (w == 0) {
        a = (l < nw) ? sa[l] : 0.f;
        b = (l < nw) ? sb[l] : 0.f;
        #pragma unroll
        for (int o = 8; o > 0; o >>= 1) {
            a += __shfl_down_sync(m, a, o);
            b += __shfl_down_sync(m, b, o);
        }
    }
}

// ---------------- fused stage-1: concretize W1 row + SPU params (float4) -----
__global__ void concretize_spu_k(const float* __restrict__ W1v,
                                 const float* __restrict__ lin, const float* __restrict__ uin,
                                 const float* __restrict__ b1v,
                                 const float* __restrict__ pl, const float* __restrict__ pu,
                                 float* __restrict__ w, float* __restrict__ bl,
                                 float* __restrict__ bu) {
    int row = blockIdx.x;
    const float* a = W1v + (size_t)row * DIN;   // DIN = 784 = 196 float4 exactly
    float al = 0.f, au = 0.f;
    for (int j = threadIdx.x * 4; j < DIN; j += blockDim.x * 4) {
        float4 v = *(const float4*)(a + j);
        float4 L = *(const float4*)(lin + j);
        float4 U = *(const float4*)(uin + j);
        float pA = fmaxf(v.x, 0.f), nA = fminf(v.x, 0.f);
        float pB = fmaxf(v.y, 0.f), nB = fminf(v.y, 0.f);
        float pC = fmaxf(v.z, 0.f), nC = fminf(v.z, 0.f);
        float pD = fmaxf(v.w, 0.f), nD = fminf(v.w, 0.f);
        al += pA * L.x + nA * U.x + pB * L.y + nB * U.y
            + pC * L.z + nC * U.z + pD * L.w + nD * U.w;
        au += pA * U.x + nA * L.x + pB * U.y + nB * L.y
            + pC * U.z + nC * L.z + pD * U.w + nD * L.w;
    }
    blk_reduce2(al, au);
    if (threadIdx.x == 0) {
        float l = al + b1v[row], u = au + b1v[row];
        float w_, bl_, bu_;
        spu_relax(l, u, pl[row], pu[row], w_, bl_, bu_);
        w[row] = w_; bl[row] = bl_; bu[row] = bu_;
    }
}

__global__ void spu_params_k(const float* __restrict__ lf, const float* __restrict__ uf,
                             const float* __restrict__ pl, const float* __restrict__ pu,
                             float* __restrict__ w, float* __restrict__ bl,
                             float* __restrict__ bu, int n) {
    int i = blockIdx.x * blockDim.x + threadIdx.x;
    if (i >= n) return;
    float w_, bl_, bu_;
    spu_relax(lf[i], uf[i], pl[i], pu[i], w_, bl_, bu_);
    w[i] = w_; bl[i] = bl_; bu[i] = bu_;
}

// bias + bf16 split, 512 threads: single float4 iteration per row
__global__ __launch_bounds__(512)
void bias2conv_k(const float* __restrict__ W,
                 const float* __restrict__ wprev,
                 const float* __restrict__ blprev, const float* __restrict__ buprev,
                 const float* __restrict__ bthis, const float* __restrict__ bprev,
                 float* __restrict__ cl, float* __restrict__ cu,
                 __nv_bfloat16* __restrict__ hi, __nv_bfloat16* __restrict__ lo) {
    int row = blockIdx.x;
    const float* wr = W + (size_t)row * H;
    __nv_bfloat16* hr = hi + (size_t)row * H;
    __nv_bfloat16* lr = lo + (size_t)row * H;
    float al = 0.f, au = 0.f;
    int j = threadIdx.x * 4;                 // 512*4 = 2048 = H exactly
    {
        float4 v  = *(const float4*)(wr + j);
        float4 wp = *(const float4*)(wprev + j);
        float4 bp = *(const float4*)(bprev + j);
        float4 bL = *(const float4*)(blprev + j);
        float4 bU = *(const float4*)(buprev + j);
        float m0 = v.x * wp.x, m1 = v.y * wp.y, m2 = v.z * wp.z, m3 = v.w * wp.w;
        float sb = m0 * bp.x + m1 * bp.y + m2 * bp.z + m3 * bp.w;
        float pA = fmaxf(v.x, 0.f), nA = fminf(v.x, 0.f);
        float pB = fmaxf(v.y, 0.f), nB = fminf(v.y, 0.f);
        float pC = fmaxf(v.z, 0.f), nC = fminf(v.z, 0.f);
        float pD = fmaxf(v.w, 0.f), nD = fminf(v.w, 0.f);
        al += pA * bL.x + nA * bU.x + pB * bL.y + nB * bU.y
            + pC * bL.z + nC * bU.z + pD * bL.w + nD * bU.w + sb;
        au += pA * bU.x + nA * bL.x + pB * bU.y + nB * bL.y
            + pC * bU.z + nC * bL.z + pD * bU.w + nD * bL.w + sb;
        __nv_bfloat16 h0 = __float2bfloat16(m0), h1 = __float2bfloat16(m1);
        __nv_bfloat16 h2 = __float2bfloat16(m2), h3 = __float2bfloat16(m3);
        __nv_bfloat162 hv0; hv0.x = h0; hv0.y = h1;
        __nv_bfloat162 hv1; hv1.x = h2; hv1.y = h3;
        *(__nv_bfloat162*)(hr + j)     = hv0;
        *(__nv_bfloat162*)(hr + j + 2) = hv1;
        __nv_bfloat162 lv0, lv1;
        lv0.x = __float2bfloat16(m0 - __bfloat162float(h0));
        lv0.y = __float2bfloat16(m1 - __bfloat162float(h1));
        lv1.x = __float2bfloat16(m2 - __bfloat162float(h2));
        lv1.y = __float2bfloat16(m3 - __bfloat162float(h3));
        *(__nv_bfloat162*)(lr + j)     = lv0;
        *(__nv_bfloat162*)(lr + j + 2) = lv1;
    }
    blk_reduce2(al, au);
    if (threadIdx.x == 0) { cl[row] = bthis[row] + al; cu[row] = bthis[row] + au; }
}

// B [K x N] fp32 -> Bt_hi/lo [Npad x K] bf16. Tile: 64 k-rows x 32 n-cols.
// Coalesced 128B reads; bf16x2 writes (2 k per lane) -> 128B store transactions.
__global__ void transp_conv_k(const float* __restrict__ B, int N,
                              __nv_bfloat16* __restrict__ thi, __nv_bfloat16* __restrict__ tlo) {
    __shared__ float t[64][33];
    int k0 = blockIdx.x * 64, n0 = blockIdx.y * 32;
    int x = threadIdx.x, y = threadIdx.y;       // 32 x 8
    #pragma unroll
    for (int yy = y; yy < 64; yy += 8) {
        int n = n0 + x;
        t[yy][x] = (n < N) ? B[(size_t)(k0 + yy) * N + n] : 0.f;
    }
    __syncthreads();
    #pragma unroll
    for (int nn = y; nn < 32; nn += 8) {
        int n = n0 + nn;
        if (n < N) {
            float v0 = t[2 * x][nn], v1 = t[2 * x + 1][nn];
            __nv_bfloat16 h0 = __float2bfloat16(v0), h1 = __float2bfloat16(v1);
            __nv_bfloat162 hv; hv.x = h0; hv.y = h1;
            __nv_bfloat162 lv;
            lv.x = __float2bfloat16(v0 - __bfloat162float(h0));
            lv.y = __float2bfloat16(v1 - __bfloat162float(h1));
            size_t base = (size_t)n * KTOT + k0 + 2 * x;
            *(__nv_bfloat162*)(thi + base) = hv;
            *(__nv_bfloat162*)(tlo + base) = lv;
        }
    }
}

// ---------------- big GEMM: 128x128 tile, MODE 0 fused epilogue ---------------
__global__ __launch_bounds__(256, 2)
void gemm_mma_k(const __nv_bfloat16* __restrict__ Ahi, const __nv_bfloat16* __restrict__ Alo,
                const __nv_bfloat16* __restrict__ Bhi, const __nv_bfloat16* __restrict__ Blo,
                __nv_bfloat16* __restrict__ Ohi, __nv_bfloat16* __restrict__ Olo,
                const float* __restrict__ scale, const float* __restrict__ bvec,
                const float* __restrict__ blv, const float* __restrict__ buv,
                float* __restrict__ cl, float* __restrict__ cu) {
    extern __shared__ char dsm[];
    uint32_t raw = smem_u32(dsm);
    uint32_t dbase = (raw + 1023) & ~1023u;

    int tid = threadIdx.x, wid = tid >> 5, lane = tid & 31;
    int brow = blockIdx.y * 128, bcol = blockIdx.x * 128;
    int wm = (wid >> 2) * 64, wn = (wid & 3) * 32;

    const __nv_bfloat16* gbase[4] = {
        Ahi + (size_t)brow * KTOT, Alo + (size_t)brow * KTOT,
        Bhi + (size_t)bcol * KTOT, Blo + (size_t)bcol * KTOT };
    const __nv_bfloat16* gsrc[8];
    uint32_t sdst[8];
    #pragma unroll
    for (int i = 0; i < 8; i++) {
        int s = i * 256 + tid;
        int t = s >> 9, row = (s >> 2) & 127, sg = s & 3;
        gsrc[i] = gbase[t] + (size_t)row * KTOT + sg * 8;
        sdst[i] = (uint32_t)(t * TILEB) + SWZ64((uint32_t)(row * 64 + sg * 16));
    }

    float acc[4][4][4];
    #pragma unroll
    for (int mt = 0; mt < 4; mt++)
        #pragma unroll
        for (int nt = 0; nt < 4; nt++)
            #pragma unroll
            for (int q = 0; q < 4; q++) acc[mt][nt][q] = 0.f;

    int l15 = lane & 15, lhi = lane >> 4;

    #pragma unroll
    for (int st = 0; st < 2; st++) {
        uint32_t sb = dbase + st * STAGEB;
        int k0 = st * KC;
        #pragma unroll
        for (int i = 0; i < 8; i++) CP_ASYNC16(sb + sdst[i], gsrc[i] + k0);
        CP_COMMIT();
    }

    int stage = 0;
    for (int chunk = 0; chunk < NCHUNK; chunk++) {
        if (chunk + 1 < NCHUNK) CP_WAIT(1); else CP_WAIT(0);
        __syncthreads();
        if (chunk + 2 < NCHUNK) {
            int ns = stage + 2; if (ns >= NSTAGE) ns -= NSTAGE;
            uint32_t sb = dbase + ns * STAGEB;
            int k0 = (chunk + 2) * KC;
            #pragma unroll
            for (int i = 0; i < 8; i++) CP_ASYNC16(sb + sdst[i], gsrc[i] + k0);
            CP_COMMIT();
        }
        uint32_t ah_b = dbase + stage * STAGEB;
        uint32_t al_b = ah_b + TILEB, bh_b = ah_b + 2 * TILEB, bl_b = ah_b + 3 * TILEB;
        #pragma unroll
        for (int kb = 0; kb < 2; kb++) {
            uint32_t kbyte = (uint32_t)(kb * 32 + lhi * 16);
            uint32_t ahi_f[4][4], alo_f[4][4];
            #pragma unroll
            for (int mt = 0; mt < 4; mt++) {
                uint32_t off = SWZ64((uint32_t)((wm + mt * 16 + l15) * 64) + kbyte);
                LDSM_X4(ahi_f[mt][0], ahi_f[mt][1], ahi_f[mt][2], ahi_f[mt][3], ah_b + off);
                LDSM_X4(alo_f[mt][0], alo_f[mt][1], alo_f[mt][2], alo_f[mt][3], al_b + off);
            }
            #pragma unroll
            for (int p = 0; p < 2; p++) {
                uint32_t off = SWZ64((uint32_t)((wn + p * 16 + l15) * 64) + kbyte);
                uint32_t r0, r1, r2, r3;
                uint32_t bhi0[2], bhi1[2], blo0[2], blo1[2];
                LDSM_X4(r0, r1, r2, r3, bh_b + off);
                bhi0[0] = r0; bhi0[1] = r2; bhi1[0] = r1; bhi1[1] = r3;
                LDSM_X4(r0, r1, r2, r3, bl_b + off);
                blo0[0] = r0; blo0[1] = r2; blo1[0] = r1; blo1[1] = r3;
                #pragma unroll
                for (int mt = 0; mt < 4; mt++) {
                    MMA16816(acc[mt][2 * p], ahi_f[mt], bhi0);
                    MMA16816(acc[mt][2 * p], ahi_f[mt], blo0);
                    MMA16816(acc[mt][2 * p], alo_f[mt], bhi0);
                    MMA16816(acc[mt][2 * p + 1], ahi_f[mt], bhi1);
                    MMA16816(acc[mt][2 * p + 1], ahi_f[mt], blo1);
                    MMA16816(acc[mt][2 * p + 1], alo_f[mt], bhi1);
                }
            }
        }
        stage++; if (stage >= NSTAGE) stage -= NSTAGE;
    }

    #pragma unroll
    for (int mt = 0; mt < 4; mt++) {
        #pragma unroll
        for (int q = 0; q < 2; q++) {
            int gr = brow + wm + mt * 16 + (lane >> 2) + q * 8;
            float pl = 0.f, pu = 0.f;
            #pragma unroll
            for (int nt = 0; nt < 4; nt++) {
                int gc = bcol + wn + nt * 8 + (lane & 3) * 2;
                float v0 = acc[mt][nt][q * 2 + 0];
                float v1 = acc[mt][nt][q * 2 + 1];
                float m0 = v0 * scale[gc], m1 = v1 * scale[gc + 1];
                __nv_bfloat16 h0 = __float2bfloat16(m0);
                __nv_bfloat16 h1 = __float2bfloat16(m1);
                __nv_bfloat162 hv; hv.x = h0; hv.y = h1;
                *(__nv_bfloat162*)(Ohi + (size_t)gr * H + gc) = hv;
                __nv_bfloat162 lv;
                lv.x = __float2bfloat16(m0 - __bfloat162float(h0));
                lv.y = __float2bfloat16(m1 - __bfloat162float(h1));
                *(__nv_bfloat162*)(Olo + (size_t)gr * H + gc) = lv;
                float p0 = fmaxf(v0, 0.f), n0 = fminf(v0, 0.f);
                float p1 = fmaxf(v1, 0.f), n1 = fminf(v1, 0.f);
                float sb = m0 * bvec[gc] + m1 * bvec[gc + 1];
                pl += p0 * blv[gc] + n0 * buv[gc] + p1 * blv[gc + 1] + n1 * buv[gc + 1] + sb;
                pu += p0 * buv[gc] + n0 * blv[gc] + p1 * buv[gc + 1] + n1 * blv[gc + 1] + sb;
            }
            pl += __shfl_xor_sync(0xffffffffu, pl, 1);
            pl += __shfl_xor_sync(0xffffffffu, pl, 2);
            pu += __shfl_xor_sync(0xffffffffu, pu, 1);
            pu += __shfl_xor_sync(0xffffffffu, pu, 2);
            if ((lane & 3) == 0) {
                atomicAdd(&cl[gr], pl);
                atomicAdd(&cu[gr], pu);
            }
        }
    }
}

// ---------------- mid GEMM: 64x128 tile, MODE 1 (concretize) epilogue ---------
__global__ __launch_bounds__(256, 2)
void gemm_mid_mma_k(const __nv_bfloat16* __restrict__ Ahi, const __nv_bfloat16* __restrict__ Alo,
                    const __nv_bfloat16* __restrict__ Bhi, const __nv_bfloat16* __restrict__ Blo,
                    float* __restrict__ cl, float* __restrict__ cu,
                    const float* __restrict__ lin, const float* __restrict__ uin) {
    extern __shared__ char dsm[];
    uint32_t raw = smem_u32(dsm);
    uint32_t dbase = (raw + 1023) & ~1023u;

    int tid = threadIdx.x, wid = tid >> 5, lane = tid & 31;
    int brow = blockIdx.y * 64, bcol = blockIdx.x * 128;
    int wm = (wid >> 2) * 32, wn = (wid & 3) * 32;

    const __nv_bfloat16* gsrc[6];
    uint32_t sdst[6];
    #pragma unroll
    for (int i = 0; i < 6; i++) {
        int s = i * 256 + tid;
        int rowg = s >> 2, sg = s & 3;
        if (rowg < 128) {
            int t = rowg >> 6, r = rowg & 63;
            gsrc[i] = (t ? Alo : Ahi) + (size_t)(brow + r) * KTOT + sg * 8;
            sdst[i] = (uint32_t)(t * MTILEA) + SWZ64((uint32_t)(r * 64 + sg * 16));
        } else {
            int rr = rowg - 128;
            int t = rr >> 7, r = rr & 127;
            gsrc[i] = (t ? Blo : Bhi) + (size_t)(bcol + r) * KTOT + sg * 8;
            sdst[i] = (uint32_t)(2 * MTILEA + t * MTILEB) + SWZ64((uint32_t)(r * 64 + sg * 16));
        }
    }

    float acc[2][4][4];
    #pragma unroll
    for (int mt = 0; mt < 2; mt++)
        #pragma unroll
        for (int nt = 0; nt < 4; nt++)
            #pragma unroll
            for (int q = 0; q < 4; q++) acc[mt][nt][q] = 0.f;

    int l15 = lane & 15, lhi = lane >> 4;

    #pragma unroll
    for (int st = 0; st < 2; st++) {
        uint32_t sb = dbase + st * MSTAGE;
        int k0 = st * KC;
        #pragma unroll
        for (int i = 0; i < 6; i++) CP_ASYNC16(sb + sdst[i], gsrc[i] + k0);
        CP_COMMIT();
    }

    int stage = 0;
    for (int chunk = 0; chunk < NCHUNK; chunk++) {
        if (chunk + 1 < NCHUNK) CP_WAIT(1); else CP_WAIT(0);
        __syncthreads();
        if (chunk + 2 < NCHUNK) {
            int ns = stage + 2; if (ns >= NSTAGE) ns -= NSTAGE;
            uint32_t sb = dbase + ns * MSTAGE;
            int k0 = (chunk + 2) * KC;
            #pragma unroll
            for (int i = 0; i < 6; i++) CP_ASYNC16(sb + sdst[i], gsrc[i] + k0);
            CP_COMMIT();
        }
        uint32_t ah_b = dbase + stage * MSTAGE;
        uint32_t al_b = ah_b + MTILEA;
        uint32_t bh_b = ah_b + 2 * MTILEA, bl_b = bh_b + MTILEB;
        #pragma unroll
        for (int kb = 0; kb < 2; kb++) {
            uint32_t kbyte = (uint32_t)(kb * 32 + lhi * 16);
            uint32_t ahi_f[2][4], alo_f[2][4];
            #pragma unroll
            for (int mt = 0; mt < 2; mt++) {
                uint32_t off = SWZ64((uint32_t)((wm + mt * 16 + l15) * 64) + kbyte);
                LDSM_X4(ahi_f[mt][0], ahi_f[mt][1], ahi_f[mt][2], ahi_f[mt][3], ah_b + off);
                LDSM_X4(alo_f[mt][0], alo_f[mt][1], alo_f[mt][2], alo_f[mt][3], al_b + off);
            }
            #pragma unroll
            for (int p = 0; p < 2; p++) {
                uint32_t off = SWZ64((uint32_t)((wn + p * 16 + l15) * 64) + kbyte);
                uint32_t r0, r1, r2, r3;
                uint32_t bhi0[2], bhi1[2], blo0[2], blo1[2];
                LDSM_X4(r0, r1, r2, r3, bh_b + off);
                bhi0[0] = r0; bhi0[1] = r2; bhi1[0] = r1; bhi1[1] = r3;
                LDSM_X4(r0, r1, r2, r3, bl_b + off);
                blo0[0] = r0; blo0[1] = r2; blo1[0] = r1; blo1[1] = r3;
                #pragma unroll
                for (int mt = 0; mt < 2; mt++) {
                    MMA16816(acc[mt][2 * p], ahi_f[mt], bhi0);
                    MMA16816(acc[mt][2 * p], ahi_f[mt], blo0);
                    MMA16816(acc[mt][2 * p], alo_f[mt], bhi0);
                    MMA16816(acc[mt][2 * p + 1], ahi_f[mt], bhi1);
                    MMA16816(acc[mt][2 * p + 1], ahi_f[mt], blo1);
                    MMA16816(acc[mt][2 * p + 1], alo_f[mt], bhi1);
                }
            }
        }
        stage++; if (stage >= NSTAGE) stage -= NSTAGE;
    }

    #pragma unroll
    for (int mt = 0; mt < 2; mt++) {
        #pragma unroll
        for (int q = 0; q < 2; q++) {
            int gr = brow + wm + mt * 16 + (lane >> 2) + q * 8;
            float pl = 0.f, pu = 0.f;
            #pragma unroll
            for (int nt = 0; nt < 4; nt++) {
                int gc = bcol + wn + nt * 8 + (lane & 3) * 2;
                if (gc < DIN) {
                    float v0 = acc[mt][nt][q * 2 + 0];
                    float v1 = acc[mt][nt][q * 2 + 1];
                    float l0 = lin[gc], u0 = uin[gc];
                    float l1 = lin[gc + 1], u1 = uin[gc + 1];
                    float p0 = fmaxf(v0, 0.f), n0 = fminf(v0, 0.f);
                    float p1 = fmaxf(v1, 0.f), n1 = fminf(v1, 0.f);
                    pl += p0 * l0 + n0 * u0 + p1 * l1 + n1 * u1;
                    pu += p0 * u0 + n0 * l0 + p1 * u1 + n1 * l1;
                }
            }
            pl += __shfl_xor_sync(0xffffffffu, pl, 1);
            pl += __shfl_xor_sync(0xffffffffu, pl, 2);
            pu += __shfl_xor_sync(0xffffffffu, pu, 1);
            pu += __shfl_xor_sync(0xffffffffu, pu, 2);
            if ((lane & 3) == 0) {
                atomicAdd(&cl[gr], pl);
                atomicAdd(&cu[gr], pu);
            }
        }
    }
}

// ---------------- output stage (9 rows) ---------------------------------------
__global__ void build_m4_k(const float* __restrict__ W4, const float* __restrict__ b4,
                           const int* __restrict__ tl, float* __restrict__ M,
                           float* __restrict__ bias) {
    int t = *tl;
    int idx = blockIdx.x * blockDim.x + threadIdx.x;
    if (idx < OUTR * H) {
        int r = idx / H, j = idx % H;
        int c = (r < t) ? r : r + 1;
        M[idx] = W4[(size_t)c * H + j] - W4[(size_t)t * H + j];
    }
    if (idx < OUTR) {
        int c = (idx < t) ? idx : idx + 1;
        bias[idx] = b4[c] - b4[t];
    }
}

__global__ void small_bias_k(const float* __restrict__ A,
                             const float* __restrict__ w, const float* __restrict__ bl,
                             const float* __restrict__ bu, const float* __restrict__ bnext,
                             float* __restrict__ bias) {
    int r = blockIdx.x;
    const float* a = A + (size_t)r * H;
    float au = 0.f, dummy = 0.f;
    for (int j = threadIdx.x; j < H; j += blockDim.x) {
        float v = a[j];
        float p = fmaxf(v, 0.f), n = fminf(v, 0.f);
        au += p * bu[j] + n * bl[j] + v * w[j] * bnext[j];
    }
    blk_reduce2(au, dummy);
    if (threadIdx.x == 0) bias[r] += au;
}

__global__ void zero_k(float* __restrict__ p, int n) {
    int i = blockIdx.x * blockDim.x + threadIdx.x;
    if (i < n) p[i] = 0.f;
}

#define SG_CHUNK 256
__global__ void small_gemm_k(int K, int N, const float* __restrict__ A,
                             const float* __restrict__ ascale,
                             const float* __restrict__ B, float* __restrict__ C) {
    __shared__ float sA[OUTR * SG_CHUNK];
    int k0 = blockIdx.y * SG_CHUNK;
    int n = blockIdx.x * blockDim.x + threadIdx.x;
    for (int idx = threadIdx.x; idx < OUTR * SG_CHUNK; idx += blockDim.x) {
        int r = idx / SG_CHUNK, kk = idx % SG_CHUNK;
        sA[idx] = A[(size_t)r * K + k0 + kk] * ascale[k0 + kk];
    }
    __syncthreads();
    if (n >= N) return;
    float acc[OUTR];
    #pragma unroll
    for (int r = 0; r < OUTR; r++) acc[r] = 0.f;
    #pragma unroll 4
    for (int kk = 0; kk < SG_CHUNK; kk++) {
        float bv = B[(size_t)(k0 + kk) * N + n];
        #pragma unroll
        for (int r = 0; r < OUTR; r++) acc[r] += sA[r * SG_CHUNK + kk] * bv;
    }
    #pragma unroll
    for (int r = 0; r < OUTR; r++) atomicAdd(&C[(size_t)r * N + n], acc[r]);
}

__global__ void final_k(const float* __restrict__ M, const float* __restrict__ lin,
                        const float* __restrict__ uin, const float* __restrict__ bias,
                        float* __restrict__ out) {
    int r = blockIdx.x;
    const float* a = M + (size_t)r * DIN;
    float au = 0.f, dummy = 0.f;
    for (int j = threadIdx.x; j < DIN; j += blockDim.x) {
        float v = a[j];
        au += fmaxf(v, 0.f) * uin[j] + fminf(v, 0.f) * lin[j];
    }
    blk_reduce2(au, dummy);
    if (threadIdx.x == 0) out[r] = au + bias[r];
}

// ---------------- launch ------------------------------------------------------
extern "C" void kernel_launch(void* const* d_in, const int* in_sizes, int n_in,
                              void* d_out, int out_size) {
    const float* W1 = (const float*)d_in[0];
    const float* b1 = (const float*)d_in[1];
    const float* W2 = (const float*)d_in[2];
    const float* b2 = (const float*)d_in[3];
    const float* W3 = (const float*)d_in[4];
    const float* b3 = (const float*)d_in[5];
    const float* W4 = (const float*)d_in[6];
    const float* b4 = (const float*)d_in[7];
    const float* l_in = (const float*)d_in[8];
    const float* u_in = (const float*)d_in[9];
    const float* p_l1 = (const float*)d_in[10];
    const float* p_u1 = (const float*)d_in[11];
    const float* p_l2 = (const float*)d_in[12];
    const float* p_u2 = (const float*)d_in[13];
    const float* p_l3 = (const float*)d_in[14];
    const float* p_u3 = (const float*)d_in[15];
    const int* tl = (const int*)d_in[16];
    float* out = (float*)d_out;

    cudaFuncSetAttribute(gemm_mma_k, cudaFuncAttributeMaxDynamicSharedMemorySize, DSMEM);
    cudaFuncSetAttribute(gemm_mid_mma_k, cudaFuncAttributeMaxDynamicSharedMemorySize, MDSMEM);

    float *T, *w1, *bl1, *bu1, *w2, *bl2, *bu2, *w3, *bl3, *bu3, *cl, *cu;
    float *m4a, *m4b, *bias4;
    __nv_bfloat16 *Ahi, *Alo, *W1th, *W1tl, *W2th, *W2tl;
    cudaGetSymbolAddress((void**)&T, g_T);
    cudaGetSymbolAddress((void**)&Ahi, g_Ahi);   cudaGetSymbolAddress((void**)&Alo, g_Alo);
    cudaGetSymbolAddress((void**)&W1th, g_W1t_hi); cudaGetSymbolAddress((void**)&W1tl, g_W1t_lo);
    cudaGetSymbolAddress((void**)&W2th, g_W2t_hi); cudaGetSymbolAddress((void**)&W2tl, g_W2t_lo);
    cudaGetSymbolAddress((void**)&w1, g_w1);   cudaGetSymbolAddress((void**)&bl1, g_bl1);
    cudaGetSymbolAddress((void**)&bu1, g_bu1);
    cudaGetSymbolAddress((void**)&w2, g_w2);   cudaGetSymbolAddress((void**)&bl2, g_bl2);
    cudaGetSymbolAddress((void**)&bu2, g_bu2);
    cudaGetSymbolAddress((void**)&w3, g_w3);   cudaGetSymbolAddress((void**)&bl3, g_bl3);
    cudaGetSymbolAddress((void**)&bu3, g_bu3);
    cudaGetSymbolAddress((void**)&cl, g_cl);   cudaGetSymbolAddress((void**)&cu, g_cu);
    cudaGetSymbolAddress((void**)&m4a, g_m4a); cudaGetSymbolAddress((void**)&m4b, g_m4b);
    cudaGetSymbolAddress((void**)&bias4, g_bias4);

    __nv_bfloat16* Thi = (__nv_bfloat16*)T;
    __nv_bfloat16* Tlo = ((__nv_bfloat16*)T) + (size_t)H * H;

    // one-time (per launch) B transpose+split (64k x 32n tiles)
    transp_conv_k<<<dim3(KTOT / 64, (DIN + 31) / 32), dim3(32, 8)>>>(W1, DIN, W1th, W1tl);
    transp_conv_k<<<dim3(KTOT / 64, H / 32), dim3(32, 8)>>>(W2, H, W2th, W2tl);

    dim3 gmid(NPAD1 / 128, H / 64);          // 7 x 32 = 224 CTAs
    dim3 gbig(H / 128, H / 128);             // 16 x 16 = 256 CTAs

    // ---- stage 1 (fused concretize + spu) ----
    concretize_spu_k<<<H, 256>>>(W1, l_in, u_in, b1, p_l1, p_u1, w1, bl1, bu1);

    // ---- stage 2 ----
    bias2conv_k<<<H, 512>>>(W2, w1, bl1, bu1, b2, b1, cl, cu, Ahi, Alo);
    gemm_mid_mma_k<<<gmid, 256, MDSMEM>>>(Ahi, Alo, W1th, W1tl, cl, cu, l_in, u_in);
    spu_params_k<<<(H + 63) / 64, 64>>>(cl, cu, p_l2, p_u2, w2, bl2, bu2, H);

    // ---- stage 3 ----
    bias2conv_k<<<H, 512>>>(W3, w2, bl2, bu2, b3, b2, cl, cu, Ahi, Alo);
    gemm_mma_k<<<gbig, 256, DSMEM>>>(Ahi, Alo, W2th, W2tl, Thi, Tlo,
                                     w1, b1, bl1, bu1, cl, cu);
    gemm_mid_mma_k<<<gmid, 256, MDSMEM>>>(Thi, Tlo, W1th, W1tl, cl, cu, l_in, u_in);
    spu_params_k<<<(H + 63) / 64, 64>>>(cl, cu, p_l3, p_u3, w3, bl3, bu3, H);

    // ---- stage 4: output chain (9 rows) ----
    build_m4_k<<<(OUTR * H + 255) / 256, 256>>>(W4, b4, tl, m4a, bias4);
    small_bias_k<<<OUTR, 256>>>(m4a, w3, bl3, bu3, b3, bias4);
    zero_k<<<(OUTR * H + 255) / 256, 256>>>(m4b, OUTR * H);
    small_gemm_k<<<dim3((H + 127) / 128, H / SG_CHUNK), 128>>>(H, H, m4a, w3, W3, m4b);
    small_bias_k<<<OUTR, 256>>>(m4b, w2, bl2, bu2, b2, bias4);
    zero_k<<<(OUTR * H + 255) / 256, 256>>>(m4a, OUTR * H);
    small_gemm_k<<<dim3((H + 127) / 128, H / SG_CHUNK), 128>>>(H, H, m4b, w2, W2, m4a);
    small_bias_k<<<OUTR, 256>>>(m4a, w1, bl1, bu1, b1, bias4);
    zero_k<<<(OUTR * DIN + 255) / 256, 256>>>(m4b, OUTR * DIN);
    small_gemm_k<<<dim3((DIN + 127) / 128, H / SG_CHUNK), 128>>>(H, DIN, m4a, w1, W1, m4b);
    final_k<<<OUTR, 256>>>(m4b, l_in, u_in, bias4, out);
}

// round 12
// speedup vs baseline: 1.8184x; 1.3295x over previous
#include <cuda_runtime.h>
#include <cuda_fp16.h>
#include <math.h>
#include <stdint.h>

#define H     2048
#define DIN   784
#define OUTR  9
#define KTOT  2048
#define KC    32
#define NCHUNK (KTOT / KC)          // 64
#define TILEB  8192                 // 128 rows * 64B
#define STAGEB (3 * TILEB)          // 24KB: Ahi, Bhi, Blo
#define NSTAGE 3
#define DSMEM  (NSTAGE * STAGEB + 1024)
// mid-GEMM (64x128 tile) sizes
#define MTILEA 4096                 // 64 rows * 64B (A hi only)
#define MTILEB 8192                 // 128 rows * 64B
#define MSTAGE (MTILEA + 2 * MTILEB)       // 20480
#define MDSMEM (NSTAGE * MSTAGE + 1024)
#define NPAD1  896

// ---------------- scratch (device globals) ----------------------------------
__device__ float g_T[H * H];        // reused as half[H*H] for stage-3 Thi
__device__ __half g_Ahi[H * H];
__device__ __half g_W1t_hi[NPAD1 * KTOT], g_W1t_lo[NPAD1 * KTOT];  // pad rows stay 0
__device__ __half g_W2t_hi[H * KTOT], g_W2t_lo[H * KTOT];
__device__ float g_w1[H], g_bl1[H], g_bu1[H];
__device__ float g_w2[H], g_bl2[H], g_bu2[H];
__device__ float g_w3[H], g_bl3[H], g_bu3[H];
__device__ float g_cl[H], g_cu[H];
__device__ float g_m4a[OUTR * H], g_m4b[OUTR * H];
__device__ float g_bias4[OUTR];

// ---------------- PTX helpers ------------------------------------------------
__device__ __forceinline__ uint32_t smem_u32(const void* p) {
    uint32_t a;
    asm("{ .reg .u64 t; cvta.to.shared.u64 t, %1; cvt.u32.u64 %0, t; }" : "=r"(a) : "l"(p));
    return a;
}
#define SWZ64(o)   ((o) ^ (((o) >> 3) & 0x30))
#define CP_ASYNC16(dst, gsrc) \
    asm volatile("cp.async.cg.shared.global [%0], [%1], 16;" :: "r"(dst), "l"(gsrc))
#define CP_COMMIT() asm volatile("cp.async.commit_group;" ::: "memory")
#define CP_WAIT(n)  asm volatile("cp.async.wait_group %0;" :: "n"(n) : "memory")
#define LDSM_X4(r0, r1, r2, r3, addr) \
    asm volatile("ldmatrix.sync.aligned.m8n8.x4.shared.b16 {%0,%1,%2,%3}, [%4];" \
        : "=r"(r0), "=r"(r1), "=r"(r2), "=r"(r3) : "r"(addr))
#define MMA16816(d, a, b) \
    asm volatile("mma.sync.aligned.m16n8k16.row.col.f32.f16.f16.f32 " \
        "{%0,%1,%2,%3}, {%4,%5,%6,%7}, {%8,%9}, {%0,%1,%2,%3};" \
        : "+f"((d)[0]), "+f"((d)[1]), "+f"((d)[2]), "+f"((d)[3]) \
        : "r"((a)[0]), "r"((a)[1]), "r"((a)[2]), "r"((a)[3]), "r"((b)[0]), "r"((b)[1]))

// ---------------- misc helpers ----------------------------------------------
__device__ __forceinline__ float spu_f(float x) {
    if (x >= 0.f) return x * x - 0.5f;
    float s = 1.f / (1.f + expf(x));
    return s - 1.f;
}
__device__ __forceinline__ float dspu_f(float x) {
    if (x >= 0.f) return 2.f * x;
    float s = 1.f / (1.f + expf(x));
    return -s * (1.f - s);
}
__device__ __forceinline__ void spu_relax(float l, float u, float pl, float pu,
                                          float &w_, float &bl_, float &bu_) {
    float k1 = dspu_f(l), k2 = dspu_f(u);
    float klo = fminf(k1, k2), khi = fmaxf(k1, k2);
    float wl = fminf(fmaxf(pl, klo), khi);
    float wu = fminf(fmaxf(pu, klo), khi);
    float p0 = l, p1 = u, p2 = 0.5f * (l + u), p3 = fminf(fmaxf(0.f, l), u);
    float s0 = spu_f(p0), s1 = spu_f(p1), s2 = spu_f(p2), s3 = spu_f(p3);
    bl_ = fminf(fminf(s0 - wl * p0, s1 - wl * p1), fminf(s2 - wl * p2, s3 - wl * p3));
    bu_ = fmaxf(fmaxf(s0 - wu * p0, s1 - wu * p1), fmaxf(s2 - wu * p2, s3 - wu * p3));
    w_ = wl;
}
__device__ __forceinline__ void blk_reduce2(float &a, float &b) {
    const unsigned m = 0xffffffffu;
    #pragma unroll
    for (int o = 16; o > 0; o >>= 1) {
        a += __shfl_down_sync(m, a, o);
        b += __shfl_down_sync(m, b, o);
    }
    __shared__ float sa[16], sb[16];
    int w = threadIdx.x >> 5, l = threadIdx.x & 31;
    int nw = blockDim.x >> 5;
    if (l == 0) { sa[w] = a; sb[w] = b; }
    __syncthreads();
    if (w == 0) {
        a = (l < nw) ? sa[l] : 0.f;
        b = (l < nw) ? sb[l] : 0.f;
        #pragma unroll
        for (int o = 8; o > 0; o >>= 1) {
            a += __shfl_down_sync(m, a, o);
            b += __shfl_down_sync(m, b, o);
        }
    }
}

// ---------------- fused stage-1: concretize W1 row + SPU params (float4) -----
__global__ void concretize_spu_k(const float* __restrict__ W1v,
                                 const float* __restrict__ lin, const float* __restrict__ uin,
                                 const float* __restrict__ b1v,
                                 const float* __restrict__ pl, const float* __restrict__ pu,
                                 float* __restrict__ w, float* __restrict__ bl,
                                 float* __restrict__ bu) {
    int row = blockIdx.x;
    const float* a = W1v + (size_t)row * DIN;
    float al = 0.f, au = 0.f;
    for (int j = threadIdx.x * 4; j < DIN; j += blockDim.x * 4) {
        float4 v = *(const float4*)(a + j);
        float4 L = *(const float4*)(lin + j);
        float4 U = *(const float4*)(uin + j);
        float pA = fmaxf(v.x, 0.f), nA = fminf(v.x, 0.f);
        float pB = fmaxf(v.y, 0.f), nB = fminf(v.y, 0.f);
        float pC = fmaxf(v.z, 0.f), nC = fminf(v.z, 0.f);
        float pD = fmaxf(v.w, 0.f), nD = fminf(v.w, 0.f);
        al += pA * L.x + nA * U.x + pB * L.y + nB * U.y
            + pC * L.z + nC * U.z + pD * L.w + nD * U.w;
        au += pA * U.x + nA * L.x + pB * U.y + nB * L.y
            + pC * U.z + nC * L.z + pD * U.w + nD * L.w;
    }
    blk_reduce2(al, au);
    if (threadIdx.x == 0) {
        float l = al + b1v[row], u = au + b1v[row];
        float w_, bl_, bu_;
        spu_relax(l, u, pl[row], pu[row], w_, bl_, bu_);
        w[row] = w_; bl[row] = bl_; bu[row] = bu_;
    }
}

__global__ void spu_params_k(const float* __restrict__ lf, const float* __restrict__ uf,
                             const float* __restrict__ pl, const float* __restrict__ pu,
                             float* __restrict__ w, float* __restrict__ bl,
                             float* __restrict__ bu, int n) {
    int i = blockIdx.x * blockDim.x + threadIdx.x;
    if (i >= n) return;
    float w_, bl_, bu_;
    spu_relax(lf[i], uf[i], pl[i], pu[i], w_, bl_, bu_);
    w[i] = w_; bl[i] = bl_; bu[i] = bu_;
}

// bias + fp16 convert (hi only), 512 threads: one float4 iteration per row
__global__ __launch_bounds__(512)
void bias2conv_k(const float* __restrict__ W,
                 const float* __restrict__ wprev,
                 const float* __restrict__ blprev, const float* __restrict__ buprev,
                 const float* __restrict__ bthis, const float* __restrict__ bprev,
                 float* __restrict__ cl, float* __restrict__ cu,
                 __half* __restrict__ hi) {
    int row = blockIdx.x;
    const float* wr = W + (size_t)row * H;
    __half* hr = hi + (size_t)row * H;
    float al = 0.f, au = 0.f;
    int j = threadIdx.x * 4;
    {
        float4 v  = *(const float4*)(wr + j);
        float4 wp = *(const float4*)(wprev + j);
        float4 bp = *(const float4*)(bprev + j);
        float4 bL = *(const float4*)(blprev + j);
        float4 bU = *(const float4*)(buprev + j);
        float m0 = v.x * wp.x, m1 = v.y * wp.y, m2 = v.z * wp.z, m3 = v.w * wp.w;
        float sb = m0 * bp.x + m1 * bp.y + m2 * bp.z + m3 * bp.w;
        float pA = fmaxf(v.x, 0.f), nA = fminf(v.x, 0.f);
        float pB = fmaxf(v.y, 0.f), nB = fminf(v.y, 0.f);
        float pC = fmaxf(v.z, 0.f), nC = fminf(v.z, 0.f);
        float pD = fmaxf(v.w, 0.f), nD = fminf(v.w, 0.f);
        al += pA * bL.x + nA * bU.x + pB * bL.y + nB * bU.y
            + pC * bL.z + nC * bU.z + pD * bL.w + nD * bU.w + sb;
        au += pA * bU.x + nA * bL.x + pB * bU.y + nB * bL.y
            + pC * bU.z + nC * bL.z + pD * bU.w + nD * bL.w + sb;
        __half2 h0; h0.x = __float2half_rn(m0); h0.y = __float2half_rn(m1);
        __half2 h1; h1.x = __float2half_rn(m2); h1.y = __float2half_rn(m3);
        *(__half2*)(hr + j)     = h0;
        *(__half2*)(hr + j + 2) = h1;
    }
    blk_reduce2(al, au);
    if (threadIdx.x == 0) { cl[row] = bthis[row] + al; cu[row] = bthis[row] + au; }
}

// B [K x N] fp32 -> Bt_hi/lo [Npad x K] fp16. Tile: 64 k-rows x 32 n-cols.
__global__ void transp_conv_k(const float* __restrict__ B, int N,
                              __half* __restrict__ thi, __half* __restrict__ tlo) {
    __shared__ float t[64][33];
    int k0 = blockIdx.x * 64, n0 = blockIdx.y * 32;
    int x = threadIdx.x, y = threadIdx.y;       // 32 x 8
    #pragma unroll
    for (int yy = y; yy < 64; yy += 8) {
        int n = n0 + x;
        t[yy][x] = (n < N) ? B[(size_t)(k0 + yy) * N + n] : 0.f;
    }
    __syncthreads();
    #pragma unroll
    for (int nn = y; nn < 32; nn += 8) {
        int n = n0 + nn;
        if (n < N) {
            float v0 = t[2 * x][nn], v1 = t[2 * x + 1][nn];
            __half h0 = __float2half_rn(v0), h1 = __float2half_rn(v1);
            __half2 hv; hv.x = h0; hv.y = h1;
            __half2 lv;
            lv.x = __float2half_rn(v0 - __half2float(h0));
            lv.y = __float2half_rn(v1 - __half2float(h1));
            size_t base = (size_t)n * KTOT + k0 + 2 * x;
            *(__half2*)(thi + base) = hv;
            *(__half2*)(tlo + base) = lv;
        }
    }
}

// ---------------- big GEMM: 128x128 tile, 2-product fp16, MODE-0 epilogue -----
__global__ __launch_bounds__(256, 2)
void gemm_mma_k(const __half* __restrict__ Ahi,
                const __half* __restrict__ Bhi, const __half* __restrict__ Blo,
                __half* __restrict__ Ohi,
                const float* __restrict__ scale, const float* __restrict__ bvec,
                const float* __restrict__ blv, const float* __restrict__ buv,
                float* __restrict__ cl, float* __restrict__ cu) {
    extern __shared__ char dsm[];
    uint32_t raw = smem_u32(dsm);
    uint32_t dbase = (raw + 1023) & ~1023u;

    int tid = threadIdx.x, wid = tid >> 5, lane = tid & 31;
    int brow = blockIdx.y * 128, bcol = blockIdx.x * 128;
    int wm = (wid >> 2) * 64, wn = (wid & 3) * 32;

    const __half* gbase[3] = {
        Ahi + (size_t)brow * KTOT,
        Bhi + (size_t)bcol * KTOT, Blo + (size_t)bcol * KTOT };
    const __half* gsrc[6];
    uint32_t sdst[6];
    #pragma unroll
    for (int i = 0; i < 6; i++) {
        int s = i * 256 + tid;                 // 0..1535
        int t = s >> 9, row = (s >> 2) & 127, sg = s & 3;
        gsrc[i] = gbase[t] + (size_t)row * KTOT + sg * 8;
        sdst[i] = (uint32_t)(t * TILEB) + SWZ64((uint32_t)(row * 64 + sg * 16));
    }

    float acc[4][4][4];
    #pragma unroll
    for (int mt = 0; mt < 4; mt++)
        #pragma unroll
        for (int nt = 0; nt < 4; nt++)
            #pragma unroll
            for (int q = 0; q < 4; q++) acc[mt][nt][q] = 0.f;

    int l15 = lane & 15, lhi = lane >> 4;

    #pragma unroll
    for (int st = 0; st < 2; st++) {
        uint32_t sb = dbase + st * STAGEB;
        int k0 = st * KC;
        #pragma unroll
        for (int i = 0; i < 6; i++) CP_ASYNC16(sb + sdst[i], gsrc[i] + k0);
        CP_COMMIT();
    }

    int stage = 0;
    for (int chunk = 0; chunk < NCHUNK; chunk++) {
        if (chunk + 1 < NCHUNK) CP_WAIT(1); else CP_WAIT(0);
        __syncthreads();
        if (chunk + 2 < NCHUNK) {
            int ns = stage + 2; if (ns >= NSTAGE) ns -= NSTAGE;
            uint32_t sb = dbase + ns * STAGEB;
            int k0 = (chunk + 2) * KC;
            #pragma unroll
            for (int i = 0; i < 6; i++) CP_ASYNC16(sb + sdst[i], gsrc[i] + k0);
            CP_COMMIT();
        }
        uint32_t ah_b = dbase + stage * STAGEB;
        uint32_t bh_b = ah_b + TILEB, bl_b = ah_b + 2 * TILEB;
        #pragma unroll
        for (int kb = 0; kb < 2; kb++) {
            uint32_t kbyte = (uint32_t)(kb * 32 + lhi * 16);
            uint32_t ah_f[4][4];
            #pragma unroll
            for (int mt = 0; mt < 4; mt++) {
                uint32_t off = SWZ64((uint32_t)((wm + mt * 16 + l15) * 64) + kbyte);
                LDSM_X4(ah_f[mt][0], ah_f[mt][1], ah_f[mt][2], ah_f[mt][3], ah_b + off);
            }
            #pragma unroll
            for (int p = 0; p < 2; p++) {
                uint32_t off = SWZ64((uint32_t)((wn + p * 16 + l15) * 64) + kbyte);
                uint32_t r0, r1, r2, r3;
                uint32_t bhi0[2], bhi1[2], blo0[2], blo1[2];
                LDSM_X4(r0, r1, r2, r3, bh_b + off);
                bhi0[0] = r0; bhi0[1] = r2; bhi1[0] = r1; bhi1[1] = r3;
                LDSM_X4(r0, r1, r2, r3, bl_b + off);
                blo0[0] = r0; blo0[1] = r2; blo1[0] = r1; blo1[1] = r3;
                #pragma unroll
                for (int mt = 0; mt < 4; mt++) {
                    MMA16816(acc[mt][2 * p], ah_f[mt], bhi0);
                    MMA16816(acc[mt][2 * p], ah_f[mt], blo0);
                    MMA16816(acc[mt][2 * p + 1], ah_f[mt], bhi1);
                    MMA16816(acc[mt][2 * p + 1], ah_f[mt], blo1);
                }
            }
        }
        stage++; if (stage >= NSTAGE) stage -= NSTAGE;
    }

    #pragma unroll
    for (int mt = 0; mt < 4; mt++) {
        #pragma unroll
        for (int q = 0; q < 2; q++) {
            int gr = brow + wm + mt * 16 + (lane >> 2) + q * 8;
            float pl = 0.f, pu = 0.f;
            #pragma unroll
            for (int nt = 0; nt < 4; nt++) {
                int gc = bcol + wn + nt * 8 + (lane & 3) * 2;
                float v0 = acc[mt][nt][q * 2 + 0];
                float v1 = acc[mt][nt][q * 2 + 1];
                float m0 = v0 * scale[gc], m1 = v1 * scale[gc + 1];
                __half2 hv; hv.x = __float2half_rn(m0); hv.y = __float2half_rn(m1);
                *(__half2*)(Ohi + (size_t)gr * H + gc) = hv;
                float p0 = fmaxf(v0, 0.f), n0 = fminf(v0, 0.f);
                float p1 = fmaxf(v1, 0.f), n1 = fminf(v1, 0.f);
                float sb = m0 * bvec[gc] + m1 * bvec[gc + 1];
                pl += p0 * blv[gc] + n0 * buv[gc] + p1 * blv[gc + 1] + n1 * buv[gc + 1] + sb;
                pu += p0 * buv[gc] + n0 * blv[gc] + p1 * buv[gc + 1] + n1 * blv[gc + 1] + sb;
            }
            pl += __shfl_xor_sync(0xffffffffu, pl, 1);
            pl += __shfl_xor_sync(0xffffffffu, pl, 2);
            pu += __shfl_xor_sync(0xffffffffu, pu, 1);
            pu += __shfl_xor_sync(0xffffffffu, pu, 2);
            if ((lane & 3) == 0) {
                atomicAdd(&cl[gr], pl);
                atomicAdd(&cu[gr], pu);
            }
        }
    }
}

// ---------------- mid GEMM: 64x128 tile, 2-product fp16, concretize epilogue --
__global__ __launch_bounds__(256, 2)
void gemm_mid_mma_k(const __half* __restrict__ Ahi,
                    const __half* __restrict__ Bhi, const __half* __restrict__ Blo,
                    float* __restrict__ cl, float* __restrict__ cu,
                    const float* __restrict__ lin, const float* __restrict__ uin) {
    extern __shared__ char dsm[];
    uint32_t raw = smem_u32(dsm);
    uint32_t dbase = (raw + 1023) & ~1023u;

    int tid = threadIdx.x, wid = tid >> 5, lane = tid & 31;
    int brow = blockIdx.y * 64, bcol = blockIdx.x * 128;
    int wm = (wid >> 2) * 32, wn = (wid & 3) * 32;

    // staging: 320 rows (64 A + 128 Bhi + 128 Blo) * 4 segs = 1280, 5 per thread
    const __half* gsrc[5];
    uint32_t sdst[5];
    #pragma unroll
    for (int i = 0; i < 5; i++) {
        int s = i * 256 + tid;          // 0..1279
        int rowg = s >> 2, sg = s & 3;
        if (rowg < 64) {
            gsrc[i] = Ahi + (size_t)(brow + rowg) * KTOT + sg * 8;
            sdst[i] = SWZ64((uint32_t)(rowg * 64 + sg * 16));
        } else {
            int rr = rowg - 64;
            int t = rr >> 7, r = rr & 127;
            gsrc[i] = (t ? Blo : Bhi) + (size_t)(bcol + r) * KTOT + sg * 8;
            sdst[i] = (uint32_t)(MTILEA + t * MTILEB) + SWZ64((uint32_t)(r * 64 + sg * 16));
        }
    }

    float acc[2][4][4];
    #pragma unroll
    for (int mt = 0; mt < 2; mt++)
        #pragma unroll
        for (int nt = 0; nt < 4; nt++)
            #pragma unroll
            for (int q = 0; q < 4; q++) acc[mt][nt][q] = 0.f;

    int l15 = lane & 15, lhi = lane >> 4;

    #pragma unroll
    for (int st = 0; st < 2; st++) {
        uint32_t sb = dbase + st * MSTAGE;
        int k0 = st * KC;
        #pragma unroll
        for (int i = 0; i < 5; i++) CP_ASYNC16(sb + sdst[i], gsrc[i] + k0);
        CP_COMMIT();
    }

    int stage = 0;
    for (int chunk = 0; chunk < NCHUNK; chunk++) {
        if (chunk + 1 < NCHUNK) CP_WAIT(1); else CP_WAIT(0);
        __syncthreads();
        if (chunk + 2 < NCHUNK) {
            int ns = stage + 2; if (ns >= NSTAGE) ns -= NSTAGE;
            uint32_t sb = dbase + ns * MSTAGE;
            int k0 = (chunk + 2) * KC;
            #pragma unroll
            for (int i = 0; i < 5; i++) CP_ASYNC16(sb + sdst[i], gsrc[i] + k0);
            CP_COMMIT();
        }
        uint32_t ah_b = dbase + stage * MSTAGE;
        uint32_t bh_b = ah_b + MTILEA, bl_b = bh_b + MTILEB;
        #pragma unroll
        for (int kb = 0; kb < 2; kb++) {
            uint32_t kbyte = (uint32_t)(kb * 32 + lhi * 16);
            uint32_t ah_f[2][4];
            #pragma unroll
            for (int mt = 0; mt < 2; mt++) {
                uint32_t off = SWZ64((uint32_t)((wm + mt * 16 + l15) * 64) + kbyte);
                LDSM_X4(ah_f[mt][0], ah_f[mt][1], ah_f[mt][2], ah_f[mt][3], ah_b + off);
            }
            #pragma unroll
            for (int p = 0; p < 2; p++) {
                uint32_t off = SWZ64((uint32_t)((wn + p * 16 + l15) * 64) + kbyte);
                uint32_t r0, r1, r2, r3;
                uint32_t bhi0[2], bhi1[2], blo0[2], blo1[2];
                LDSM_X4(r0, r1, r2, r3, bh_b + off);
                bhi0[0] = r0; bhi0[1] = r2; bhi1[0] = r1; bhi1[1] = r3;
                LDSM_X4(r0, r1, r2, r3, bl_b + off);
                blo0[0] = r0; blo0[1] = r2; blo1[0] = r1; blo1[1] = r3;
                #pragma unroll
                for (int mt = 0; mt < 2; mt++) {
                    MMA16816(acc[mt][2 * p], ah_f[mt], bhi0);
                    MMA16816(acc[mt][2 * p], ah_f[mt], blo0);
                    MMA16816(acc[mt][2 * p + 1], ah_f[mt], bhi1);
                    MMA16816(acc[mt][2 * p + 1], ah_f[mt], blo1);
                }
            }
        }
        stage++; if (stage >= NSTAGE) stage -= NSTAGE;
    }

    #pragma unroll
    for (int mt = 0; mt < 2; mt++) {
        #pragma unroll
        for (int q = 0; q < 2; q++) {
            int gr = brow + wm + mt * 16 + (lane >> 2) + q * 8;
            float pl = 0.f, pu = 0.f;
            #pragma unroll
            for (int nt = 0; nt < 4; nt++) {
                int gc = bcol + wn + nt * 8 + (lane & 3) * 2;
                if (gc < DIN) {
                    float v0 = acc[mt][nt][q * 2 + 0];
                    float v1 = acc[mt][nt][q * 2 + 1];
                    float l0 = lin[gc], u0 = uin[gc];
                    float l1 = lin[gc + 1], u1 = uin[gc + 1];
                    float p0 = fmaxf(v0, 0.f), n0 = fminf(v0, 0.f);
                    float p1 = fmaxf(v1, 0.f), n1 = fminf(v1, 0.f);
                    pl += p0 * l0 + n0 * u0 + p1 * l1 + n1 * u1;
                    pu += p0 * u0 + n0 * l0 + p1 * u1 + n1 * l1;
                }
            }
            pl += __shfl_xor_sync(0xffffffffu, pl, 1);
            pl += __shfl_xor_sync(0xffffffffu, pl, 2);
            pu += __shfl_xor_sync(0xffffffffu, pu, 1);
            pu += __shfl_xor_sync(0xffffffffu, pu, 2);
            if ((lane & 3) == 0) {
                atomicAdd(&cl[gr], pl);
                atomicAdd(&cu[gr], pu);
            }
        }
    }
}

// ---------------- output stage (9 rows) ---------------------------------------
__global__ void build_m4_k(const float* __restrict__ W4, const float* __restrict__ b4,
                           const int* __restrict__ tl, float* __restrict__ M,
                           float* __restrict__ bias) {
    int t = *tl;
    int idx = blockIdx.x * blockDim.x + threadIdx.x;
    if (idx < OUTR * H) {
        int r = idx / H, j = idx % H;
        int c = (r < t) ? r : r + 1;
        M[idx] = W4[(size_t)c * H + j] - W4[(size_t)t * H + j];
    }
    if (idx < OUTR) {
        int c = (idx < t) ? idx : idx + 1;
        bias[idx] = b4[c] - b4[t];
    }
}

__global__ void small_bias_k(const float* __restrict__ A,
                             const float* __restrict__ w, const float* __restrict__ bl,
                             const float* __restrict__ bu, const float* __restrict__ bnext,
                             float* __restrict__ bias) {
    int r = blockIdx.x;
    const float* a = A + (size_t)r * H;
    float au = 0.f, dummy = 0.f;
    for (int j = threadIdx.x; j < H; j += blockDim.x) {
        float v = a[j];
        float p = fmaxf(v, 0.f), n = fminf(v, 0.f);
        au += p * bu[j] + n * bl[j] + v * w[j] * bnext[j];
    }
    blk_reduce2(au, dummy);
    if (threadIdx.x == 0) bias[r] += au;
}

__global__ void zero_k(float* __restrict__ p, int n) {
    int i = blockIdx.x * blockDim.x + threadIdx.x;
    if (i < n) p[i] = 0.f;
}

#define SG_CHUNK 256
__global__ void small_gemm_k(int K, int N, const float* __restrict__ A,
                             const float* __restrict__ ascale,
                             const float* __restrict__ B, float* __restrict__ C) {
    __shared__ float sA[OUTR * SG_CHUNK];
    int k0 = blockIdx.y * SG_CHUNK;
    int n = blockIdx.x * blockDim.x + threadIdx.x;
    for (int idx = threadIdx.x; idx < OUTR * SG_CHUNK; idx += blockDim.x) {
        int r = idx / SG_CHUNK, kk = idx % SG_CHUNK;
        sA[idx] = A[(size_t)r * K + k0 + kk] * ascale[k0 + kk];
    }
    __syncthreads();
    if (n >= N) return;
    float acc[OUTR];
    #pragma unroll
    for (int r = 0; r < OUTR; r++) acc[r] = 0.f;
    #pragma unroll 4
    for (int kk = 0; kk < SG_CHUNK; kk++) {
        float bv = B[(size_t)(k0 + kk) * N + n];
        #pragma unroll
        for (int r = 0; r < OUTR; r++) acc[r] += sA[r * SG_CHUNK + kk] * bv;
    }
    #pragma unroll
    for (int r = 0; r < OUTR; r++) atomicAdd(&C[(size_t)r * N + n], acc[r]);
}

__global__ void final_k(const float* __restrict__ M, const float* __restrict__ lin,
                        const float* __restrict__ uin, const float* __restrict__ bias,
                        float* __restrict__ out) {
    int r = blockIdx.x;
    const float* a = M + (size_t)r * DIN;
    float au = 0.f, dummy = 0.f;
    for (int j = threadIdx.x; j < DIN; j += blockDim.x) {
        float v = a[j];
        au += fmaxf(v, 0.f) * uin[j] + fminf(v, 0.f) * lin[j];
    }
    blk_reduce2(au, dummy);
    if (threadIdx.x == 0) out[r] = au + bias[r];
}

// ---------------- launch ------------------------------------------------------
extern "C" void kernel_launch(void* const* d_in, const int* in_sizes, int n_in,
                              void* d_out, int out_size) {
    const float* W1 = (const float*)d_in[0];
    const float* b1 = (const float*)d_in[1];
    const float* W2 = (const float*)d_in[2];
    const float* b2 = (const float*)d_in[3];
    const float* W3 = (const float*)d_in[4];
    const float* b3 = (const float*)d_in[5];
    const float* W4 = (const float*)d_in[6];
    const float* b4 = (const float*)d_in[7];
    const float* l_in = (const float*)d_in[8];
    const float* u_in = (const float*)d_in[9];
    const float* p_l1 = (const float*)d_in[10];
    const float* p_u1 = (const float*)d_in[11];
    const float* p_l2 = (const float*)d_in[12];
    const float* p_u2 = (const float*)d_in[13];
    const float* p_l3 = (const float*)d_in[14];
    const float* p_u3 = (const float*)d_in[15];
    const int* tl = (const int*)d_in[16];
    float* out = (float*)d_out;

    cudaFuncSetAttribute(gemm_mma_k, cudaFuncAttributeMaxDynamicSharedMemorySize, DSMEM);
    cudaFuncSetAttribute(gemm_mid_mma_k, cudaFuncAttributeMaxDynamicSharedMemorySize, MDSMEM);

    float *T, *w1, *bl1, *bu1, *w2, *bl2, *bu2, *w3, *bl3, *bu3, *cl, *cu;
    float *m4a, *m4b, *bias4;
    __half *Ahi, *W1th, *W1tl, *W2th, *W2tl;
    cudaGetSymbolAddress((void**)&T, g_T);
    cudaGetSymbolAddress((void**)&Ahi, g_Ahi);
    cudaGetSymbolAddress((void**)&W1th, g_W1t_hi); cudaGetSymbolAddress((void**)&W1tl, g_W1t_lo);
    cudaGetSymbolAddress((void**)&W2th, g_W2t_hi); cudaGetSymbolAddress((void**)&W2tl, g_W2t_lo);
    cudaGetSymbolAddress((void**)&w1, g_w1);   cudaGetSymbolAddress((void**)&bl1, g_bl1);
    cudaGetSymbolAddress((void**)&bu1, g_bu1);
    cudaGetSymbolAddress((void**)&w2, g_w2);   cudaGetSymbolAddress((void**)&bl2, g_bl2);
    cudaGetSymbolAddress((void**)&bu2, g_bu2);
    cudaGetSymbolAddress((void**)&w3, g_w3);   cudaGetSymbolAddress((void**)&bl3, g_bl3);
    cudaGetSymbolAddress((void**)&bu3, g_bu3);
    cudaGetSymbolAddress((void**)&cl, g_cl);   cudaGetSymbolAddress((void**)&cu, g_cu);
    cudaGetSymbolAddress((void**)&m4a, g_m4a); cudaGetSymbolAddress((void**)&m4b, g_m4b);
    cudaGetSymbolAddress((void**)&bias4, g_bias4);

    __half* Thi = (__half*)T;

    // one-time (per launch) B transpose+split (64k x 32n tiles)
    transp_conv_k<<<dim3(KTOT / 64, (DIN + 31) / 32), dim3(32, 8)>>>(W1, DIN, W1th, W1tl);
    transp_conv_k<<<dim3(KTOT / 64, H / 32), dim3(32, 8)>>>(W2, H, W2th, W2tl);

    dim3 gmid(NPAD1 / 128, H / 64);          // 7 x 32 = 224 CTAs
    dim3 gbig(H / 128, H / 128);             // 16 x 16 = 256 CTAs

    // ---- stage 1 (fused concretize + spu) ----
    concretize_spu_k<<<H, 256>>>(W1, l_in, u_in, b1, p_l1, p_u1, w1, bl1, bu1);

    // ---- stage 2 ----
    bias2conv_k<<<H, 512>>>(W2, w1, bl1, bu1, b2, b1, cl, cu, Ahi);
    gemm_mid_mma_k<<<gmid, 256, MDSMEM>>>(Ahi, W1th, W1tl, cl, cu, l_in, u_in);
    spu_params_k<<<(H + 63) / 64, 64>>>(cl, cu, p_l2, p_u2, w2, bl2, bu2, H);

    // ---- stage 3 ----
    bias2conv_k<<<H, 512>>>(W3, w2, bl2, bu2, b3, b2, cl, cu, Ahi);
    gemm_mma_k<<<gbig, 256, DSMEM>>>(Ahi, W2th, W2tl, Thi,
                                     w1, b1, bl1, bu1, cl, cu);
    gemm_mid_mma_k<<<gmid, 256, MDSMEM>>>(Thi, W1th, W1tl, cl, cu, l_in, u_in);
    spu_params_k<<<(H + 63) / 64, 64>>>(cl, cu, p_l3, p_u3, w3, bl3, bu3, H);

    // ---- stage 4: output chain (9 rows) ----
    build_m4_k<<<(OUTR * H + 255) / 256, 256>>>(W4, b4, tl, m4a, bias4);
    small_bias_k<<<OUTR, 256>>>(m4a, w3, bl3, bu3, b3, bias4);
    zero_k<<<(OUTR * H + 255) / 256, 256>>>(m4b, OUTR * H);
    small_gemm_k<<<dim3((H + 127) / 128, H / SG_CHUNK), 128>>>(H, H, m4a, w3, W3, m4b);
    small_bias_k<<<OUTR, 256>>>(m4b, w2, bl2, bu2, b2, bias4);
    zero_k<<<(OUTR * H + 255) / 256, 256>>>(m4a, OUTR * H);
    small_gemm_k<<<dim3((H + 127) / 128, H / SG_CHUNK), 128>>>(H, H, m4b, w2, W2, m4a);
    small_bias_k<<<OUTR, 256>>>(m4a, w1, bl1, bu1, b1, bias4);
    zero_k<<<(OUTR * DIN + 255) / 256, 256>>>(m4b, OUTR * DIN);
    small_gemm_k<<<dim3((DIN + 127) / 128, H / SG_CHUNK), 128>>>(H, DIN, m4a, w1, W1, m4b);
    final_k<<<OUTR, 256>>>(m4b, l_in, u_in, bias4, out);
}

// round 13
// speedup vs baseline: 2.6043x; 1.4322x over previous
#include <cuda_runtime.h>
#include <cuda_fp16.h>
#include <math.h>
#include <stdint.h>

#define H     2048
#define DIN   784
#define OUTR  9
#define KTOT  2048
#define KC    32
#define NCHUNK (KTOT / KC)          // 64
#define TILEB  8192                 // 128 rows * 64B
#define STAGEB (2 * TILEB)          // 16KB: Ahi, Bhi
#define NSTAGE 3
#define DSMEM  (NSTAGE * STAGEB + 1024)
// mid-GEMM (64x128 tile) sizes
#define MTILEA 4096                 // 64 rows * 64B
#define MTILEB 8192                 // 128 rows * 64B
#define MSTAGE (MTILEA + MTILEB)    // 12288
#define MDSMEM (NSTAGE * MSTAGE + 1024)
#define NPAD1  896

// ---------------- scratch (device globals) ----------------------------------
__device__ float g_T[H * H];        // reused as half[H*H] for stage-3 Thi
__device__ __half g_Ahi[H * H];
__device__ __half g_W1t_hi[NPAD1 * KTOT];   // pad rows stay 0
__device__ __half g_W2t_hi[H * KTOT];
__device__ float g_w1[H], g_bl1[H], g_bu1[H];
__device__ float g_w2[H], g_bl2[H], g_bu2[H];
__device__ float g_w3[H], g_bl3[H], g_bu3[H];
__device__ float g_cl[H], g_cu[H];
__device__ float g_m4a[OUTR * H], g_m4b[OUTR * H];
__device__ float g_bias4[OUTR];

// ---------------- PTX helpers ------------------------------------------------
__device__ __forceinline__ uint32_t smem_u32(const void* p) {
    uint32_t a;
    asm("{ .reg .u64 t; cvta.to.shared.u64 t, %1; cvt.u32.u64 %0, t; }" : "=r"(a) : "l"(p));
    return a;
}
#define SWZ64(o)   ((o) ^ (((o) >> 3) & 0x30))
#define CP_ASYNC16(dst, gsrc) \
    asm volatile("cp.async.cg.shared.global [%0], [%1], 16;" :: "r"(dst), "l"(gsrc))
#define CP_COMMIT() asm volatile("cp.async.commit_group;" ::: "memory")
#define CP_WAIT(n)  asm volatile("cp.async.wait_group %0;" :: "n"(n) : "memory")
#define LDSM_X4(r0, r1, r2, r3, addr) \
    asm volatile("ldmatrix.sync.aligned.m8n8.x4.shared.b16 {%0,%1,%2,%3}, [%4];" \
        : "=r"(r0), "=r"(r1), "=r"(r2), "=r"(r3) : "r"(addr))
#define MMA16816(d, a, b) \
    asm volatile("mma.sync.aligned.m16n8k16.row.col.f32.f16.f16.f32 " \
        "{%0,%1,%2,%3}, {%4,%5,%6,%7}, {%8,%9}, {%0,%1,%2,%3};" \
        : "+f"((d)[0]), "+f"((d)[1]), "+f"((d)[2]), "+f"((d)[3]) \
        : "r"((a)[0]), "r"((a)[1]), "r"((a)[2]), "r"((a)[3]), "r"((b)[0]), "r"((b)[1]))

// ---------------- misc helpers ----------------------------------------------
__device__ __forceinline__ float spu_f(float x) {
    if (x >= 0.f) return x * x - 0.5f;
    float s = 1.f / (1.f + expf(x));
    return s - 1.f;
}
__device__ __forceinline__ float dspu_f(float x) {
    if (x >= 0.f) return 2.f * x;
    float s = 1.f / (1.f + expf(x));
    return -s * (1.f - s);
}
__device__ __forceinline__ void spu_relax(float l, float u, float pl, float pu,
                                          float &w_, float &bl_, float &bu_) {
    float k1 = dspu_f(l), k2 = dspu_f(u);
    float klo = fminf(k1, k2), khi = fmaxf(k1, k2);
    float wl = fminf(fmaxf(pl, klo), khi);
    float wu = fminf(fmaxf(pu, klo), khi);
    float p0 = l, p1 = u, p2 = 0.5f * (l + u), p3 = fminf(fmaxf(0.f, l), u);
    float s0 = spu_f(p0), s1 = spu_f(p1), s2 = spu_f(p2), s3 = spu_f(p3);
    bl_ = fminf(fminf(s0 - wl * p0, s1 - wl * p1), fminf(s2 - wl * p2, s3 - wl * p3));
    bu_ = fmaxf(fmaxf(s0 - wu * p0, s1 - wu * p1), fmaxf(s2 - wu * p2, s3 - wu * p3));
    w_ = wl;
}
__device__ __forceinline__ void blk_reduce2(float &a, float &b) {
    const unsigned m = 0xffffffffu;
    #pragma unroll
    for (int o = 16; o > 0; o >>= 1) {
        a += __shfl_down_sync(m, a, o);
        b += __shfl_down_sync(m, b, o);
    }
    __shared__ float sa[16], sb[16];
    int w = threadIdx.x >> 5, l = threadIdx.x & 31;
    int nw = blockDim.x >> 5;
    if (l == 0) { sa[w] = a; sb[w] = b; }
    __syncthreads();
    if (w == 0) {
        a = (l < nw) ? sa[l] : 0.f;
        b = (l < nw) ? sb[l] : 0.f;
        #pragma unroll
        for (int o = 8; o > 0; o >>= 1) {
            a += __shfl_down_sync(m, a, o);
            b += __shfl_down_sync(m, b, o);
        }
    }
}

// ---------------- fused stage-1: concretize W1 row + SPU params (float4) -----
__global__ void concretize_spu_k(const float* __restrict__ W1v,
                                 const float* __restrict__ lin, const float* __restrict__ uin,
                                 const float* __restrict__ b1v,
                                 const float* __restrict__ pl, const float* __restrict__ pu,
                                 float* __restrict__ w, float* __restrict__ bl,
                                 float* __restrict__ bu) {
    int row = blockIdx.x;
    const float* a = W1v + (size_t)row * DIN;
    float al = 0.f, au = 0.f;
    for (int j = threadIdx.x * 4; j < DIN; j += blockDim.x * 4) {
        float4 v = *(const float4*)(a + j);
        float4 L = *(const float4*)(lin + j);
        float4 U = *(const float4*)(uin + j);
        float pA = fmaxf(v.x, 0.f), nA = fminf(v.x, 0.f);
        float pB = fmaxf(v.y, 0.f), nB = fminf(v.y, 0.f);
        float pC = fmaxf(v.z, 0.f), nC = fminf(v.z, 0.f);
        float pD = fmaxf(v.w, 0.f), nD = fminf(v.w, 0.f);
        al += pA * L.x + nA * U.x + pB * L.y + nB * U.y
            + pC * L.z + nC * U.z + pD * L.w + nD * U.w;
        au += pA * U.x + nA * L.x + pB * U.y + nB * L.y
            + pC * U.z + nC * L.z + pD * U.w + nD * L.w;
    }
    blk_reduce2(al, au);
    if (threadIdx.x == 0) {
        float l = al + b1v[row], u = au + b1v[row];
        float w_, bl_, bu_;
        spu_relax(l, u, pl[row], pu[row], w_, bl_, bu_);
        w[row] = w_; bl[row] = bl_; bu[row] = bu_;
    }
}

__global__ void spu_params_k(const float* __restrict__ lf, const float* __restrict__ uf,
                             const float* __restrict__ pl, const float* __restrict__ pu,
                             float* __restrict__ w, float* __restrict__ bl,
                             float* __restrict__ bu, int n) {
    int i = blockIdx.x * blockDim.x + threadIdx.x;
    if (i >= n) return;
    float w_, bl_, bu_;
    spu_relax(lf[i], uf[i], pl[i], pu[i], w_, bl_, bu_);
    w[i] = w_; bl[i] = bl_; bu[i] = bu_;
}

// bias + fp16 convert (hi only), 512 threads: one float4 iteration per row
__global__ __launch_bounds__(512)
void bias2conv_k(const float* __restrict__ W,
                 const float* __restrict__ wprev,
                 const float* __restrict__ blprev, const float* __restrict__ buprev,
                 const float* __restrict__ bthis, const float* __restrict__ bprev,
                 float* __restrict__ cl, float* __restrict__ cu,
                 __half* __restrict__ hi) {
    int row = blockIdx.x;
    const float* wr = W + (size_t)row * H;
    __half* hr = hi + (size_t)row * H;
    float al = 0.f, au = 0.f;
    int j = threadIdx.x * 4;
    {
        float4 v  = *(const float4*)(wr + j);
        float4 wp = *(const float4*)(wprev + j);
        float4 bp = *(const float4*)(bprev + j);
        float4 bL = *(const float4*)(blprev + j);
        float4 bU = *(const float4*)(buprev + j);
        float m0 = v.x * wp.x, m1 = v.y * wp.y, m2 = v.z * wp.z, m3 = v.w * wp.w;
        float sb = m0 * bp.x + m1 * bp.y + m2 * bp.z + m3 * bp.w;
        float pA = fmaxf(v.x, 0.f), nA = fminf(v.x, 0.f);
        float pB = fmaxf(v.y, 0.f), nB = fminf(v.y, 0.f);
        float pC = fmaxf(v.z, 0.f), nC = fminf(v.z, 0.f);
        float pD = fmaxf(v.w, 0.f), nD = fminf(v.w, 0.f);
        al += pA * bL.x + nA * bU.x + pB * bL.y + nB * bU.y
            + pC * bL.z + nC * bU.z + pD * bL.w + nD * bU.w + sb;
        au += pA * bU.x + nA * bL.x + pB * bU.y + nB * bL.y
            + pC * bU.z + nC * bL.z + pD * bU.w + nD * bL.w + sb;
        __half2 h0; h0.x = __float2half_rn(m0); h0.y = __float2half_rn(m1);
        __half2 h1; h1.x = __float2half_rn(m2); h1.y = __float2half_rn(m3);
        *(__half2*)(hr + j)     = h0;
        *(__half2*)(hr + j + 2) = h1;
    }
    blk_reduce2(al, au);
    if (threadIdx.x == 0) { cl[row] = bthis[row] + al; cu[row] = bthis[row] + au; }
}

// B [K x N] fp32 -> Bt_hi [Npad x K] fp16. Tile: 64 k-rows x 32 n-cols.
__global__ void transp_conv_k(const float* __restrict__ B, int N,
                              __half* __restrict__ thi) {
    __shared__ float t[64][33];
    int k0 = blockIdx.x * 64, n0 = blockIdx.y * 32;
    int x = threadIdx.x, y = threadIdx.y;       // 32 x 8
    #pragma unroll
    for (int yy = y; yy < 64; yy += 8) {
        int n = n0 + x;
        t[yy][x] = (n < N) ? B[(size_t)(k0 + yy) * N + n] : 0.f;
    }
    __syncthreads();
    #pragma unroll
    for (int nn = y; nn < 32; nn += 8) {
        int n = n0 + nn;
        if (n < N) {
            __half2 hv;
            hv.x = __float2half_rn(t[2 * x][nn]);
            hv.y = __float2half_rn(t[2 * x + 1][nn]);
            *(__half2*)(thi + (size_t)n * KTOT + k0 + 2 * x) = hv;
        }
    }
}

// ---------------- big GEMM: 128x128 tile, 1-product fp16, MODE-0 epilogue -----
__global__ __launch_bounds__(256, 2)
void gemm_mma_k(const __half* __restrict__ Ahi, const __half* __restrict__ Bhi,
                __half* __restrict__ Ohi,
                const float* __restrict__ scale, const float* __restrict__ bvec,
                const float* __restrict__ blv, const float* __restrict__ buv,
                float* __restrict__ cl, float* __restrict__ cu) {
    extern __shared__ char dsm[];
    uint32_t raw = smem_u32(dsm);
    uint32_t dbase = (raw + 1023) & ~1023u;

    int tid = threadIdx.x, wid = tid >> 5, lane = tid & 31;
    int brow = blockIdx.y * 128, bcol = blockIdx.x * 128;
    int wm = (wid >> 2) * 64, wn = (wid & 3) * 32;

    const __half* gbase[2] = { Ahi + (size_t)brow * KTOT, Bhi + (size_t)bcol * KTOT };
    const __half* gsrc[4];
    uint32_t sdst[4];
    #pragma unroll
    for (int i = 0; i < 4; i++) {
        int s = i * 256 + tid;                 // 0..1023
        int t = s >> 9, row = (s >> 2) & 127, sg = s & 3;
        gsrc[i] = gbase[t] + (size_t)row * KTOT + sg * 8;
        sdst[i] = (uint32_t)(t * TILEB) + SWZ64((uint32_t)(row * 64 + sg * 16));
    }

    float acc[4][4][4];
    #pragma unroll
    for (int mt = 0; mt < 4; mt++)
        #pragma unroll
        for (int nt = 0; nt < 4; nt++)
            #pragma unroll
            for (int q = 0; q < 4; q++) acc[mt][nt][q] = 0.f;

    int l15 = lane & 15, lhi = lane >> 4;

    #pragma unroll
    for (int st = 0; st < 2; st++) {
        uint32_t sb = dbase + st * STAGEB;
        int k0 = st * KC;
        #pragma unroll
        for (int i = 0; i < 4; i++) CP_ASYNC16(sb + sdst[i], gsrc[i] + k0);
        CP_COMMIT();
    }

    int stage = 0;
    for (int chunk = 0; chunk < NCHUNK; chunk++) {
        if (chunk + 1 < NCHUNK) CP_WAIT(1); else CP_WAIT(0);
        __syncthreads();
        if (chunk + 2 < NCHUNK) {
            int ns = stage + 2; if (ns >= NSTAGE) ns -= NSTAGE;
            uint32_t sb = dbase + ns * STAGEB;
            int k0 = (chunk + 2) * KC;
            #pragma unroll
            for (int i = 0; i < 4; i++) CP_ASYNC16(sb + sdst[i], gsrc[i] + k0);
            CP_COMMIT();
        }
        uint32_t ah_b = dbase + stage * STAGEB;
        uint32_t bh_b = ah_b + TILEB;
        #pragma unroll
        for (int kb = 0; kb < 2; kb++) {
            uint32_t kbyte = (uint32_t)(kb * 32 + lhi * 16);
            uint32_t ah_f[4][4];
            #pragma unroll
            for (int mt = 0; mt < 4; mt++) {
                uint32_t off = SWZ64((uint32_t)((wm + mt * 16 + l15) * 64) + kbyte);
                LDSM_X4(ah_f[mt][0], ah_f[mt][1], ah_f[mt][2], ah_f[mt][3], ah_b + off);
            }
            #pragma unroll
            for (int p = 0; p < 2; p++) {
                uint32_t off = SWZ64((uint32_t)((wn + p * 16 + l15) * 64) + kbyte);
                uint32_t r0, r1, r2, r3;
                uint32_t bhi0[2], bhi1[2];
                LDSM_X4(r0, r1, r2, r3, bh_b + off);
                bhi0[0] = r0; bhi0[1] = r2; bhi1[0] = r1; bhi1[1] = r3;
                #pragma unroll
                for (int mt = 0; mt < 4; mt++) {
                    MMA16816(acc[mt][2 * p], ah_f[mt], bhi0);
                    MMA16816(acc[mt][2 * p + 1], ah_f[mt], bhi1);
                }
            }
        }
        stage++; if (stage >= NSTAGE) stage -= NSTAGE;
    }

    #pragma unroll
    for (int mt = 0; mt < 4; mt++) {
        #pragma unroll
        for (int q = 0; q < 2; q++) {
            int gr = brow + wm + mt * 16 + (lane >> 2) + q * 8;
            float pl = 0.f, pu = 0.f;
            #pragma unroll
            for (int nt = 0; nt < 4; nt++) {
                int gc = bcol + wn + nt * 8 + (lane & 3) * 2;
                float v0 = acc[mt][nt][q * 2 + 0];
                float v1 = acc[mt][nt][q * 2 + 1];
                float m0 = v0 * scale[gc], m1 = v1 * scale[gc + 1];
                __half2 hv; hv.x = __float2half_rn(m0); hv.y = __float2half_rn(m1);
                *(__half2*)(Ohi + (size_t)gr * H + gc) = hv;
                float p0 = fmaxf(v0, 0.f), n0 = fminf(v0, 0.f);
                float p1 = fmaxf(v1, 0.f), n1 = fminf(v1, 0.f);
                float sb = m0 * bvec[gc] + m1 * bvec[gc + 1];
                pl += p0 * blv[gc] + n0 * buv[gc] + p1 * blv[gc + 1] + n1 * buv[gc + 1] + sb;
                pu += p0 * buv[gc] + n0 * blv[gc] + p1 * buv[gc + 1] + n1 * blv[gc + 1] + sb;
            }
            pl += __shfl_xor_sync(0xffffffffu, pl, 1);
            pl += __shfl_xor_sync(0xffffffffu, pl, 2);
            pu += __shfl_xor_sync(0xffffffffu, pu, 1);
            pu += __shfl_xor_sync(0xffffffffu, pu, 2);
            if ((lane & 3) == 0) {
                atomicAdd(&cl[gr], pl);
                atomicAdd(&cu[gr], pu);
            }
        }
    }
}

// ---------------- mid GEMM: 64x128 tile, 1-product fp16, concretize epilogue --
__global__ __launch_bounds__(256, 2)
void gemm_mid_mma_k(const __half* __restrict__ Ahi, const __half* __restrict__ Bhi,
                    float* __restrict__ cl, float* __restrict__ cu,
                    const float* __restrict__ lin, const float* __restrict__ uin) {
    extern __shared__ char dsm[];
    uint32_t raw = smem_u32(dsm);
    uint32_t dbase = (raw + 1023) & ~1023u;

    int tid = threadIdx.x, wid = tid >> 5, lane = tid & 31;
    int brow = blockIdx.y * 64, bcol = blockIdx.x * 128;
    int wm = (wid >> 2) * 32, wn = (wid & 3) * 32;

    // staging: 192 rows (64 A + 128 B) * 4 segs = 768, 3 per thread
    const __half* gsrc[3];
    uint32_t sdst[3];
    #pragma unroll
    for (int i = 0; i < 3; i++) {
        int s = i * 256 + tid;          // 0..767
        int rowg = s >> 2, sg = s & 3;
        if (rowg < 64) {
            gsrc[i] = Ahi + (size_t)(brow + rowg) * KTOT + sg * 8;
            sdst[i] = SWZ64((uint32_t)(rowg * 64 + sg * 16));
        } else {
            int r = rowg - 64;
            gsrc[i] = Bhi + (size_t)(bcol + r) * KTOT + sg * 8;
            sdst[i] = (uint32_t)MTILEA + SWZ64((uint32_t)(r * 64 + sg * 16));
        }
    }

    float acc[2][4][4];
    #pragma unroll
    for (int mt = 0; mt < 2; mt++)
        #pragma unroll
        for (int nt = 0; nt < 4; nt++)
            #pragma unroll
            for (int q = 0; q < 4; q++) acc[mt][nt][q] = 0.f;

    int l15 = lane & 15, lhi = lane >> 4;

    #pragma unroll
    for (int st = 0; st < 2; st++) {
        uint32_t sb = dbase + st * MSTAGE;
        int k0 = st * KC;
        #pragma unroll
        for (int i = 0; i < 3; i++) CP_ASYNC16(sb + sdst[i], gsrc[i] + k0);
        CP_COMMIT();
    }

    int stage = 0;
    for (int chunk = 0; chunk < NCHUNK; chunk++) {
        if (chunk + 1 < NCHUNK) CP_WAIT(1); else CP_WAIT(0);
        __syncthreads();
        if (chunk + 2 < NCHUNK) {
            int ns = stage + 2; if (ns >= NSTAGE) ns -= NSTAGE;
            uint32_t sb = dbase + ns * MSTAGE;
            int k0 = (chunk + 2) * KC;
            #pragma unroll
            for (int i = 0; i < 3; i++) CP_ASYNC16(sb + sdst[i], gsrc[i] + k0);
            CP_COMMIT();
        }
        uint32_t ah_b = dbase + stage * MSTAGE;
        uint32_t bh_b = ah_b + MTILEA;
        #pragma unroll
        for (int kb = 0; kb < 2; kb++) {
            uint32_t kbyte = (uint32_t)(kb * 32 + lhi * 16);
            uint32_t ah_f[2][4];
            #pragma unroll
            for (int mt = 0; mt < 2; mt++) {
                uint32_t off = SWZ64((uint32_t)((wm + mt * 16 + l15) * 64) + kbyte);
                LDSM_X4(ah_f[mt][0], ah_f[mt][1], ah_f[mt][2], ah_f[mt][3], ah_b + off);
            }
            #pragma unroll
            for (int p = 0; p < 2; p++) {
                uint32_t off = SWZ64((uint32_t)((wn + p * 16 + l15) * 64) + kbyte);
                uint32_t r0, r1, r2, r3;
                uint32_t bhi0[2], bhi1[2];
                LDSM_X4(r0, r1, r2, r3, bh_b + off);
                bhi0[0] = r0; bhi0[1] = r2; bhi1[0] = r1; bhi1[1] = r3;
                #pragma unroll
                for (int mt = 0; mt < 2; mt++) {
                    MMA16816(acc[mt][2 * p], ah_f[mt], bhi0);
                    MMA16816(acc[mt][2 * p + 1], ah_f[mt], bhi1);
                }
            }
        }
        stage++; if (stage >= NSTAGE) stage -= NSTAGE;
    }

    #pragma unroll
    for (int mt = 0; mt < 2; mt++) {
        #pragma unroll
        for (int q = 0; q < 2; q++) {
            int gr = brow + wm + mt * 16 + (lane >> 2) + q * 8;
            float pl = 0.f, pu = 0.f;
            #pragma unroll
            for (int nt = 0; nt < 4; nt++) {
                int gc = bcol + wn + nt * 8 + (lane & 3) * 2;
                if (gc < DIN) {
                    float v0 = acc[mt][nt][q * 2 + 0];
                    float v1 = acc[mt][nt][q * 2 + 1];
                    float l0 = lin[gc], u0 = uin[gc];
                    float l1 = lin[gc + 1], u1 = uin[gc + 1];
                    float p0 = fmaxf(v0, 0.f), n0 = fminf(v0, 0.f);
                    float p1 = fmaxf(v1, 0.f), n1 = fminf(v1, 0.f);
                    pl += p0 * l0 + n0 * u0 + p1 * l1 + n1 * u1;
                    pu += p0 * u0 + n0 * l0 + p1 * u1 + n1 * l1;
                }
            }
            pl += __shfl_xor_sync(0xffffffffu, pl, 1);
            pl += __shfl_xor_sync(0xffffffffu, pl, 2);
            pu += __shfl_xor_sync(0xffffffffu, pu, 1);
            pu += __shfl_xor_sync(0xffffffffu, pu, 2);
            if ((lane & 3) == 0) {
                atomicAdd(&cl[gr], pl);
                atomicAdd(&cu[gr], pu);
            }
        }
    }
}

// ---------------- output stage (9 rows) ---------------------------------------
__global__ void build_m4_k(const float* __restrict__ W4, const float* __restrict__ b4,
                           const int* __restrict__ tl, float* __restrict__ M,
                           float* __restrict__ bias) {
    int t = *tl;
    int idx = blockIdx.x * blockDim.x + threadIdx.x;
    if (idx < OUTR * H) {
        int r = idx / H, j = idx % H;
        int c = (r < t) ? r : r + 1;
        M[idx] = W4[(size_t)c * H + j] - W4[(size_t)t * H + j];
    }
    if (idx < OUTR) {
        int c = (idx < t) ? idx : idx + 1;
        bias[idx] = b4[c] - b4[t];
    }
}

__global__ void small_bias_k(const float* __restrict__ A,
                             const float* __restrict__ w, const float* __restrict__ bl,
                             const float* __restrict__ bu, const float* __restrict__ bnext,
                             float* __restrict__ bias) {
    int r = blockIdx.x;
    const float* a = A + (size_t)r * H;
    float au = 0.f, dummy = 0.f;
    for (int j = threadIdx.x; j < H; j += blockDim.x) {
        float v = a[j];
        float p = fmaxf(v, 0.f), n = fminf(v, 0.f);
        au += p * bu[j] + n * bl[j] + v * w[j] * bnext[j];
    }
    blk_reduce2(au, dummy);
    if (threadIdx.x == 0) bias[r] += au;
}

__global__ void zero_k(float* __restrict__ p, int n) {
    int i = blockIdx.x * blockDim.x + threadIdx.x;
    if (i < n) p[i] = 0.f;
}

#define SG_CHUNK 256
__global__ void small_gemm_k(int K, int N, const float* __restrict__ A,
                             const float* __restrict__ ascale,
                             const float* __restrict__ B, float* __restrict__ C) {
    __shared__ float sA[OUTR * SG_CHUNK];
    int k0 = blockIdx.y * SG_CHUNK;
    int n = blockIdx.x * blockDim.x + threadIdx.x;
    for (int idx = threadIdx.x; idx < OUTR * SG_CHUNK; idx += blockDim.x) {
        int r = idx / SG_CHUNK, kk = idx % SG_CHUNK;
        sA[idx] = A[(size_t)r * K + k0 + kk] * ascale[k0 + kk];
    }
    __syncthreads();
    if (n >= N) return;
    float acc[OUTR];
    #pragma unroll
    for (int r = 0; r < OUTR; r++) acc[r] = 0.f;
    #pragma unroll 4
    for (int kk = 0; kk < SG_CHUNK; kk++) {
        float bv = B[(size_t)(k0 + kk) * N + n];
        #pragma unroll
        for (int r = 0; r < OUTR; r++) acc[r] += sA[r * SG_CHUNK + kk] * bv;
    }
    #pragma unroll
    for (int r = 0; r < OUTR; r++) atomicAdd(&C[(size_t)r * N + n], acc[r]);
}

__global__ void final_k(const float* __restrict__ M, const float* __restrict__ lin,
                        const float* __restrict__ uin, const float* __restrict__ bias,
                        float* __restrict__ out) {
    int r = blockIdx.x;
    const float* a = M + (size_t)r * DIN;
    float au = 0.f, dummy = 0.f;
    for (int j = threadIdx.x; j < DIN; j += blockDim.x) {
        float v = a[j];
        au += fmaxf(v, 0.f) * uin[j] + fminf(v, 0.f) * lin[j];
    }
    blk_reduce2(au, dummy);
    if (threadIdx.x == 0) out[r] = au + bias[r];
}

// ---------------- launch ------------------------------------------------------
extern "C" void kernel_launch(void* const* d_in, const int* in_sizes, int n_in,
                              void* d_out, int out_size) {
    const float* W1 = (const float*)d_in[0];
    const float* b1 = (const float*)d_in[1];
    const float* W2 = (const float*)d_in[2];
    const float* b2 = (const float*)d_in[3];
    const float* W3 = (const float*)d_in[4];
    const float* b3 = (const float*)d_in[5];
    const float* W4 = (const float*)d_in[6];
    const float* b4 = (const float*)d_in[7];
    const float* l_in = (const float*)d_in[8];
    const float* u_in = (const float*)d_in[9];
    const float* p_l1 = (const float*)d_in[10];
    const float* p_u1 = (const float*)d_in[11];
    const float* p_l2 = (const float*)d_in[12];
    const float* p_u2 = (const float*)d_in[13];
    const float* p_l3 = (const float*)d_in[14];
    const float* p_u3 = (const float*)d_in[15];
    const int* tl = (const int*)d_in[16];
    float* out = (float*)d_out;

    cudaFuncSetAttribute(gemm_mma_k, cudaFuncAttributeMaxDynamicSharedMemorySize, DSMEM);
    cudaFuncSetAttribute(gemm_mid_mma_k, cudaFuncAttributeMaxDynamicSharedMemorySize, MDSMEM);

    float *T, *w1, *bl1, *bu1, *w2, *bl2, *bu2, *w3, *bl3, *bu3, *cl, *cu;
    float *m4a, *m4b, *bias4;
    __half *Ahi, *W1th, *W2th;
    cudaGetSymbolAddress((void**)&T, g_T);
    cudaGetSymbolAddress((void**)&Ahi, g_Ahi);
    cudaGetSymbolAddress((void**)&W1th, g_W1t_hi);
    cudaGetSymbolAddress((void**)&W2th, g_W2t_hi);
    cudaGetSymbolAddress((void**)&w1, g_w1);   cudaGetSymbolAddress((void**)&bl1, g_bl1);
    cudaGetSymbolAddress((void**)&bu1, g_bu1);
    cudaGetSymbolAddress((void**)&w2, g_w2);   cudaGetSymbolAddress((void**)&bl2, g_bl2);
    cudaGetSymbolAddress((void**)&bu2, g_bu2);
    cudaGetSymbolAddress((void**)&w3, g_w3);   cudaGetSymbolAddress((void**)&bl3, g_bl3);
    cudaGetSymbolAddress((void**)&bu3, g_bu3);
    cudaGetSymbolAddress((void**)&cl, g_cl);   cudaGetSymbolAddress((void**)&cu, g_cu);
    cudaGetSymbolAddress((void**)&m4a, g_m4a); cudaGetSymbolAddress((void**)&m4b, g_m4b);
    cudaGetSymbolAddress((void**)&bias4, g_bias4);

    __half* Thi = (__half*)T;

    // one-time (per launch) B transpose+convert (64k x 32n tiles)
    transp_conv_k<<<dim3(KTOT / 64, (DIN + 31) / 32), dim3(32, 8)>>>(W1, DIN, W1th);
    transp_conv_k<<<dim3(KTOT / 64, H / 32), dim3(32, 8)>>>(W2, H, W2th);

    dim3 gmid(NPAD1 / 128, H / 64);          // 7 x 32 = 224 CTAs
    dim3 gbig(H / 128, H / 128);             // 16 x 16 = 256 CTAs

    // ---- stage 1 (fused concretize + spu) ----
    concretize_spu_k<<<H, 256>>>(W1, l_in, u_in, b1, p_l1, p_u1, w1, bl1, bu1);

    // ---- stage 2 ----
    bias2conv_k<<<H, 512>>>(W2, w1, bl1, bu1, b2, b1, cl, cu, Ahi);
    gemm_mid_mma_k<<<gmid, 256, MDSMEM>>>(Ahi, W1th, cl, cu, l_in, u_in);
    spu_params_k<<<(H + 63) / 64, 64>>>(cl, cu, p_l2, p_u2, w2, bl2, bu2, H);

    // ---- stage 3 ----
    bias2conv_k<<<H, 512>>>(W3, w2, bl2, bu2, b3, b2, cl, cu, Ahi);
    gemm_mma_k<<<gbig, 256, DSMEM>>>(Ahi, W2th, Thi, w1, b1, bl1, bu1, cl, cu);
    gemm_mid_mma_k<<<gmid, 256, MDSMEM>>>(Thi, W1th, cl, cu, l_in, u_in);
    spu_params_k<<<(H + 63) / 64, 64>>>(cl, cu, p_l3, p_u3, w3, bl3, bu3, H);

    // ---- stage 4: output chain (9 rows) ----
    build_m4_k<<<(OUTR * H + 255) / 256, 256>>>(W4, b4, tl, m4a, bias4);
    small_bias_k<<<OUTR, 256>>>(m4a, w3, bl3, bu3, b3, bias4);
    zero_k<<<(OUTR * H + 255) / 256, 256>>>(m4b, OUTR * H);
    small_gemm_k<<<dim3((H + 127) / 128, H / SG_CHUNK), 128>>>(H, H, m4a, w3, W3, m4b);
    small_bias_k<<<OUTR, 256>>>(m4b, w2, bl2, bu2, b2, bias4);
    zero_k<<<(OUTR * H + 255) / 256, 256>>>(m4a, OUTR * H);
    small_gemm_k<<<dim3((H + 127) / 128, H / SG_CHUNK), 128>>>(H, H, m4b, w2, W2, m4a);
    small_bias_k<<<OUTR, 256>>>(m4a, w1, bl1, bu1, b1, bias4);
    zero_k<<<(OUTR * DIN + 255) / 256, 256>>>(m4b, OUTR * DIN);
    small_gemm_k<<<dim3((DIN + 127) / 128, H / SG_CHUNK), 128>>>(H, DIN, m4a, w1, W1, m4b);
    final_k<<<OUTR, 256>>>(m4b, l_in, u_in, bias4, out);
}

// round 14
// speedup vs baseline: 3.1958x; 1.2271x over previous
#include <cuda_runtime.h>
#include <cuda_fp16.h>
#include <math.h>
#include <stdint.h>

#define H     2048
#define DIN   784
#define OUTR  9
#define KTOT  2048
#define KC    32
#define NCHUNK (KTOT / KC)          // 64
#define TILEB  8192                 // 128 rows * 64B
#define STAGEB (2 * TILEB)          // 16KB: Ahi, Bhi
#define NSTAGE 3
#define DSMEM  (NSTAGE * STAGEB + 1024)
// mid-GEMM (64x128 tile)
#define MTILEA 4096
#define MTILEB 8192
#define MSTAGE (MTILEA + MTILEB)    // 12288
#define MDSMEM (NSTAGE * MSTAGE + 1024)
// stage-4 skinny GEMM (16 x 128 tile, KC16 = 64, 128B rows)
#define KC16    64
#define NCHUNK16 (KTOT / KC16)      // 32
#define A16TILE (16 * 128)          // 2KB
#define B16TILE (128 * 128)         // 16KB
#define S16STAGE (A16TILE + B16TILE)
#define DSMEM16 (NSTAGE * S16STAGE + 1024)
#define NPAD1  896

// ---------------- scratch (device globals) ----------------------------------
__device__ float g_T[H * H];        // reused as half[H*H] for stage-3 Thi
__device__ __half g_Ahi[H * H];
__device__ __half g_W1t_hi[NPAD1 * KTOT];   // pad rows stay 0
__device__ __half g_W2t_hi[H * KTOT];
__device__ __half g_W3t_hi[H * KTOT];
__device__ __half g_s4a[16 * KTOT], g_s4b[16 * KTOT];
__device__ float g_w1[H], g_bl1[H], g_bu1[H];
__device__ float g_w2[H], g_bl2[H], g_bu2[H];
__device__ float g_w3[H], g_bl3[H], g_bu3[H];
__device__ float g_cl[H], g_cu[H];
__device__ float g_bias4[OUTR];

// ---------------- PTX helpers ------------------------------------------------
__device__ __forceinline__ uint32_t smem_u32(const void* p) {
    uint32_t a;
    asm("{ .reg .u64 t; cvta.to.shared.u64 t, %1; cvt.u32.u64 %0, t; }" : "=r"(a) : "l"(p));
    return a;
}
#define SWZ64(o)   ((o) ^ (((o) >> 3) & 0x30))
#define SWZ128(o)  ((o) ^ (((o) >> 3) & 0x70))
#define CP_ASYNC16(dst, gsrc) \
    asm volatile("cp.async.cg.shared.global [%0], [%1], 16;" :: "r"(dst), "l"(gsrc))
#define CP_COMMIT() asm volatile("cp.async.commit_group;" ::: "memory")
#define CP_WAIT(n)  asm volatile("cp.async.wait_group %0;" :: "n"(n) : "memory")
#define LDSM_X4(r0, r1, r2, r3, addr) \
    asm volatile("ldmatrix.sync.aligned.m8n8.x4.shared.b16 {%0,%1,%2,%3}, [%4];" \
        : "=r"(r0), "=r"(r1), "=r"(r2), "=r"(r3) : "r"(addr))
#define MMA16816(d, a, b) \
    asm volatile("mma.sync.aligned.m16n8k16.row.col.f32.f16.f16.f32 " \
        "{%0,%1,%2,%3}, {%4,%5,%6,%7}, {%8,%9}, {%0,%1,%2,%3};" \
        : "+f"((d)[0]), "+f"((d)[1]), "+f"((d)[2]), "+f"((d)[3]) \
        : "r"((a)[0]), "r"((a)[1]), "r"((a)[2]), "r"((a)[3]), "r"((b)[0]), "r"((b)[1]))

// ---------------- misc helpers ----------------------------------------------
__device__ __forceinline__ float spu_f(float x) {
    if (x >= 0.f) return x * x - 0.5f;
    float s = 1.f / (1.f + expf(x));
    return s - 1.f;
}
__device__ __forceinline__ float dspu_f(float x) {
    if (x >= 0.f) return 2.f * x;
    float s = 1.f / (1.f + expf(x));
    return -s * (1.f - s);
}
__device__ __forceinline__ void spu_relax(float l, float u, float pl, float pu,
                                          float &w_, float &bl_, float &bu_) {
    float k1 = dspu_f(l), k2 = dspu_f(u);
    float klo = fminf(k1, k2), khi = fmaxf(k1, k2);
    float wl = fminf(fmaxf(pl, klo), khi);
    float wu = fminf(fmaxf(pu, klo), khi);
    float p0 = l, p1 = u, p2 = 0.5f * (l + u), p3 = fminf(fmaxf(0.f, l), u);
    float s0 = spu_f(p0), s1 = spu_f(p1), s2 = spu_f(p2), s3 = spu_f(p3);
    bl_ = fminf(fminf(s0 - wl * p0, s1 - wl * p1), fminf(s2 - wl * p2, s3 - wl * p3));
    bu_ = fmaxf(fmaxf(s0 - wu * p0, s1 - wu * p1), fmaxf(s2 - wu * p2, s3 - wu * p3));
    w_ = wl;
}
__device__ __forceinline__ void blk_reduce2(float &a, float &b) {
    const unsigned m = 0xffffffffu;
    #pragma unroll
    for (int o = 16; o > 0; o >>= 1) {
        a += __shfl_down_sync(m, a, o);
        b += __shfl_down_sync(m, b, o);
    }
    __shared__ float sa[16], sb[16];
    int w = threadIdx.x >> 5, l = threadIdx.x & 31;
    int nw = blockDim.x >> 5;
    if (l == 0) { sa[w] = a; sb[w] = b; }
    __syncthreads();
    if (w == 0) {
        a = (l < nw) ? sa[l] : 0.f;
        b = (l < nw) ? sb[l] : 0.f;
        #pragma unroll
        for (int o = 8; o > 0; o >>= 1) {
            a += __shfl_down_sync(m, a, o);
            b += __shfl_down_sync(m, b, o);
        }
    }
}

// ---------------- fused stage-1: concretize W1 row + SPU params --------------
__global__ void concretize_spu_k(const float* __restrict__ W1v,
                                 const float* __restrict__ lin, const float* __restrict__ uin,
                                 const float* __restrict__ b1v,
                                 const float* __restrict__ pl, const float* __restrict__ pu,
                                 float* __restrict__ w, float* __restrict__ bl,
                                 float* __restrict__ bu) {
    int row = blockIdx.x;
    const float* a = W1v + (size_t)row * DIN;
    float al = 0.f, au = 0.f;
    for (int j = threadIdx.x * 4; j < DIN; j += blockDim.x * 4) {
        float4 v = *(const float4*)(a + j);
        float4 L = *(const float4*)(lin + j);
        float4 U = *(const float4*)(uin + j);
        float pA = fmaxf(v.x, 0.f), nA = fminf(v.x, 0.f);
        float pB = fmaxf(v.y, 0.f), nB = fminf(v.y, 0.f);
        float pC = fmaxf(v.z, 0.f), nC = fminf(v.z, 0.f);
        float pD = fmaxf(v.w, 0.f), nD = fminf(v.w, 0.f);
        al += pA * L.x + nA * U.x + pB * L.y + nB * U.y
            + pC * L.z + nC * U.z + pD * L.w + nD * U.w;
        au += pA * U.x + nA * L.x + pB * U.y + nB * L.y
            + pC * U.z + nC * L.z + pD * U.w + nD * L.w;
    }
    blk_reduce2(al, au);
    if (threadIdx.x == 0) {
        float l = al + b1v[row], u = au + b1v[row];
        float w_, bl_, bu_;
        spu_relax(l, u, pl[row], pu[row], w_, bl_, bu_);
        w[row] = w_; bl[row] = bl_; bu[row] = bu_;
    }
}

__global__ void spu_params_k(const float* __restrict__ lf, const float* __restrict__ uf,
                             const float* __restrict__ pl, const float* __restrict__ pu,
                             float* __restrict__ w, float* __restrict__ bl,
                             float* __restrict__ bu, int n) {
    int i = blockIdx.x * blockDim.x + threadIdx.x;
    if (i >= n) return;
    float w_, bl_, bu_;
    spu_relax(lf[i], uf[i], pl[i], pu[i], w_, bl_, bu_);
    w[i] = w_; bl[i] = bl_; bu[i] = bu_;
}

// bias + fp16 convert (hi only), 512 threads: one float4 iteration per row
__global__ __launch_bounds__(512)
void bias2conv_k(const float* __restrict__ W,
                 const float* __restrict__ wprev,
                 const float* __restrict__ blprev, const float* __restrict__ buprev,
                 const float* __restrict__ bthis, const float* __restrict__ bprev,
                 float* __restrict__ cl, float* __restrict__ cu,
                 __half* __restrict__ hi) {
    int row = blockIdx.x;
    const float* wr = W + (size_t)row * H;
    __half* hr = hi + (size_t)row * H;
    float al = 0.f, au = 0.f;
    int j = threadIdx.x * 4;
    {
        float4 v  = *(const float4*)(wr + j);
        float4 wp = *(const float4*)(wprev + j);
        float4 bp = *(const float4*)(bprev + j);
        float4 bL = *(const float4*)(blprev + j);
        float4 bU = *(const float4*)(buprev + j);
        float m0 = v.x * wp.x, m1 = v.y * wp.y, m2 = v.z * wp.z, m3 = v.w * wp.w;
        float sb = m0 * bp.x + m1 * bp.y + m2 * bp.z + m3 * bp.w;
        float pA = fmaxf(v.x, 0.f), nA = fminf(v.x, 0.f);
        float pB = fmaxf(v.y, 0.f), nB = fminf(v.y, 0.f);
        float pC = fmaxf(v.z, 0.f), nC = fminf(v.z, 0.f);
        float pD = fmaxf(v.w, 0.f), nD = fminf(v.w, 0.f);
        al += pA * bL.x + nA * bU.x + pB * bL.y + nB * bU.y
            + pC * bL.z + nC * bU.z + pD * bL.w + nD * bU.w + sb;
        au += pA * bU.x + nA * bL.x + pB * bU.y + nB * bL.y
            + pC * bU.z + nC * bL.z + pD * bU.w + nD * bL.w + sb;
        __half2 h0; h0.x = __float2half_rn(m0); h0.y = __float2half_rn(m1);
        __half2 h1; h1.x = __float2half_rn(m2); h1.y = __float2half_rn(m3);
        *(__half2*)(hr + j)     = h0;
        *(__half2*)(hr + j + 2) = h1;
    }
    blk_reduce2(al, au);
    if (threadIdx.x == 0) { cl[row] = bthis[row] + al; cu[row] = bthis[row] + au; }
}

// B [K x N] fp32 -> Bt_hi [Npad x K] fp16. Tile: 64 k-rows x 32 n-cols.
__global__ void transp_conv_k(const float* __restrict__ B, int N,
                              __half* __restrict__ thi) {
    __shared__ float t[64][33];
    int k0 = blockIdx.x * 64, n0 = blockIdx.y * 32;
    int x = threadIdx.x, y = threadIdx.y;       // 32 x 8
    #pragma unroll
    for (int yy = y; yy < 64; yy += 8) {
        int n = n0 + x;
        t[yy][x] = (n < N) ? B[(size_t)(k0 + yy) * N + n] : 0.f;
    }
    __syncthreads();
    #pragma unroll
    for (int nn = y; nn < 32; nn += 8) {
        int n = n0 + nn;
        if (n < N) {
            __half2 hv;
            hv.x = __float2half_rn(t[2 * x][nn]);
            hv.y = __float2half_rn(t[2 * x + 1][nn]);
            *(__half2*)(thi + (size_t)n * KTOT + k0 + 2 * x) = hv;
        }
    }
}

// ---------------- big GEMM: 128x128 tile, 1-product fp16, MODE-0 epilogue -----
__global__ __launch_bounds__(256, 2)
void gemm_mma_k(const __half* __restrict__ Ahi, const __half* __restrict__ Bhi,
                __half* __restrict__ Ohi,
                const float* __restrict__ scale, const float* __restrict__ bvec,
                const float* __restrict__ blv, const float* __restrict__ buv,
                float* __restrict__ cl, float* __restrict__ cu) {
    extern __shared__ char dsm[];
    uint32_t raw = smem_u32(dsm);
    uint32_t dbase = (raw + 1023) & ~1023u;

    int tid = threadIdx.x, wid = tid >> 5, lane = tid & 31;
    int brow = blockIdx.y * 128, bcol = blockIdx.x * 128;
    int wm = (wid >> 2) * 64, wn = (wid & 3) * 32;

    const __half* gbase[2] = { Ahi + (size_t)brow * KTOT, Bhi + (size_t)bcol * KTOT };
    const __half* gsrc[4];
    uint32_t sdst[4];
    #pragma unroll
    for (int i = 0; i < 4; i++) {
        int s = i * 256 + tid;
        int t = s >> 9, row = (s >> 2) & 127, sg = s & 3;
        gsrc[i] = gbase[t] + (size_t)row * KTOT + sg * 8;
        sdst[i] = (uint32_t)(t * TILEB) + SWZ64((uint32_t)(row * 64 + sg * 16));
    }

    float acc[4][4][4];
    #pragma unroll
    for (int mt = 0; mt < 4; mt++)
        #pragma unroll
        for (int nt = 0; nt < 4; nt++)
            #pragma unroll
            for (int q = 0; q < 4; q++) acc[mt][nt][q] = 0.f;

    int l15 = lane & 15, lhi = lane >> 4;

    #pragma unroll
    for (int st = 0; st < 2; st++) {
        uint32_t sb = dbase + st * STAGEB;
        int k0 = st * KC;
        #pragma unroll
        for (int i = 0; i < 4; i++) CP_ASYNC16(sb + sdst[i], gsrc[i] + k0);
        CP_COMMIT();
    }

    int stage = 0;
    for (int chunk = 0; chunk < NCHUNK; chunk++) {
        if (chunk + 1 < NCHUNK) CP_WAIT(1); else CP_WAIT(0);
        __syncthreads();
        if (chunk + 2 < NCHUNK) {
            int ns = stage + 2; if (ns >= NSTAGE) ns -= NSTAGE;
            uint32_t sb = dbase + ns * STAGEB;
            int k0 = (chunk + 2) * KC;
            #pragma unroll
            for (int i = 0; i < 4; i++) CP_ASYNC16(sb + sdst[i], gsrc[i] + k0);
            CP_COMMIT();
        }
        uint32_t ah_b = dbase + stage * STAGEB;
        uint32_t bh_b = ah_b + TILEB;
        #pragma unroll
        for (int kb = 0; kb < 2; kb++) {
            uint32_t kbyte = (uint32_t)(kb * 32 + lhi * 16);
            uint32_t ah_f[4][4];
            #pragma unroll
            for (int mt = 0; mt < 4; mt++) {
                uint32_t off = SWZ64((uint32_t)((wm + mt * 16 + l15) * 64) + kbyte);
                LDSM_X4(ah_f[mt][0], ah_f[mt][1], ah_f[mt][2], ah_f[mt][3], ah_b + off);
            }
            #pragma unroll
            for (int p = 0; p < 2; p++) {
                uint32_t off = SWZ64((uint32_t)((wn + p * 16 + l15) * 64) + kbyte);
                uint32_t r0, r1, r2, r3;
                uint32_t bhi0[2], bhi1[2];
                LDSM_X4(r0, r1, r2, r3, bh_b + off);
                bhi0[0] = r0; bhi0[1] = r2; bhi1[0] = r1; bhi1[1] = r3;
                #pragma unroll
                for (int mt = 0; mt < 4; mt++) {
                    MMA16816(acc[mt][2 * p], ah_f[mt], bhi0);
                    MMA16816(acc[mt][2 * p + 1], ah_f[mt], bhi1);
                }
            }
        }
        stage++; if (stage >= NSTAGE) stage -= NSTAGE;
    }

    #pragma unroll
    for (int mt = 0; mt < 4; mt++) {
        #pragma unroll
        for (int q = 0; q < 2; q++) {
            int gr = brow + wm + mt * 16 + (lane >> 2) + q * 8;
            float pl = 0.f, pu = 0.f;
            #pragma unroll
            for (int nt = 0; nt < 4; nt++) {
                int gc = bcol + wn + nt * 8 + (lane & 3) * 2;
                float v0 = acc[mt][nt][q * 2 + 0];
                float v1 = acc[mt][nt][q * 2 + 1];
                float m0 = v0 * scale[gc], m1 = v1 * scale[gc + 1];
                __half2 hv; hv.x = __float2half_rn(m0); hv.y = __float2half_rn(m1);
                *(__half2*)(Ohi + (size_t)gr * H + gc) = hv;
                float p0 = fmaxf(v0, 0.f), n0 = fminf(v0, 0.f);
                float p1 = fmaxf(v1, 0.f), n1 = fminf(v1, 0.f);
                float sb = m0 * bvec[gc] + m1 * bvec[gc + 1];
                pl += p0 * blv[gc] + n0 * buv[gc] + p1 * blv[gc + 1] + n1 * buv[gc + 1] + sb;
                pu += p0 * buv[gc] + n0 * blv[gc] + p1 * buv[gc + 1] + n1 * blv[gc + 1] + sb;
            }
            pl += __shfl_xor_sync(0xffffffffu, pl, 1);
            pl += __shfl_xor_sync(0xffffffffu, pl, 2);
            pu += __shfl_xor_sync(0xffffffffu, pu, 1);
            pu += __shfl_xor_sync(0xffffffffu, pu, 2);
            if ((lane & 3) == 0) {
                atomicAdd(&cl[gr], pl);
                atomicAdd(&cu[gr], pu);
            }
        }
    }
}

// ---------------- mid GEMM: 64x128 tile, 1-product fp16, concretize epilogue --
__global__ __launch_bounds__(256, 2)
void gemm_mid_mma_k(const __half* __restrict__ Ahi, const __half* __restrict__ Bhi,
                    float* __restrict__ cl, float* __restrict__ cu,
                    const float* __restrict__ lin, const float* __restrict__ uin) {
    extern __shared__ char dsm[];
    uint32_t raw = smem_u32(dsm);
    uint32_t dbase = (raw + 1023) & ~1023u;

    int tid = threadIdx.x, wid = tid >> 5, lane = tid & 31;
    int brow = blockIdx.y * 64, bcol = blockIdx.x * 128;
    int wm = (wid >> 2) * 32, wn = (wid & 3) * 32;

    const __half* gsrc[3];
    uint32_t sdst[3];
    #pragma unroll
    for (int i = 0; i < 3; i++) {
        int s = i * 256 + tid;
        int rowg = s >> 2, sg = s & 3;
        if (rowg < 64) {
            gsrc[i] = Ahi + (size_t)(brow + rowg) * KTOT + sg * 8;
            sdst[i] = SWZ64((uint32_t)(rowg * 64 + sg * 16));
        } else {
            int r = rowg - 64;
            gsrc[i] = Bhi + (size_t)(bcol + r) * KTOT + sg * 8;
            sdst[i] = (uint32_t)MTILEA + SWZ64((uint32_t)(r * 64 + sg * 16));
        }
    }

    float acc[2][4][4];
    #pragma unroll
    for (int mt = 0; mt < 2; mt++)
        #pragma unroll
        for (int nt = 0; nt < 4; nt++)
            #pragma unroll
            for (int q = 0; q < 4; q++) acc[mt][nt][q] = 0.f;

    int l15 = lane & 15, lhi = lane >> 4;

    #pragma unroll
    for (int st = 0; st < 2; st++) {
        uint32_t sb = dbase + st * MSTAGE;
        int k0 = st * KC;
        #pragma unroll
        for (int i = 0; i < 3; i++) CP_ASYNC16(sb + sdst[i], gsrc[i] + k0);
        CP_COMMIT();
    }

    int stage = 0;
    for (int chunk = 0; chunk < NCHUNK; chunk++) {
        if (chunk + 1 < NCHUNK) CP_WAIT(1); else CP_WAIT(0);
        __syncthreads();
        if (chunk + 2 < NCHUNK) {
            int ns = stage + 2; if (ns >= NSTAGE) ns -= NSTAGE;
            uint32_t sb = dbase + ns * MSTAGE;
            int k0 = (chunk + 2) * KC;
            #pragma unroll
            for (int i = 0; i < 3; i++) CP_ASYNC16(sb + sdst[i], gsrc[i] + k0);
            CP_COMMIT();
        }
        uint32_t ah_b = dbase + stage * MSTAGE;
        uint32_t bh_b = ah_b + MTILEA;
        #pragma unroll
        for (int kb = 0; kb < 2; kb++) {
            uint32_t kbyte = (uint32_t)(kb * 32 + lhi * 16);
            uint32_t ah_f[2][4];
            #pragma unroll
            for (int mt = 0; mt < 2; mt++) {
                uint32_t off = SWZ64((uint32_t)((wm + mt * 16 + l15) * 64) + kbyte);
                LDSM_X4(ah_f[mt][0], ah_f[mt][1], ah_f[mt][2], ah_f[mt][3], ah_b + off);
            }
            #pragma unroll
            for (int p = 0; p < 2; p++) {
                uint32_t off = SWZ64((uint32_t)((wn + p * 16 + l15) * 64) + kbyte);
                uint32_t r0, r1, r2, r3;
                uint32_t bhi0[2], bhi1[2];
                LDSM_X4(r0, r1, r2, r3, bh_b + off);
                bhi0[0] = r0; bhi0[1] = r2; bhi1[0] = r1; bhi1[1] = r3;
                #pragma unroll
                for (int mt = 0; mt < 2; mt++) {
                    MMA16816(acc[mt][2 * p], ah_f[mt], bhi0);
                    MMA16816(acc[mt][2 * p + 1], ah_f[mt], bhi1);
                }
            }
        }
        stage++; if (stage >= NSTAGE) stage -= NSTAGE;
    }

    #pragma unroll
    for (int mt = 0; mt < 2; mt++) {
        #pragma unroll
        for (int q = 0; q < 2; q++) {
            int gr = brow + wm + mt * 16 + (lane >> 2) + q * 8;
            float pl = 0.f, pu = 0.f;
            #pragma unroll
            for (int nt = 0; nt < 4; nt++) {
                int gc = bcol + wn + nt * 8 + (lane & 3) * 2;
                if (gc < DIN) {
                    float v0 = acc[mt][nt][q * 2 + 0];
                    float v1 = acc[mt][nt][q * 2 + 1];
                    float l0 = lin[gc], u0 = uin[gc];
                    float l1 = lin[gc + 1], u1 = uin[gc + 1];
                    float p0 = fmaxf(v0, 0.f), n0 = fminf(v0, 0.f);
                    float p1 = fmaxf(v1, 0.f), n1 = fminf(v1, 0.f);
                    pl += p0 * l0 + n0 * u0 + p1 * l1 + n1 * u1;
                    pu += p0 * u0 + n0 * l0 + p1 * u1 + n1 * l1;
                }
            }
            pl += __shfl_xor_sync(0xffffffffu, pl, 1);
            pl += __shfl_xor_sync(0xffffffffu, pl, 2);
            pu += __shfl_xor_sync(0xffffffffu, pu, 1);
            pu += __shfl_xor_sync(0xffffffffu, pu, 2);
            if ((lane & 3) == 0) {
                atomicAdd(&cl[gr], pl);
                atomicAdd(&cu[gr], pu);
            }
        }
    }
}

// ---------------- stage-4: init + fused build ---------------------------------
__global__ void init4_k(const float* __restrict__ b4, const int* __restrict__ tl,
                        float* __restrict__ bias4, float* __restrict__ out) {
    int t = *tl;
    int r = threadIdx.x;
    if (r < OUTR) {
        int c = (r < t) ? r : r + 1;
        bias4[r] = b4[c] - b4[t];
        out[r] = 0.f;
    }
}

// grid 16*8 blocks of 256: r = blockIdx>>3, j0 = (blockIdx&7)*256
__global__ void build_m4conv_k(const float* __restrict__ W4, const int* __restrict__ tl,
                               const float* __restrict__ w3v, const float* __restrict__ bl3v,
                               const float* __restrict__ bu3v, const float* __restrict__ b3v,
                               __half* __restrict__ A0, float* __restrict__ bias4) {
    int t = *tl;
    int r = blockIdx.x >> 3;
    int j = (blockIdx.x & 7) * 256 + threadIdx.x;
    if (r >= OUTR) {                 // pad rows 9..15 stay zero
        A0[(size_t)r * KTOT + j] = __float2half_rn(0.f);
        return;
    }
    int c = (r < t) ? r : r + 1;
    float v = W4[(size_t)c * H + j] - W4[(size_t)t * H + j];
    float m = v * w3v[j];
    A0[(size_t)r * KTOT + j] = __float2half_rn(m);
    float au = fmaxf(v, 0.f) * bu3v[j] + fminf(v, 0.f) * bl3v[j] + m * b3v[j];
    float dummy = 0.f;
    blk_reduce2(au, dummy);
    if (threadIdx.x == 0) atomicAdd(&bias4[r], au);
}

// ---------------- stage-4 skinny GEMM: 16 x 128 tile --------------------------
// C[16, bcol:bcol+128] = A[16,K] @ Bt[bcol.., K]^T
// MODE 0: m=v*scale[gc]; Aout=fp16(m); bias4[r] += pos(v)*buv+neg(v)*blv+m*bvec
// MODE 1: out[r] += pos(v)*uin[gc]+neg(v)*lin[gc]  (gc < DIN)
template <int MODE>
__global__ __launch_bounds__(128)
void gemm16_k(const __half* __restrict__ A, const __half* __restrict__ Bt,
              __half* __restrict__ Aout,
              const float* __restrict__ scale, const float* __restrict__ bvec,
              const float* __restrict__ blv, const float* __restrict__ buv,
              float* __restrict__ bias4,
              const float* __restrict__ lin, const float* __restrict__ uin,
              float* __restrict__ out) {
    extern __shared__ char dsm[];
    uint32_t raw = smem_u32(dsm);
    uint32_t dbase = (raw + 1023) & ~1023u;

    int tid = threadIdx.x, wid = tid >> 5, lane = tid & 31;
    int bcol = blockIdx.x * 128;
    int wn = wid * 32;

    // staging: 1152 segs (A 16x8 + B 128x8), 9 per thread
    const __half* gsrc[9];
    uint32_t sdst[9];
    #pragma unroll
    for (int i = 0; i < 9; i++) {
        int s = i * 128 + tid;          // 0..1151
        if (s < 128) {
            int row = s >> 3, sg = s & 7;
            gsrc[i] = A + (size_t)row * KTOT + sg * 8;
            sdst[i] = SWZ128((uint32_t)(row * 128 + sg * 16));
        } else {
            int ss = s - 128;
            int row = ss >> 3, sg = ss & 7;
            gsrc[i] = Bt + (size_t)(bcol + row) * KTOT + sg * 8;
            sdst[i] = (uint32_t)A16TILE + SWZ128((uint32_t)(row * 128 + sg * 16));
        }
    }

    float acc[4][4];
    #pragma unroll
    for (int nt = 0; nt < 4; nt++)
        #pragma unroll
        for (int q = 0; q < 4; q++) acc[nt][q] = 0.f;

    int l15 = lane & 15, lhi = lane >> 4;

    #pragma unroll
    for (int st = 0; st < 2; st++) {
        uint32_t sb = dbase + st * S16STAGE;
        int k0 = st * KC16;
        #pragma unroll
        for (int i = 0; i < 9; i++) CP_ASYNC16(sb + sdst[i], gsrc[i] + k0);
        CP_COMMIT();
    }

    int stage = 0;
    for (int chunk = 0; chunk < NCHUNK16; chunk++) {
        if (chunk + 1 < NCHUNK16) CP_WAIT(1); else CP_WAIT(0);
        __syncthreads();
        if (chunk + 2 < NCHUNK16) {
            int ns = stage + 2; if (ns >= NSTAGE) ns -= NSTAGE;
            uint32_t sb = dbase + ns * S16STAGE;
            int k0 = (chunk + 2) * KC16;
            #pragma unroll
            for (int i = 0; i < 9; i++) CP_ASYNC16(sb + sdst[i], gsrc[i] + k0);
            CP_COMMIT();
        }
        uint32_t a_b = dbase + stage * S16STAGE;
        uint32_t b_b = a_b + A16TILE;
        #pragma unroll
        for (int kb = 0; kb < 4; kb++) {
            uint32_t kbyte = (uint32_t)(kb * 32 + lhi * 16);
            uint32_t a_f[4];
            {
                uint32_t off = SWZ128((uint32_t)(l15 * 128) + kbyte);
                LDSM_X4(a_f[0], a_f[1], a_f[2], a_f[3], a_b + off);
            }
            #pragma unroll
            for (int p = 0; p < 2; p++) {
                uint32_t off = SWZ128((uint32_t)((wn + p * 16 + l15) * 128) + kbyte);
                uint32_t r0, r1, r2, r3;
                uint32_t bhi0[2], bhi1[2];
                LDSM_X4(r0, r1, r2, r3, b_b + off);
                bhi0[0] = r0; bhi0[1] = r2; bhi1[0] = r1; bhi1[1] = r3;
                MMA16816(acc[2 * p], a_f, bhi0);
                MMA16816(acc[2 * p + 1], a_f, bhi1);
            }
        }
        stage++; if (stage >= NSTAGE) stage -= NSTAGE;
    }

    // epilogue: rows r0 = lane>>2, r1 = r0 + 8
    int r0 = lane >> 2, r1 = r0 + 8;
    float s0 = 0.f, s1 = 0.f;
    #pragma unroll
    for (int nt = 0; nt < 4; nt++) {
        int gc = bcol + wn + nt * 8 + (lane & 3) * 2;
        float v0 = acc[nt][0], v1 = acc[nt][1];   // row r0
        float v2 = acc[nt][2], v3 = acc[nt][3];   // row r1
        if (MODE == 0) {
            float sc0 = scale[gc], sc1 = scale[gc + 1];
            float m0 = v0 * sc0, m1 = v1 * sc1;
            float m2 = v2 * sc0, m3 = v3 * sc1;
            __half2 h0; h0.x = __float2half_rn(m0); h0.y = __float2half_rn(m1);
            __half2 h1; h1.x = __float2half_rn(m2); h1.y = __float2half_rn(m3);
            *(__half2*)(Aout + (size_t)r0 * KTOT + gc) = h0;
            *(__half2*)(Aout + (size_t)r1 * KTOT + gc) = h1;
            float b0 = bvec[gc], b1 = bvec[gc + 1];
            float bl0 = blv[gc], bl1 = blv[gc + 1];
            float bu0 = buv[gc], bu1 = buv[gc + 1];
            s0 += fmaxf(v0, 0.f) * bu0 + fminf(v0, 0.f) * bl0 + m0 * b0
                + fmaxf(v1, 0.f) * bu1 + fminf(v1, 0.f) * bl1 + m1 * b1;
            s1 += fmaxf(v2, 0.f) * bu0 + fminf(v2, 0.f) * bl0 + m2 * b0
                + fmaxf(v3, 0.f) * bu1 + fminf(v3, 0.f) * bl1 + m3 * b1;
        } else {
            if (gc < DIN) {
                float l0 = lin[gc], u0 = uin[gc];
                float l1 = lin[gc + 1], u1 = uin[gc + 1];
                s0 += fmaxf(v0, 0.f) * u0 + fminf(v0, 0.f) * l0
                    + fmaxf(v1, 0.f) * u1 + fminf(v1, 0.f) * l1;
                s1 += fmaxf(v2, 0.f) * u0 + fminf(v2, 0.f) * l0
                    + fmaxf(v3, 0.f) * u1 + fminf(v3, 0.f) * l1;
            }
        }
    }
    s0 += __shfl_xor_sync(0xffffffffu, s0, 1);
    s0 += __shfl_xor_sync(0xffffffffu, s0, 2);
    s1 += __shfl_xor_sync(0xffffffffu, s1, 1);
    s1 += __shfl_xor_sync(0xffffffffu, s1, 2);
    if ((lane & 3) == 0) {
        if (MODE == 0) {
            if (r0 < OUTR) atomicAdd(&bias4[r0], s0);
            if (r1 < OUTR) atomicAdd(&bias4[r1], s1);
        } else {
            if (r0 < OUTR) atomicAdd(&out[r0], s0);
            if (r1 < OUTR) atomicAdd(&out[r1], s1);
        }
    }
}

__global__ void final_add_k(const float* __restrict__ bias4, float* __restrict__ out) {
    int r = threadIdx.x;
    if (r < OUTR) out[r] += bias4[r];
}

// ---------------- launch ------------------------------------------------------
extern "C" void kernel_launch(void* const* d_in, const int* in_sizes, int n_in,
                              void* d_out, int out_size) {
    const float* W1 = (const float*)d_in[0];
    const float* b1 = (const float*)d_in[1];
    const float* W2 = (const float*)d_in[2];
    const float* b2 = (const float*)d_in[3];
    const float* W3 = (const float*)d_in[4];
    const float* b3 = (const float*)d_in[5];
    const float* W4 = (const float*)d_in[6];
    const float* b4 = (const float*)d_in[7];
    const float* l_in = (const float*)d_in[8];
    const float* u_in = (const float*)d_in[9];
    const float* p_l1 = (const float*)d_in[10];
    const float* p_u1 = (const float*)d_in[11];
    const float* p_l2 = (const float*)d_in[12];
    const float* p_u2 = (const float*)d_in[13];
    const float* p_l3 = (const float*)d_in[14];
    const float* p_u3 = (const float*)d_in[15];
    const int* tl = (const int*)d_in[16];
    float* out = (float*)d_out;

    cudaFuncSetAttribute(gemm_mma_k, cudaFuncAttributeMaxDynamicSharedMemorySize, DSMEM);
    cudaFuncSetAttribute(gemm_mid_mma_k, cudaFuncAttributeMaxDynamicSharedMemorySize, MDSMEM);
    cudaFuncSetAttribute(gemm16_k<0>, cudaFuncAttributeMaxDynamicSharedMemorySize, DSMEM16);
    cudaFuncSetAttribute(gemm16_k<1>, cudaFuncAttributeMaxDynamicSharedMemorySize, DSMEM16);

    float *T, *w1, *bl1, *bu1, *w2, *bl2, *bu2, *w3, *bl3, *bu3, *cl, *cu, *bias4;
    __half *Ahi, *W1th, *W2th, *W3th, *s4a, *s4b;
    cudaGetSymbolAddress((void**)&T, g_T);
    cudaGetSymbolAddress((void**)&Ahi, g_Ahi);
    cudaGetSymbolAddress((void**)&W1th, g_W1t_hi);
    cudaGetSymbolAddress((void**)&W2th, g_W2t_hi);
    cudaGetSymbolAddress((void**)&W3th, g_W3t_hi);
    cudaGetSymbolAddress((void**)&s4a, g_s4a);  cudaGetSymbolAddress((void**)&s4b, g_s4b);
    cudaGetSymbolAddress((void**)&w1, g_w1);   cudaGetSymbolAddress((void**)&bl1, g_bl1);
    cudaGetSymbolAddress((void**)&bu1, g_bu1);
    cudaGetSymbolAddress((void**)&w2, g_w2);   cudaGetSymbolAddress((void**)&bl2, g_bl2);
    cudaGetSymbolAddress((void**)&bu2, g_bu2);
    cudaGetSymbolAddress((void**)&w3, g_w3);   cudaGetSymbolAddress((void**)&bl3, g_bl3);
    cudaGetSymbolAddress((void**)&bu3, g_bu3);
    cudaGetSymbolAddress((void**)&cl, g_cl);   cudaGetSymbolAddress((void**)&cu, g_cu);
    cudaGetSymbolAddress((void**)&bias4, g_bias4);

    __half* Thi = (__half*)T;

    // upfront: transposes + bias init
    transp_conv_k<<<dim3(KTOT / 64, (DIN + 31) / 32), dim3(32, 8)>>>(W1, DIN, W1th);
    transp_conv_k<<<dim3(KTOT / 64, H / 32), dim3(32, 8)>>>(W2, H, W2th);
    transp_conv_k<<<dim3(KTOT / 64, H / 32), dim3(32, 8)>>>(W3, H, W3th);
    init4_k<<<1, 32>>>(b4, tl, bias4, out);

    dim3 gmid(NPAD1 / 128, H / 64);          // 7 x 32
    dim3 gbig(H / 128, H / 128);             // 16 x 16

    // ---- stage 1 ----
    concretize_spu_k<<<H, 256>>>(W1, l_in, u_in, b1, p_l1, p_u1, w1, bl1, bu1);

    // ---- stage 2 ----
    bias2conv_k<<<H, 512>>>(W2, w1, bl1, bu1, b2, b1, cl, cu, Ahi);
    gemm_mid_mma_k<<<gmid, 256, MDSMEM>>>(Ahi, W1th, cl, cu, l_in, u_in);
    spu_params_k<<<(H + 63) / 64, 64>>>(cl, cu, p_l2, p_u2, w2, bl2, bu2, H);

    // ---- stage 3 ----
    bias2conv_k<<<H, 512>>>(W3, w2, bl2, bu2, b3, b2, cl, cu, Ahi);
    gemm_mma_k<<<gbig, 256, DSMEM>>>(Ahi, W2th, Thi, w1, b1, bl1, bu1, cl, cu);
    gemm_mid_mma_k<<<gmid, 256, MDSMEM>>>(Thi, W1th, cl, cu, l_in, u_in);
    spu_params_k<<<(H + 63) / 64, 64>>>(cl, cu, p_l3, p_u3, w3, bl3, bu3, H);

    // ---- stage 4: tensor-core chain, fused bias epilogues ----
    build_m4conv_k<<<16 * 8, 256>>>(W4, tl, w3, bl3, bu3, b3, s4a, bias4);
    gemm16_k<0><<<H / 128, 128, DSMEM16>>>(s4a, W3th, s4b,
                                           w2, b2, bl2, bu2, bias4, nullptr, nullptr, nullptr);
    gemm16_k<0><<<H / 128, 128, DSMEM16>>>(s4b, W2th, s4a,
                                           w1, b1, bl1, bu1, bias4, nullptr, nullptr, nullptr);
    gemm16_k<1><<<NPAD1 / 128, 128, DSMEM16>>>(s4a, W1th, nullptr,
                                               nullptr, nullptr, nullptr, nullptr, nullptr,
                                               l_in, u_in, out);
    final_add_k<<<1, 32>>>(bias4, out);
}

// round 15
// speedup vs baseline: 3.4412x; 1.0768x over previous
#include <cuda_runtime.h>
#include <cuda_fp16.h>
#include <math.h>
#include <stdint.h>

#define H     2048
#define DIN   784
#define OUTR  9
#define KTOT  2048
#define KC    32
#define NCHUNK (KTOT / KC)          // 64
#define TILEB  8192                 // 128 rows * 64B
#define STAGEB (2 * TILEB)          // 16KB: Ahi, Bhi
#define NSTAGE 3
#define DSMEM  (NSTAGE * STAGEB + 1024)
// mid-GEMM (64x128 tile)
#define MTILEA 4096
#define MTILEB 8192
#define MSTAGE (MTILEA + MTILEB)    // 12288
#define MDSMEM (NSTAGE * MSTAGE + 1024)
// stage-4 skinny GEMM (16 x 64 tile, KC16 = 64, 128B rows)
#define KC16    64
#define NCHUNK16 (KTOT / KC16)      // 32
#define A16TILE (16 * 128)          // 2KB
#define B16TILE (64 * 128)          // 8KB
#define S16STAGE (A16TILE + B16TILE)
#define DSMEM16 (NSTAGE * S16STAGE + 1024)
#define NPAD1  896

// ---------------- scratch (device globals) ----------------------------------
__device__ float g_T[H * H];        // reused as half[H*H] for stage-3 Thi
__device__ __half g_Ahi[H * H];
__device__ __half g_W1t_hi[NPAD1 * KTOT];   // pad rows stay 0
__device__ __half g_W2t_hi[H * KTOT];
__device__ __half g_W3t_hi[H * KTOT];
__device__ __half g_s4a[16 * KTOT], g_s4b[16 * KTOT];
__device__ float g_w1[H], g_bl1[H], g_bu1[H];
__device__ float g_w2[H], g_bl2[H], g_bu2[H];
__device__ float g_w3[H], g_bl3[H], g_bu3[H];
__device__ float g_cl[H], g_cu[H];
__device__ float g_bias4[OUTR];

// ---------------- PTX helpers ------------------------------------------------
__device__ __forceinline__ uint32_t smem_u32(const void* p) {
    uint32_t a;
    asm("{ .reg .u64 t; cvta.to.shared.u64 t, %1; cvt.u32.u64 %0, t; }" : "=r"(a) : "l"(p));
    return a;
}
#define SWZ64(o)   ((o) ^ (((o) >> 3) & 0x30))
#define SWZ128(o)  ((o) ^ (((o) >> 3) & 0x70))
#define CP_ASYNC16(dst, gsrc) \
    asm volatile("cp.async.cg.shared.global [%0], [%1], 16;" :: "r"(dst), "l"(gsrc))
#define CP_COMMIT() asm volatile("cp.async.commit_group;" ::: "memory")
#define CP_WAIT(n)  asm volatile("cp.async.wait_group %0;" :: "n"(n) : "memory")
#define LDSM_X4(r0, r1, r2, r3, addr) \
    asm volatile("ldmatrix.sync.aligned.m8n8.x4.shared.b16 {%0,%1,%2,%3}, [%4];" \
        : "=r"(r0), "=r"(r1), "=r"(r2), "=r"(r3) : "r"(addr))
#define MMA16816(d, a, b) \
    asm volatile("mma.sync.aligned.m16n8k16.row.col.f32.f16.f16.f32 " \
        "{%0,%1,%2,%3}, {%4,%5,%6,%7}, {%8,%9}, {%0,%1,%2,%3};" \
        : "+f"((d)[0]), "+f"((d)[1]), "+f"((d)[2]), "+f"((d)[3]) \
        : "r"((a)[0]), "r"((a)[1]), "r"((a)[2]), "r"((a)[3]), "r"((b)[0]), "r"((b)[1]))

// ---------------- misc helpers ----------------------------------------------
__device__ __forceinline__ float spu_f(float x) {
    if (x >= 0.f) return x * x - 0.5f;
    float s = 1.f / (1.f + expf(x));
    return s - 1.f;
}
__device__ __forceinline__ float dspu_f(float x) {
    if (x >= 0.f) return 2.f * x;
    float s = 1.f / (1.f + expf(x));
    return -s * (1.f - s);
}
__device__ __forceinline__ void spu_relax(float l, float u, float pl, float pu,
                                          float &w_, float &bl_, float &bu_) {
    float k1 = dspu_f(l), k2 = dspu_f(u);
    float klo = fminf(k1, k2), khi = fmaxf(k1, k2);
    float wl = fminf(fmaxf(pl, klo), khi);
    float wu = fminf(fmaxf(pu, klo), khi);
    float p0 = l, p1 = u, p2 = 0.5f * (l + u), p3 = fminf(fmaxf(0.f, l), u);
    float s0 = spu_f(p0), s1 = spu_f(p1), s2 = spu_f(p2), s3 = spu_f(p3);
    bl_ = fminf(fminf(s0 - wl * p0, s1 - wl * p1), fminf(s2 - wl * p2, s3 - wl * p3));
    bu_ = fmaxf(fmaxf(s0 - wu * p0, s1 - wu * p1), fmaxf(s2 - wu * p2, s3 - wu * p3));
    w_ = wl;
}
__device__ __forceinline__ void blk_reduce2(float &a, float &b) {
    const unsigned m = 0xffffffffu;
    #pragma unroll
    for (int o = 16; o > 0; o >>= 1) {
        a += __shfl_down_sync(m, a, o);
        b += __shfl_down_sync(m, b, o);
    }
    __shared__ float sa[16], sb[16];
    int w = threadIdx.x >> 5, l = threadIdx.x & 31;
    int nw = blockDim.x >> 5;
    if (l == 0) { sa[w] = a; sb[w] = b; }
    __syncthreads();
    if (w == 0) {
        a = (l < nw) ? sa[l] : 0.f;
        b = (l < nw) ? sb[l] : 0.f;
        #pragma unroll
        for (int o = 8; o > 0; o >>= 1) {
            a += __shfl_down_sync(m, a, o);
            b += __shfl_down_sync(m, b, o);
        }
    }
}

// ---------------- fused stage-1: concretize + SPU + stage-4 accumulator init --
__global__ void concretize_spu_k(const float* __restrict__ W1v,
                                 const float* __restrict__ lin, const float* __restrict__ uin,
                                 const float* __restrict__ b1v,
                                 const float* __restrict__ pl, const float* __restrict__ pu,
                                 float* __restrict__ w, float* __restrict__ bl,
                                 float* __restrict__ bu,
                                 float* __restrict__ bias4, float* __restrict__ out) {
    int row = blockIdx.x;
    if (row == 0 && threadIdx.x < OUTR) {   // zero stage-4 accumulators (runs first)
        bias4[threadIdx.x] = 0.f;
        out[threadIdx.x] = 0.f;
    }
    const float* a = W1v + (size_t)row * DIN;
    float al = 0.f, au = 0.f;
    for (int j = threadIdx.x * 4; j < DIN; j += blockDim.x * 4) {
        float4 v = *(const float4*)(a + j);
        float4 L = *(const float4*)(lin + j);
        float4 U = *(const float4*)(uin + j);
        float pA = fmaxf(v.x, 0.f), nA = fminf(v.x, 0.f);
        float pB = fmaxf(v.y, 0.f), nB = fminf(v.y, 0.f);
        float pC = fmaxf(v.z, 0.f), nC = fminf(v.z, 0.f);
        float pD = fmaxf(v.w, 0.f), nD = fminf(v.w, 0.f);
        al += pA * L.x + nA * U.x + pB * L.y + nB * U.y
            + pC * L.z + nC * U.z + pD * L.w + nD * U.w;
        au += pA * U.x + nA * L.x + pB * U.y + nB * L.y
            + pC * U.z + nC * L.z + pD * U.w + nD * L.w;
    }
    blk_reduce2(al, au);
    if (threadIdx.x == 0) {
        float l = al + b1v[row], u = au + b1v[row];
        float w_, bl_, bu_;
        spu_relax(l, u, pl[row], pu[row], w_, bl_, bu_);
        w[row] = w_; bl[row] = bl_; bu[row] = bu_;
    }
}

__global__ void spu_params_k(const float* __restrict__ lf, const float* __restrict__ uf,
                             const float* __restrict__ pl, const float* __restrict__ pu,
                             float* __restrict__ w, float* __restrict__ bl,
                             float* __restrict__ bu, int n) {
    int i = blockIdx.x * blockDim.x + threadIdx.x;
    if (i >= n) return;
    float w_, bl_, bu_;
    spu_relax(lf[i], uf[i], pl[i], pu[i], w_, bl_, bu_);
    w[i] = w_; bl[i] = bl_; bu[i] = bu_;
}

// bias + fp16 convert (hi only), 512 threads: one float4 iteration per row
__global__ __launch_bounds__(512)
void bias2conv_k(const float* __restrict__ W,
                 const float* __restrict__ wprev,
                 const float* __restrict__ blprev, const float* __restrict__ buprev,
                 const float* __restrict__ bthis, const float* __restrict__ bprev,
                 float* __restrict__ cl, float* __restrict__ cu,
                 __half* __restrict__ hi) {
    int row = blockIdx.x;
    const float* wr = W + (size_t)row * H;
    __half* hr = hi + (size_t)row * H;
    float al = 0.f, au = 0.f;
    int j = threadIdx.x * 4;
    {
        float4 v  = *(const float4*)(wr + j);
        float4 wp = *(const float4*)(wprev + j);
        float4 bp = *(const float4*)(bprev + j);
        float4 bL = *(const float4*)(blprev + j);
        float4 bU = *(const float4*)(buprev + j);
        float m0 = v.x * wp.x, m1 = v.y * wp.y, m2 = v.z * wp.z, m3 = v.w * wp.w;
        float sb = m0 * bp.x + m1 * bp.y + m2 * bp.z + m3 * bp.w;
        float pA = fmaxf(v.x, 0.f), nA = fminf(v.x, 0.f);
        float pB = fmaxf(v.y, 0.f), nB = fminf(v.y, 0.f);
        float pC = fmaxf(v.z, 0.f), nC = fminf(v.z, 0.f);
        float pD = fmaxf(v.w, 0.f), nD = fminf(v.w, 0.f);
        al += pA * bL.x + nA * bU.x + pB * bL.y + nB * bU.y
            + pC * bL.z + nC * bU.z + pD * bL.w + nD * bU.w + sb;
        au += pA * bU.x + nA * bL.x + pB * bU.y + nB * bL.y
            + pC * bU.z + nC * bL.z + pD * bU.w + nD * bL.w + sb;
        __half2 h0; h0.x = __float2half_rn(m0); h0.y = __float2half_rn(m1);
        __half2 h1; h1.x = __float2half_rn(m2); h1.y = __float2half_rn(m3);
        *(__half2*)(hr + j)     = h0;
        *(__half2*)(hr + j + 2) = h1;
    }
    blk_reduce2(al, au);
    if (threadIdx.x == 0) { cl[row] = bthis[row] + al; cu[row] = bthis[row] + au; }
}

// merged transpose+convert for W1/W2/W3 (blockIdx.z selects tensor)
__global__ void transp3_k(const float* __restrict__ W1v, const float* __restrict__ W2v,
                          const float* __restrict__ W3v,
                          __half* __restrict__ T1, __half* __restrict__ T2,
                          __half* __restrict__ T3) {
    const float* B;
    __half* thi;
    int N;
    if (blockIdx.z == 0)      { B = W1v; thi = T1; N = DIN; }
    else if (blockIdx.z == 1) { B = W2v; thi = T2; N = H; }
    else                      { B = W3v; thi = T3; N = H; }
    int k0 = blockIdx.x * 64, n0 = blockIdx.y * 32;
    if (n0 >= N) return;
    __shared__ float t[64][33];
    int x = threadIdx.x, y = threadIdx.y;       // 32 x 8
    #pragma unroll
    for (int yy = y; yy < 64; yy += 8) {
        int n = n0 + x;
        t[yy][x] = (n < N) ? B[(size_t)(k0 + yy) * N + n] : 0.f;
    }
    __syncthreads();
    #pragma unroll
    for (int nn = y; nn < 32; nn += 8) {
        int n = n0 + nn;
        if (n < N) {
            __half2 hv;
            hv.x = __float2half_rn(t[2 * x][nn]);
            hv.y = __float2half_rn(t[2 * x + 1][nn]);
            *(__half2*)(thi + (size_t)n * KTOT + k0 + 2 * x) = hv;
        }
    }
}

// ---------------- big GEMM: 128x128 tile, 1-product fp16, MODE-0 epilogue -----
__global__ __launch_bounds__(256, 2)
void gemm_mma_k(const __half* __restrict__ Ahi, const __half* __restrict__ Bhi,
                __half* __restrict__ Ohi,
                const float* __restrict__ scale, const float* __restrict__ bvec,
                const float* __restrict__ blv, const float* __restrict__ buv,
                float* __restrict__ cl, float* __restrict__ cu) {
    extern __shared__ char dsm[];
    uint32_t raw = smem_u32(dsm);
    uint32_t dbase = (raw + 1023) & ~1023u;

    int tid = threadIdx.x, wid = tid >> 5, lane = tid & 31;
    int brow = blockIdx.y * 128, bcol = blockIdx.x * 128;
    int wm = (wid >> 2) * 64, wn = (wid & 3) * 32;

    const __half* gbase[2] = { Ahi + (size_t)brow * KTOT, Bhi + (size_t)bcol * KTOT };
    const __half* gsrc[4];
    uint32_t sdst[4];
    #pragma unroll
    for (int i = 0; i < 4; i++) {
        int s = i * 256 + tid;
        int t = s >> 9, row = (s >> 2) & 127, sg = s & 3;
        gsrc[i] = gbase[t] + (size_t)row * KTOT + sg * 8;
        sdst[i] = (uint32_t)(t * TILEB) + SWZ64((uint32_t)(row * 64 + sg * 16));
    }

    float acc[4][4][4];
    #pragma unroll
    for (int mt = 0; mt < 4; mt++)
        #pragma unroll
        for (int nt = 0; nt < 4; nt++)
            #pragma unroll
            for (int q = 0; q < 4; q++) acc[mt][nt][q] = 0.f;

    int l15 = lane & 15, lhi = lane >> 4;

    #pragma unroll
    for (int st = 0; st < 2; st++) {
        uint32_t sb = dbase + st * STAGEB;
        int k0 = st * KC;
        #pragma unroll
        for (int i = 0; i < 4; i++) CP_ASYNC16(sb + sdst[i], gsrc[i] + k0);
        CP_COMMIT();
    }

    int stage = 0;
    for (int chunk = 0; chunk < NCHUNK; chunk++) {
        if (chunk + 1 < NCHUNK) CP_WAIT(1); else CP_WAIT(0);
        __syncthreads();
        if (chunk + 2 < NCHUNK) {
            int ns = stage + 2; if (ns >= NSTAGE) ns -= NSTAGE;
            uint32_t sb = dbase + ns * STAGEB;
            int k0 = (chunk + 2) * KC;
            #pragma unroll
            for (int i = 0; i < 4; i++) CP_ASYNC16(sb + sdst[i], gsrc[i] + k0);
            CP_COMMIT();
        }
        uint32_t ah_b = dbase + stage * STAGEB;
        uint32_t bh_b = ah_b + TILEB;
        #pragma unroll
        for (int kb = 0; kb < 2; kb++) {
            uint32_t kbyte = (uint32_t)(kb * 32 + lhi * 16);
            uint32_t ah_f[4][4];
            #pragma unroll
            for (int mt = 0; mt < 4; mt++) {
                uint32_t off = SWZ64((uint32_t)((wm + mt * 16 + l15) * 64) + kbyte);
                LDSM_X4(ah_f[mt][0], ah_f[mt][1], ah_f[mt][2], ah_f[mt][3], ah_b + off);
            }
            #pragma unroll
            for (int p = 0; p < 2; p++) {
                uint32_t off = SWZ64((uint32_t)((wn + p * 16 + l15) * 64) + kbyte);
                uint32_t r0, r1, r2, r3;
                uint32_t bhi0[2], bhi1[2];
                LDSM_X4(r0, r1, r2, r3, bh_b + off);
                bhi0[0] = r0; bhi0[1] = r2; bhi1[0] = r1; bhi1[1] = r3;
                #pragma unroll
                for (int mt = 0; mt < 4; mt++) {
                    MMA16816(acc[mt][2 * p], ah_f[mt], bhi0);
                    MMA16816(acc[mt][2 * p + 1], ah_f[mt], bhi1);
                }
            }
        }
        stage++; if (stage >= NSTAGE) stage -= NSTAGE;
    }

    #pragma unroll
    for (int mt = 0; mt < 4; mt++) {
        #pragma unroll
        for (int q = 0; q < 2; q++) {
            int gr = brow + wm + mt * 16 + (lane >> 2) + q * 8;
            float pl = 0.f, pu = 0.f;
            #pragma unroll
            for (int nt = 0; nt < 4; nt++) {
                int gc = bcol + wn + nt * 8 + (lane & 3) * 2;
                float v0 = acc[mt][nt][q * 2 + 0];
                float v1 = acc[mt][nt][q * 2 + 1];
                float m0 = v0 * scale[gc], m1 = v1 * scale[gc + 1];
                __half2 hv; hv.x = __float2half_rn(m0); hv.y = __float2half_rn(m1);
                *(__half2*)(Ohi + (size_t)gr * H + gc) = hv;
                float p0 = fmaxf(v0, 0.f), n0 = fminf(v0, 0.f);
                float p1 = fmaxf(v1, 0.f), n1 = fminf(v1, 0.f);
                float sb = m0 * bvec[gc] + m1 * bvec[gc + 1];
                pl += p0 * blv[gc] + n0 * buv[gc] + p1 * blv[gc + 1] + n1 * buv[gc + 1] + sb;
                pu += p0 * buv[gc] + n0 * blv[gc] + p1 * buv[gc + 1] + n1 * blv[gc + 1] + sb;
            }
            pl += __shfl_xor_sync(0xffffffffu, pl, 1);
            pl += __shfl_xor_sync(0xffffffffu, pl, 2);
            pu += __shfl_xor_sync(0xffffffffu, pu, 1);
            pu += __shfl_xor_sync(0xffffffffu, pu, 2);
            if ((lane & 3) == 0) {
                atomicAdd(&cl[gr], pl);
                atomicAdd(&cu[gr], pu);
            }
        }
    }
}

// ---------------- mid GEMM: 64x128 tile, 1-product fp16, concretize epilogue --
__global__ __launch_bounds__(256, 2)
void gemm_mid_mma_k(const __half* __restrict__ Ahi, const __half* __restrict__ Bhi,
                    float* __restrict__ cl, float* __restrict__ cu,
                    const float* __restrict__ lin, const float* __restrict__ uin) {
    extern __shared__ char dsm[];
    uint32_t raw = smem_u32(dsm);
    uint32_t dbase = (raw + 1023) & ~1023u;

    int tid = threadIdx.x, wid = tid >> 5, lane = tid & 31;
    int brow = blockIdx.y * 64, bcol = blockIdx.x * 128;
    int wm = (wid >> 2) * 32, wn = (wid & 3) * 32;

    const __half* gsrc[3];
    uint32_t sdst[3];
    #pragma unroll
    for (int i = 0; i < 3; i++) {
        int s = i * 256 + tid;
        int rowg = s >> 2, sg = s & 3;
        if (rowg < 64) {
            gsrc[i] = Ahi + (size_t)(brow + rowg) * KTOT + sg * 8;
            sdst[i] = SWZ64((uint32_t)(rowg * 64 + sg * 16));
        } else {
            int r = rowg - 64;
            gsrc[i] = Bhi + (size_t)(bcol + r) * KTOT + sg * 8;
            sdst[i] = (uint32_t)MTILEA + SWZ64((uint32_t)(r * 64 + sg * 16));
        }
    }

    float acc[2][4][4];
    #pragma unroll
    for (int mt = 0; mt < 2; mt++)
        #pragma unroll
        for (int nt = 0; nt < 4; nt++)
            #pragma unroll
            for (int q = 0; q < 4; q++) acc[mt][nt][q] = 0.f;

    int l15 = lane & 15, lhi = lane >> 4;

    #pragma unroll
    for (int st = 0; st < 2; st++) {
        uint32_t sb = dbase + st * MSTAGE;
        int k0 = st * KC;
        #pragma unroll
        for (int i = 0; i < 3; i++) CP_ASYNC16(sb + sdst[i], gsrc[i] + k0);
        CP_COMMIT();
    }

    int stage = 0;
    for (int chunk = 0; chunk < NCHUNK; chunk++) {
        if (chunk + 1 < NCHUNK) CP_WAIT(1); else CP_WAIT(0);
        __syncthreads();
        if (chunk + 2 < NCHUNK) {
            int ns = stage + 2; if (ns >= NSTAGE) ns -= NSTAGE;
            uint32_t sb = dbase + ns * MSTAGE;
            int k0 = (chunk + 2) * KC;
            #pragma unroll
            for (int i = 0; i < 3; i++) CP_ASYNC16(sb + sdst[i], gsrc[i] + k0);
            CP_COMMIT();
        }
        uint32_t ah_b = dbase + stage * MSTAGE;
        uint32_t bh_b = ah_b + MTILEA;
        #pragma unroll
        for (int kb = 0; kb < 2; kb++) {
            uint32_t kbyte = (uint32_t)(kb * 32 + lhi * 16);
            uint32_t ah_f[2][4];
            #pragma unroll
            for (int mt = 0; mt < 2; mt++) {
                uint32_t off = SWZ64((uint32_t)((wm + mt * 16 + l15) * 64) + kbyte);
                LDSM_X4(ah_f[mt][0], ah_f[mt][1], ah_f[mt][2], ah_f[mt][3], ah_b + off);
            }
            #pragma unroll
            for (int p = 0; p < 2; p++) {
                uint32_t off = SWZ64((uint32_t)((wn + p * 16 + l15) * 64) + kbyte);
                uint32_t r0, r1, r2, r3;
                uint32_t bhi0[2], bhi1[2];
                LDSM_X4(r0, r1, r2, r3, bh_b + off);
                bhi0[0] = r0; bhi0[1] = r2; bhi1[0] = r1; bhi1[1] = r3;
                #pragma unroll
                for (int mt = 0; mt < 2; mt++) {
                    MMA16816(acc[mt][2 * p], ah_f[mt], bhi0);
                    MMA16816(acc[mt][2 * p + 1], ah_f[mt], bhi1);
                }
            }
        }
        stage++; if (stage >= NSTAGE) stage -= NSTAGE;
    }

    #pragma unroll
    for (int mt = 0; mt < 2; mt++) {
        #pragma unroll
        for (int q = 0; q < 2; q++) {
            int gr = brow + wm + mt * 16 + (lane >> 2) + q * 8;
            float pl = 0.f, pu = 0.f;
            #pragma unroll
            for (int nt = 0; nt < 4; nt++) {
                int gc = bcol + wn + nt * 8 + (lane & 3) * 2;
                if (gc < DIN) {
                    float v0 = acc[mt][nt][q * 2 + 0];
                    float v1 = acc[mt][nt][q * 2 + 1];
                    float l0 = lin[gc], u0 = uin[gc];
                    float l1 = lin[gc + 1], u1 = uin[gc + 1];
                    float p0 = fmaxf(v0, 0.f), n0 = fminf(v0, 0.f);
                    float p1 = fmaxf(v1, 0.f), n1 = fminf(v1, 0.f);
                    pl += p0 * l0 + n0 * u0 + p1 * l1 + n1 * u1;
                    pu += p0 * u0 + n0 * l0 + p1 * u1 + n1 * l1;
                }
            }
            pl += __shfl_xor_sync(0xffffffffu, pl, 1);
            pl += __shfl_xor_sync(0xffffffffu, pl, 2);
            pu += __shfl_xor_sync(0xffffffffu, pu, 1);
            pu += __shfl_xor_sync(0xffffffffu, pu, 2);
            if ((lane & 3) == 0) {
                atomicAdd(&cl[gr], pl);
                atomicAdd(&cu[gr], pu);
            }
        }
    }
}

// grid 16*8 blocks of 256: r = blockIdx>>3, j0 = (blockIdx&7)*256
__global__ void build_m4conv_k(const float* __restrict__ W4, const int* __restrict__ tl,
                               const float* __restrict__ w3v, const float* __restrict__ bl3v,
                               const float* __restrict__ bu3v, const float* __restrict__ b3v,
                               __half* __restrict__ A0, float* __restrict__ bias4) {
    int t = *tl;
    int r = blockIdx.x >> 3;
    int j = (blockIdx.x & 7) * 256 + threadIdx.x;
    if (r >= OUTR) {                 // pad rows 9..15 stay zero
        A0[(size_t)r * KTOT + j] = __float2half_rn(0.f);
        return;
    }
    int c = (r < t) ? r : r + 1;
    float v = W4[(size_t)c * H + j] - W4[(size_t)t * H + j];
    float m = v * w3v[j];
    A0[(size_t)r * KTOT + j] = __float2half_rn(m);
    float au = fmaxf(v, 0.f) * bu3v[j] + fminf(v, 0.f) * bl3v[j] + m * b3v[j];
    float dummy = 0.f;
    blk_reduce2(au, dummy);
    if (threadIdx.x == 0) atomicAdd(&bias4[r], au);
}

// ---------------- stage-4 skinny GEMM: 16 x 64 tile ----------------------------
// MODE 0: m=v*scale[gc]; Aout=fp16(m); bias4[r] += pos(v)*buv+neg(v)*blv+m*bvec
// MODE 1: out[r] += pos(v)*uin[gc]+neg(v)*lin[gc]  (gc < DIN)
template <int MODE>
__global__ __launch_bounds__(128)
void gemm16_k(const __half* __restrict__ A, const __half* __restrict__ Bt,
              __half* __restrict__ Aout,
              const float* __restrict__ scale, const float* __restrict__ bvec,
              const float* __restrict__ blv, const float* __restrict__ buv,
              float* __restrict__ bias4,
              const float* __restrict__ lin, const float* __restrict__ uin,
              float* __restrict__ out) {
    extern __shared__ char dsm[];
    uint32_t raw = smem_u32(dsm);
    uint32_t dbase = (raw + 1023) & ~1023u;

    int tid = threadIdx.x, wid = tid >> 5, lane = tid & 31;
    int bcol = blockIdx.x * 64;
    int wn = wid * 16;

    // staging: 640 segs (A 16x8 + B 64x8), 5 per thread
    const __half* gsrc[5];
    uint32_t sdst[5];
    #pragma unroll
    for (int i = 0; i < 5; i++) {
        int s = i * 128 + tid;          // 0..639
        if (s < 128) {
            int row = s >> 3, sg = s & 7;
            gsrc[i] = A + (size_t)row * KTOT + sg * 8;
            sdst[i] = SWZ128((uint32_t)(row * 128 + sg * 16));
        } else {
            int ss = s - 128;
            int row = ss >> 3, sg = ss & 7;
            gsrc[i] = Bt + (size_t)(bcol + row) * KTOT + sg * 8;
            sdst[i] = (uint32_t)A16TILE + SWZ128((uint32_t)(row * 128 + sg * 16));
        }
    }

    float acc[2][4];
    #pragma unroll
    for (int nt = 0; nt < 2; nt++)
        #pragma unroll
        for (int q = 0; q < 4; q++) acc[nt][q] = 0.f;

    int l15 = lane & 15, lhi = lane >> 4;

    #pragma unroll
    for (int st = 0; st < 2; st++) {
        uint32_t sb = dbase + st * S16STAGE;
        int k0 = st * KC16;
        #pragma unroll
        for (int i = 0; i < 5; i++) CP_ASYNC16(sb + sdst[i], gsrc[i] + k0);
        CP_COMMIT();
    }

    int stage = 0;
    for (int chunk = 0; chunk < NCHUNK16; chunk++) {
        if (chunk + 1 < NCHUNK16) CP_WAIT(1); else CP_WAIT(0);
        __syncthreads();
        if (chunk + 2 < NCHUNK16) {
            int ns = stage + 2; if (ns >= NSTAGE) ns -= NSTAGE;
            uint32_t sb = dbase + ns * S16STAGE;
            int k0 = (chunk + 2) * KC16;
            #pragma unroll
            for (int i = 0; i < 5; i++) CP_ASYNC16(sb + sdst[i], gsrc[i] + k0);
            CP_COMMIT();
        }
        uint32_t a_b = dbase + stage * S16STAGE;
        uint32_t b_b = a_b + A16TILE;
        #pragma unroll
        for (int kb = 0; kb < 4; kb++) {
            uint32_t kbyte = (uint32_t)(kb * 32 + lhi * 16);
            uint32_t a_f[4];
            {
                uint32_t off = SWZ128((uint32_t)(l15 * 128) + kbyte);
                LDSM_X4(a_f[0], a_f[1], a_f[2], a_f[3], a_b + off);
            }
            uint32_t off = SWZ128((uint32_t)((wn + l15) * 128) + kbyte);
            uint32_t r0, r1, r2, r3;
            uint32_t bhi0[2], bhi1[2];
            LDSM_X4(r0, r1, r2, r3, b_b + off);
            bhi0[0] = r0; bhi0[1] = r2; bhi1[0] = r1; bhi1[1] = r3;
            MMA16816(acc[0], a_f, bhi0);
            MMA16816(acc[1], a_f, bhi1);
        }
        stage++; if (stage >= NSTAGE) stage -= NSTAGE;
    }

    // epilogue: rows r0 = lane>>2, r1 = r0 + 8
    int r0 = lane >> 2, r1 = r0 + 8;
    float s0 = 0.f, s1 = 0.f;
    #pragma unroll
    for (int nt = 0; nt < 2; nt++) {
        int gc = bcol + wn + nt * 8 + (lane & 3) * 2;
        float v0 = acc[nt][0], v1 = acc[nt][1];   // row r0
        float v2 = acc[nt][2], v3 = acc[nt][3];   // row r1
        if (MODE == 0) {
            float sc0 = scale[gc], sc1 = scale[gc + 1];
            float m0 = v0 * sc0, m1 = v1 * sc1;
            float m2 = v2 * sc0, m3 = v3 * sc1;
            __half2 h0; h0.x = __float2half_rn(m0); h0.y = __float2half_rn(m1);
            __half2 h1; h1.x = __float2half_rn(m2); h1.y = __float2half_rn(m3);
            *(__half2*)(Aout + (size_t)r0 * KTOT + gc) = h0;
            *(__half2*)(Aout + (size_t)r1 * KTOT + gc) = h1;
            float b0 = bvec[gc], b1 = bvec[gc + 1];
            float bl0 = blv[gc], bl1 = blv[gc + 1];
            float bu0 = buv[gc], bu1 = buv[gc + 1];
            s0 += fmaxf(v0, 0.f) * bu0 + fminf(v0, 0.f) * bl0 + m0 * b0
                + fmaxf(v1, 0.f) * bu1 + fminf(v1, 0.f) * bl1 + m1 * b1;
            s1 += fmaxf(v2, 0.f) * bu0 + fminf(v2, 0.f) * bl0 + m2 * b0
                + fmaxf(v3, 0.f) * bu1 + fminf(v3, 0.f) * bl1 + m3 * b1;
        } else {
            if (gc < DIN) {
                float l0 = lin[gc], u0 = uin[gc];
                float l1 = lin[gc + 1], u1 = uin[gc + 1];
                s0 += fmaxf(v0, 0.f) * u0 + fminf(v0, 0.f) * l0
                    + fmaxf(v1, 0.f) * u1 + fminf(v1, 0.f) * l1;
                s1 += fmaxf(v2, 0.f) * u0 + fminf(v2, 0.f) * l0
                    + fmaxf(v3, 0.f) * u1 + fminf(v3, 0.f) * l1;
            }
        }
    }
    s0 += __shfl_xor_sync(0xffffffffu, s0, 1);
    s0 += __shfl_xor_sync(0xffffffffu, s0, 2);
    s1 += __shfl_xor_sync(0xffffffffu, s1, 1);
    s1 += __shfl_xor_sync(0xffffffffu, s1, 2);
    if ((lane & 3) == 0) {
        if (MODE == 0) {
            if (r0 < OUTR) atomicAdd(&bias4[r0], s0);
            if (r1 < OUTR) atomicAdd(&bias4[r1], s1);
        } else {
            if (r0 < OUTR) atomicAdd(&out[r0], s0);
            if (r1 < OUTR) atomicAdd(&out[r1], s1);
        }
    }
}

__global__ void final_add_k(const float* __restrict__ bias4,
                            const float* __restrict__ b4, const int* __restrict__ tl,
                            float* __restrict__ out) {
    int t = *tl;
    int r = threadIdx.x;
    if (r < OUTR) {
        int c = (r < t) ? r : r + 1;
        out[r] += bias4[r] + b4[c] - b4[t];
    }
}

// ---------------- launch ------------------------------------------------------
extern "C" void kernel_launch(void* const* d_in, const int* in_sizes, int n_in,
                              void* d_out, int out_size) {
    const float* W1 = (const float*)d_in[0];
    const float* b1 = (const float*)d_in[1];
    const float* W2 = (const float*)d_in[2];
    const float* b2 = (const float*)d_in[3];
    const float* W3 = (const float*)d_in[4];
    const float* b3 = (const float*)d_in[5];
    const float* W4 = (const float*)d_in[6];
    const float* b4 = (const float*)d_in[7];
    const float* l_in = (const float*)d_in[8];
    const float* u_in = (const float*)d_in[9];
    const float* p_l1 = (const float*)d_in[10];
    const float* p_u1 = (const float*)d_in[11];
    const float* p_l2 = (const float*)d_in[12];
    const float* p_u2 = (const float*)d_in[13];
    const float* p_l3 = (const float*)d_in[14];
    const float* p_u3 = (const float*)d_in[15];
    const int* tl = (const int*)d_in[16];
    float* out = (float*)d_out;

    cudaFuncSetAttribute(gemm_mma_k, cudaFuncAttributeMaxDynamicSharedMemorySize, DSMEM);
    cudaFuncSetAttribute(gemm_mid_mma_k, cudaFuncAttributeMaxDynamicSharedMemorySize, MDSMEM);
    cudaFuncSetAttribute(gemm16_k<0>, cudaFuncAttributeMaxDynamicSharedMemorySize, DSMEM16);
    cudaFuncSetAttribute(gemm16_k<1>, cudaFuncAttributeMaxDynamicSharedMemorySize, DSMEM16);

    float *T, *w1, *bl1, *bu1, *w2, *bl2, *bu2, *w3, *bl3, *bu3, *cl, *cu, *bias4;
    __half *Ahi, *W1th, *W2th, *W3th, *s4a, *s4b;
    cudaGetSymbolAddress((void**)&T, g_T);
    cudaGetSymbolAddress((void**)&Ahi, g_Ahi);
    cudaGetSymbolAddress((void**)&W1th, g_W1t_hi);
    cudaGetSymbolAddress((void**)&W2th, g_W2t_hi);
    cudaGetSymbolAddress((void**)&W3th, g_W3t_hi);
    cudaGetSymbolAddress((void**)&s4a, g_s4a);  cudaGetSymbolAddress((void**)&s4b, g_s4b);
    cudaGetSymbolAddress((void**)&w1, g_w1);   cudaGetSymbolAddress((void**)&bl1, g_bl1);
    cudaGetSymbolAddress((void**)&bu1, g_bu1);
    cudaGetSymbolAddress((void**)&w2, g_w2);   cudaGetSymbolAddress((void**)&bl2, g_bl2);
    cudaGetSymbolAddress((void**)&bu2, g_bu2);
    cudaGetSymbolAddress((void**)&w3, g_w3);   cudaGetSymbolAddress((void**)&bl3, g_bl3);
    cudaGetSymbolAddress((void**)&bu3, g_bu3);
    cudaGetSymbolAddress((void**)&cl, g_cl);   cudaGetSymbolAddress((void**)&cu, g_cu);
    cudaGetSymbolAddress((void**)&bias4, g_bias4);

    __half* Thi = (__half*)T;

    // upfront: merged transpose (W1/W2/W3 -> fp16 [N x K])
    transp3_k<<<dim3(KTOT / 64, H / 32, 3), dim3(32, 8)>>>(W1, W2, W3, W1th, W2th, W3th);

    dim3 gmid(NPAD1 / 128, H / 64);          // 7 x 32
    dim3 gbig(H / 128, H / 128);             // 16 x 16

    // ---- stage 1 (fused concretize + spu + stage-4 accumulator init) ----
    concretize_spu_k<<<H, 256>>>(W1, l_in, u_in, b1, p_l1, p_u1, w1, bl1, bu1, bias4, out);

    // ---- stage 2 ----
    bias2conv_k<<<H, 512>>>(W2, w1, bl1, bu1, b2, b1, cl, cu, Ahi);
    gemm_mid_mma_k<<<gmid, 256, MDSMEM>>>(Ahi, W1th, cl, cu, l_in, u_in);
    spu_params_k<<<(H + 63) / 64, 64>>>(cl, cu, p_l2, p_u2, w2, bl2, bu2, H);

    // ---- stage 3 ----
    bias2conv_k<<<H, 512>>>(W3, w2, bl2, bu2, b3, b2, cl, cu, Ahi);
    gemm_mma_k<<<gbig, 256, DSMEM>>>(Ahi, W2th, Thi, w1, b1, bl1, bu1, cl, cu);
    gemm_mid_mma_k<<<gmid, 256, MDSMEM>>>(Thi, W1th, cl, cu, l_in, u_in);
    spu_params_k<<<(H + 63) / 64, 64>>>(cl, cu, p_l3, p_u3, w3, bl3, bu3, H);

    // ---- stage 4: tensor-core chain, fused bias epilogues ----
    build_m4conv_k<<<16 * 8, 256>>>(W4, tl, w3, bl3, bu3, b3, s4a, bias4);
    gemm16_k<0><<<H / 64, 128, DSMEM16>>>(s4a, W3th, s4b,
                                          w2, b2, bl2, bu2, bias4, nullptr, nullptr, nullptr);
    gemm16_k<0><<<H / 64, 128, DSMEM16>>>(s4b, W2th, s4a,
                                          w1, b1, bl1, bu1, bias4, nullptr, nullptr, nullptr);
    gemm16_k<1><<<NPAD1 / 64, 128, DSMEM16>>>(s4a, W1th, nullptr,
                                              nullptr, nullptr, nullptr, nullptr, nullptr,
                                              l_in, u_in, out);
    final_add_k<<<1, 32>>>(bias4, b4, tl, out);
}

// round 16
// speedup vs baseline: 3.6980x; 1.0746x over previous
#include <cuda_runtime.h>
#include <cuda_fp16.h>
#include <math.h>
#include <stdint.h>

#define H     2048
#define DIN   784
#define OUTR  9
#define KTOT  2048
#define KC    64
#define NCHUNK (KTOT / KC)          // 32
#define TILEB  16384                // 128 rows * 128B
#define STAGEB (2 * TILEB)          // 32KB: Ahi, Bhi
#define NSTAGE 3
#define DSMEM  (NSTAGE * STAGEB + 1024)
// mid-GEMM (64x128 tile)
#define MTILEA 8192                 // 64 rows * 128B
#define MTILEB 16384                // 128 rows * 128B
#define MSTAGE (MTILEA + MTILEB)    // 24KB
#define MDSMEM (NSTAGE * MSTAGE + 1024)
// stage-4 skinny GEMM (16 x 64 tile, KC16 = 64, 128B rows)
#define KC16    64
#define NCHUNK16 (KTOT / KC16)      // 32
#define A16TILE (16 * 128)          // 2KB
#define B16TILE (64 * 128)          // 8KB
#define S16STAGE (A16TILE + B16TILE)
#define DSMEM16 (NSTAGE * S16STAGE + 1024)
#define NPAD1  896

// ---------------- scratch (device globals) ----------------------------------
__device__ float g_T[H * H];        // reused as half[H*H] for stage-3 Thi
__device__ __half g_Ahi[H * H];
__device__ __half g_W1t_hi[NPAD1 * KTOT];   // pad rows stay 0
__device__ __half g_W2t_hi[H * KTOT];
__device__ __half g_W3t_hi[H * KTOT];
__device__ __half g_s4a[16 * KTOT], g_s4b[16 * KTOT];
__device__ float g_w1[H], g_bl1[H], g_bu1[H];
__device__ float g_w2[H], g_bl2[H], g_bu2[H];
__device__ float g_w3[H], g_bl3[H], g_bu3[H];
__device__ float g_cl[H], g_cu[H];
__device__ float g_bias4[OUTR];

// ---------------- PTX helpers ------------------------------------------------
__device__ __forceinline__ uint32_t smem_u32(const void* p) {
    uint32_t a;
    asm("{ .reg .u64 t; cvta.to.shared.u64 t, %1; cvt.u32.u64 %0, t; }" : "=r"(a) : "l"(p));
    return a;
}
#define SWZ128(o)  ((o) ^ (((o) >> 3) & 0x70))
#define CP_ASYNC16(dst, gsrc) \
    asm volatile("cp.async.cg.shared.global [%0], [%1], 16;" :: "r"(dst), "l"(gsrc))
#define CP_COMMIT() asm volatile("cp.async.commit_group;" ::: "memory")
#define CP_WAIT(n)  asm volatile("cp.async.wait_group %0;" :: "n"(n) : "memory")
#define LDSM_X4(r0, r1, r2, r3, addr) \
    asm volatile("ldmatrix.sync.aligned.m8n8.x4.shared.b16 {%0,%1,%2,%3}, [%4];" \
        : "=r"(r0), "=r"(r1), "=r"(r2), "=r"(r3) : "r"(addr))
#define MMA16816(d, a, b) \
    asm volatile("mma.sync.aligned.m16n8k16.row.col.f32.f16.f16.f32 " \
        "{%0,%1,%2,%3}, {%4,%5,%6,%7}, {%8,%9}, {%0,%1,%2,%3};" \
        : "+f"((d)[0]), "+f"((d)[1]), "+f"((d)[2]), "+f"((d)[3]) \
        : "r"((a)[0]), "r"((a)[1]), "r"((a)[2]), "r"((a)[3]), "r"((b)[0]), "r"((b)[1]))

// ---------------- misc helpers ----------------------------------------------
__device__ __forceinline__ float spu_f(float x) {
    if (x >= 0.f) return x * x - 0.5f;
    float s = 1.f / (1.f + expf(x));
    return s - 1.f;
}
__device__ __forceinline__ float dspu_f(float x) {
    if (x >= 0.f) return 2.f * x;
    float s = 1.f / (1.f + expf(x));
    return -s * (1.f - s);
}
__device__ __forceinline__ void spu_relax(float l, float u, float pl, float pu,
                                          float &w_, float &bl_, float &bu_) {
    float k1 = dspu_f(l), k2 = dspu_f(u);
    float klo = fminf(k1, k2), khi = fmaxf(k1, k2);
    float wl = fminf(fmaxf(pl, klo), khi);
    float wu = fminf(fmaxf(pu, klo), khi);
    float p0 = l, p1 = u, p2 = 0.5f * (l + u), p3 = fminf(fmaxf(0.f, l), u);
    float s0 = spu_f(p0), s1 = spu_f(p1), s2 = spu_f(p2), s3 = spu_f(p3);
    bl_ = fminf(fminf(s0 - wl * p0, s1 - wl * p1), fminf(s2 - wl * p2, s3 - wl * p3));
    bu_ = fmaxf(fmaxf(s0 - wu * p0, s1 - wu * p1), fmaxf(s2 - wu * p2, s3 - wu * p3));
    w_ = wl;
}
__device__ __forceinline__ void blk_reduce2(float &a, float &b) {
    const unsigned m = 0xffffffffu;
    #pragma unroll
    for (int o = 16; o > 0; o >>= 1) {
        a += __shfl_down_sync(m, a, o);
        b += __shfl_down_sync(m, b, o);
    }
    __shared__ float sa[16], sb[16];
    int w = threadIdx.x >> 5, l = threadIdx.x & 31;
    int nw = blockDim.x >> 5;
    if (l == 0) { sa[w] = a; sb[w] = b; }
    __syncthreads();
    if (w == 0) {
        a = (l < nw) ? sa[l] : 0.f;
        b = (l < nw) ? sb[l] : 0.f;
        #pragma unroll
        for (int o = 8; o > 0; o >>= 1) {
            a += __shfl_down_sync(m, a, o);
            b += __shfl_down_sync(m, b, o);
        }
    }
}

// ---------------- fused stage-1: concretize + SPU + stage-4 accumulator init --
__global__ void concretize_spu_k(const float* __restrict__ W1v,
                                 const float* __restrict__ lin, const float* __restrict__ uin,
                                 const float* __restrict__ b1v,
                                 const float* __restrict__ pl, const float* __restrict__ pu,
                                 float* __restrict__ w, float* __restrict__ bl,
                                 float* __restrict__ bu,
                                 float* __restrict__ bias4, float* __restrict__ out) {
    int row = blockIdx.x;
    if (row == 0 && threadIdx.x < OUTR) {
        bias4[threadIdx.x] = 0.f;
        out[threadIdx.x] = 0.f;
    }
    const float* a = W1v + (size_t)row * DIN;
    float al = 0.f, au = 0.f;
    for (int j = threadIdx.x * 4; j < DIN; j += blockDim.x * 4) {
        float4 v = *(const float4*)(a + j);
        float4 L = *(const float4*)(lin + j);
        float4 U = *(const float4*)(uin + j);
        float pA = fmaxf(v.x, 0.f), nA = fminf(v.x, 0.f);
        float pB = fmaxf(v.y, 0.f), nB = fminf(v.y, 0.f);
        float pC = fmaxf(v.z, 0.f), nC = fminf(v.z, 0.f);
        float pD = fmaxf(v.w, 0.f), nD = fminf(v.w, 0.f);
        al += pA * L.x + nA * U.x + pB * L.y + nB * U.y
            + pC * L.z + nC * U.z + pD * L.w + nD * U.w;
        au += pA * U.x + nA * L.x + pB * U.y + nB * L.y
            + pC * U.z + nC * L.z + pD * U.w + nD * L.w;
    }
    blk_reduce2(al, au);
    if (threadIdx.x == 0) {
        float l = al + b1v[row], u = au + b1v[row];
        float w_, bl_, bu_;
        spu_relax(l, u, pl[row], pu[row], w_, bl_, bu_);
        w[row] = w_; bl[row] = bl_; bu[row] = bu_;
    }
}

__global__ void spu_params_k(const float* __restrict__ lf, const float* __restrict__ uf,
                             const float* __restrict__ pl, const float* __restrict__ pu,
                             float* __restrict__ w, float* __restrict__ bl,
                             float* __restrict__ bu, int n) {
    int i = blockIdx.x * blockDim.x + threadIdx.x;
    if (i >= n) return;
    float w_, bl_, bu_;
    spu_relax(lf[i], uf[i], pl[i], pu[i], w_, bl_, bu_);
    w[i] = w_; bl[i] = bl_; bu[i] = bu_;
}

// bias + fp16 convert (hi only), 512 threads: one float4 iteration per row
__global__ __launch_bounds__(512)
void bias2conv_k(const float* __restrict__ W,
                 const float* __restrict__ wprev,
                 const float* __restrict__ blprev, const float* __restrict__ buprev,
                 const float* __restrict__ bthis, const float* __restrict__ bprev,
                 float* __restrict__ cl, float* __restrict__ cu,
                 __half* __restrict__ hi) {
    int row = blockIdx.x;
    const float* wr = W + (size_t)row * H;
    __half* hr = hi + (size_t)row * H;
    float al = 0.f, au = 0.f;
    int j = threadIdx.x * 4;
    {
        float4 v  = *(const float4*)(wr + j);
        float4 wp = *(const float4*)(wprev + j);
        float4 bp = *(const float4*)(bprev + j);
        float4 bL = *(const float4*)(blprev + j);
        float4 bU = *(const float4*)(buprev + j);
        float m0 = v.x * wp.x, m1 = v.y * wp.y, m2 = v.z * wp.z, m3 = v.w * wp.w;
        float sb = m0 * bp.x + m1 * bp.y + m2 * bp.z + m3 * bp.w;
        float pA = fmaxf(v.x, 0.f), nA = fminf(v.x, 0.f);
        float pB = fmaxf(v.y, 0.f), nB = fminf(v.y, 0.f);
        float pC = fmaxf(v.z, 0.f), nC = fminf(v.z, 0.f);
        float pD = fmaxf(v.w, 0.f), nD = fminf(v.w, 0.f);
        al += pA * bL.x + nA * bU.x + pB * bL.y + nB * bU.y
            + pC * bL.z + nC * bU.z + pD * bL.w + nD * bU.w + sb;
        au += pA * bU.x + nA * bL.x + pB * bU.y + nB * bL.y
            + pC * bU.z + nC * bL.z + pD * bU.w + nD * bL.w + sb;
        __half2 h0; h0.x = __float2half_rn(m0); h0.y = __float2half_rn(m1);
        __half2 h1; h1.x = __float2half_rn(m2); h1.y = __float2half_rn(m3);
        *(__half2*)(hr + j)     = h0;
        *(__half2*)(hr + j + 2) = h1;
    }
    blk_reduce2(al, au);
    if (threadIdx.x == 0) { cl[row] = bthis[row] + al; cu[row] = bthis[row] + au; }
}

// merged transpose+convert for W1/W2/W3 (blockIdx.z selects tensor)
__global__ void transp3_k(const float* __restrict__ W1v, const float* __restrict__ W2v,
                          const float* __restrict__ W3v,
                          __half* __restrict__ T1, __half* __restrict__ T2,
                          __half* __restrict__ T3) {
    const float* B;
    __half* thi;
    int N;
    if (blockIdx.z == 0)      { B = W1v; thi = T1; N = DIN; }
    else if (blockIdx.z == 1) { B = W2v; thi = T2; N = H; }
    else                      { B = W3v; thi = T3; N = H; }
    int k0 = blockIdx.x * 64, n0 = blockIdx.y * 32;
    if (n0 >= N) return;
    __shared__ float t[64][33];
    int x = threadIdx.x, y = threadIdx.y;       // 32 x 8
    #pragma unroll
    for (int yy = y; yy < 64; yy += 8) {
        int n = n0 + x;
        t[yy][x] = (n < N) ? B[(size_t)(k0 + yy) * N + n] : 0.f;
    }
    __syncthreads();
    #pragma unroll
    for (int nn = y; nn < 32; nn += 8) {
        int n = n0 + nn;
        if (n < N) {
            __half2 hv;
            hv.x = __float2half_rn(t[2 * x][nn]);
            hv.y = __float2half_rn(t[2 * x + 1][nn]);
            *(__half2*)(thi + (size_t)n * KTOT + k0 + 2 * x) = hv;
        }
    }
}

// ---------------- big GEMM: 128x128 tile, KC=64, MODE-0 epilogue --------------
__global__ __launch_bounds__(256, 2)
void gemm_mma_k(const __half* __restrict__ Ahi, const __half* __restrict__ Bhi,
                __half* __restrict__ Ohi,
                const float* __restrict__ scale, const float* __restrict__ bvec,
                const float* __restrict__ blv, const float* __restrict__ buv,
                float* __restrict__ cl, float* __restrict__ cu) {
    extern __shared__ char dsm[];
    uint32_t raw = smem_u32(dsm);
    uint32_t dbase = (raw + 1023) & ~1023u;

    int tid = threadIdx.x, wid = tid >> 5, lane = tid & 31;
    int brow = blockIdx.y * 128, bcol = blockIdx.x * 128;
    int wm = (wid >> 2) * 64, wn = (wid & 3) * 32;

    const __half* gbase[2] = { Ahi + (size_t)brow * KTOT, Bhi + (size_t)bcol * KTOT };
    const __half* gsrc[8];
    uint32_t sdst[8];
    #pragma unroll
    for (int i = 0; i < 8; i++) {
        int s = i * 256 + tid;                 // 0..2047
        int t = s >> 10, row = (s >> 3) & 127, sg = s & 7;
        gsrc[i] = gbase[t] + (size_t)row * KTOT + sg * 8;
        sdst[i] = (uint32_t)(t * TILEB) + SWZ128((uint32_t)(row * 128 + sg * 16));
    }

    float acc[4][4][4];
    #pragma unroll
    for (int mt = 0; mt < 4; mt++)
        #pragma unroll
        for (int nt = 0; nt < 4; nt++)
            #pragma unroll
            for (int q = 0; q < 4; q++) acc[mt][nt][q] = 0.f;

    int l15 = lane & 15, lhi = lane >> 4;

    #pragma unroll
    for (int st = 0; st < 2; st++) {
        uint32_t sb = dbase + st * STAGEB;
        int k0 = st * KC;
        #pragma unroll
        for (int i = 0; i < 8; i++) CP_ASYNC16(sb + sdst[i], gsrc[i] + k0);
        CP_COMMIT();
    }

    int stage = 0;
    for (int chunk = 0; chunk < NCHUNK; chunk++) {
        if (chunk + 1 < NCHUNK) CP_WAIT(1); else CP_WAIT(0);
        __syncthreads();
        if (chunk + 2 < NCHUNK) {
            int ns = stage + 2; if (ns >= NSTAGE) ns -= NSTAGE;
            uint32_t sb = dbase + ns * STAGEB;
            int k0 = (chunk + 2) * KC;
            #pragma unroll
            for (int i = 0; i < 8; i++) CP_ASYNC16(sb + sdst[i], gsrc[i] + k0);
            CP_COMMIT();
        }
        uint32_t ah_b = dbase + stage * STAGEB;
        uint32_t bh_b = ah_b + TILEB;
        #pragma unroll
        for (int kb = 0; kb < 4; kb++) {
            uint32_t kbyte = (uint32_t)(kb * 32 + lhi * 16);
            uint32_t ah_f[4][4];
            #pragma unroll
            for (int mt = 0; mt < 4; mt++) {
                uint32_t off = SWZ128((uint32_t)((wm + mt * 16 + l15) * 128) + kbyte);
                LDSM_X4(ah_f[mt][0], ah_f[mt][1], ah_f[mt][2], ah_f[mt][3], ah_b + off);
            }
            #pragma unroll
            for (int p = 0; p < 2; p++) {
                uint32_t off = SWZ128((uint32_t)((wn + p * 16 + l15) * 128) + kbyte);
                uint32_t r0, r1, r2, r3;
                uint32_t bhi0[2], bhi1[2];
                LDSM_X4(r0, r1, r2, r3, bh_b + off);
                bhi0[0] = r0; bhi0[1] = r2; bhi1[0] = r1; bhi1[1] = r3;
                #pragma unroll
                for (int mt = 0; mt < 4; mt++) {
                    MMA16816(acc[mt][2 * p], ah_f[mt], bhi0);
                    MMA16816(acc[mt][2 * p + 1], ah_f[mt], bhi1);
                }
            }
        }
        stage++; if (stage >= NSTAGE) stage -= NSTAGE;
    }

    #pragma unroll
    for (int mt = 0; mt < 4; mt++) {
        #pragma unroll
        for (int q = 0; q < 2; q++) {
            int gr = brow + wm + mt * 16 + (lane >> 2) + q * 8;
            float pl = 0.f, pu = 0.f;
            #pragma unroll
            for (int nt = 0; nt < 4; nt++) {
                int gc = bcol + wn + nt * 8 + (lane & 3) * 2;
                float v0 = acc[mt][nt][q * 2 + 0];
                float v1 = acc[mt][nt][q * 2 + 1];
                float m0 = v0 * scale[gc], m1 = v1 * scale[gc + 1];
                __half2 hv; hv.x = __float2half_rn(m0); hv.y = __float2half_rn(m1);
                *(__half2*)(Ohi + (size_t)gr * H + gc) = hv;
                float p0 = fmaxf(v0, 0.f), n0 = fminf(v0, 0.f);
                float p1 = fmaxf(v1, 0.f), n1 = fminf(v1, 0.f);
                float sb = m0 * bvec[gc] + m1 * bvec[gc + 1];
                pl += p0 * blv[gc] + n0 * buv[gc] + p1 * blv[gc + 1] + n1 * buv[gc + 1] + sb;
                pu += p0 * buv[gc] + n0 * blv[gc] + p1 * buv[gc + 1] + n1 * blv[gc + 1] + sb;
            }
            pl += __shfl_xor_sync(0xffffffffu, pl, 1);
            pl += __shfl_xor_sync(0xffffffffu, pl, 2);
            pu += __shfl_xor_sync(0xffffffffu, pu, 1);
            pu += __shfl_xor_sync(0xffffffffu, pu, 2);
            if ((lane & 3) == 0) {
                atomicAdd(&cl[gr], pl);
                atomicAdd(&cu[gr], pu);
            }
        }
    }
}

// ---------------- mid GEMM: 64x128 tile, KC=64, concretize epilogue -----------
__global__ __launch_bounds__(256, 2)
void gemm_mid_mma_k(const __half* __restrict__ Ahi, const __half* __restrict__ Bhi,
                    float* __restrict__ cl, float* __restrict__ cu,
                    const float* __restrict__ lin, const float* __restrict__ uin) {
    extern __shared__ char dsm[];
    uint32_t raw = smem_u32(dsm);
    uint32_t dbase = (raw + 1023) & ~1023u;

    int tid = threadIdx.x, wid = tid >> 5, lane = tid & 31;
    int brow = blockIdx.y * 64, bcol = blockIdx.x * 128;
    int wm = (wid >> 2) * 32, wn = (wid & 3) * 32;

    // staging per chunk: A 64 rows x 8 segs + B 128 rows x 8 segs = 1536, 6/thread
    const __half* gsrc[6];
    uint32_t sdst[6];
    #pragma unroll
    for (int i = 0; i < 6; i++) {
        int s = i * 256 + tid;          // 0..1535
        int rowg = s >> 3, sg = s & 7;
        if (rowg < 64) {
            gsrc[i] = Ahi + (size_t)(brow + rowg) * KTOT + sg * 8;
            sdst[i] = SWZ128((uint32_t)(rowg * 128 + sg * 16));
        } else {
            int r = rowg - 64;
            gsrc[i] = Bhi + (size_t)(bcol + r) * KTOT + sg * 8;
            sdst[i] = (uint32_t)MTILEA + SWZ128((uint32_t)(r * 128 + sg * 16));
        }
    }

    float acc[2][4][4];
    #pragma unroll
    for (int mt = 0; mt < 2; mt++)
        #pragma unroll
        for (int nt = 0; nt < 4; nt++)
            #pragma unroll
            for (int q = 0; q < 4; q++) acc[mt][nt][q] = 0.f;

    int l15 = lane & 15, lhi = lane >> 4;

    #pragma unroll
    for (int st = 0; st < 2; st++) {
        uint32_t sb = dbase + st * MSTAGE;
        int k0 = st * KC;
        #pragma unroll
        for (int i = 0; i < 6; i++) CP_ASYNC16(sb + sdst[i], gsrc[i] + k0);
        CP_COMMIT();
    }

    int stage = 0;
    for (int chunk = 0; chunk < NCHUNK; chunk++) {
        if (chunk + 1 < NCHUNK) CP_WAIT(1); else CP_WAIT(0);
        __syncthreads();
        if (chunk + 2 < NCHUNK) {
            int ns = stage + 2; if (ns >= NSTAGE) ns -= NSTAGE;
            uint32_t sb = dbase + ns * MSTAGE;
            int k0 = (chunk + 2) * KC;
            #pragma unroll
            for (int i = 0; i < 6; i++) CP_ASYNC16(sb + sdst[i], gsrc[i] + k0);
            CP_COMMIT();
        }
        uint32_t ah_b = dbase + stage * MSTAGE;
        uint32_t bh_b = ah_b + MTILEA;
        #pragma unroll
        for (int kb = 0; kb < 4; kb++) {
            uint32_t kbyte = (uint32_t)(kb * 32 + lhi * 16);
            uint32_t ah_f[2][4];
            #pragma unroll
            for (int mt = 0; mt < 2; mt++) {
                uint32_t off = SWZ128((uint32_t)((wm + mt * 16 + l15) * 128) + kbyte);
                LDSM_X4(ah_f[mt][0], ah_f[mt][1], ah_f[mt][2], ah_f[mt][3], ah_b + off);
            }
            #pragma unroll
            for (int p = 0; p < 2; p++) {
                uint32_t off = SWZ128((uint32_t)((wn + p * 16 + l15) * 128) + kbyte);
                uint32_t r0, r1, r2, r3;
                uint32_t bhi0[2], bhi1[2];
                LDSM_X4(r0, r1, r2, r3, bh_b + off);
                bhi0[0] = r0; bhi0[1] = r2; bhi1[0] = r1; bhi1[1] = r3;
                #pragma unroll
                for (int mt = 0; mt < 2; mt++) {
                    MMA16816(acc[mt][2 * p], ah_f[mt], bhi0);
                    MMA16816(acc[mt][2 * p + 1], ah_f[mt], bhi1);
                }
            }
        }
        stage++; if (stage >= NSTAGE) stage -= NSTAGE;
    }

    #pragma unroll
    for (int mt = 0; mt < 2; mt++) {
        #pragma unroll
        for (int q = 0; q < 2; q++) {
            int gr = brow + wm + mt * 16 + (lane >> 2) + q * 8;
            float pl = 0.f, pu = 0.f;
            #pragma unroll
            for (int nt = 0; nt < 4; nt++) {
                int gc = bcol + wn + nt * 8 + (lane & 3) * 2;
                if (gc < DIN) {
                    float v0 = acc[mt][nt][q * 2 + 0];
                    float v1 = acc[mt][nt][q * 2 + 1];
                    float l0 = lin[gc], u0 = uin[gc];
                    float l1 = lin[gc + 1], u1 = uin[gc + 1];
                    float p0 = fmaxf(v0, 0.f), n0 = fminf(v0, 0.f);
                    float p1 = fmaxf(v1, 0.f), n1 = fminf(v1, 0.f);
                    pl += p0 * l0 + n0 * u0 + p1 * l1 + n1 * u1;
                    pu += p0 * u0 + n0 * l0 + p1 * u1 + n1 * l1;
                }
            }
            pl += __shfl_xor_sync(0xffffffffu, pl, 1);
            pl += __shfl_xor_sync(0xffffffffu, pl, 2);
            pu += __shfl_xor_sync(0xffffffffu, pu, 1);
            pu += __shfl_xor_sync(0xffffffffu, pu, 2);
            if ((lane & 3) == 0) {
                atomicAdd(&cl[gr], pl);
                atomicAdd(&cu[gr], pu);
            }
        }
    }
}

// grid 16*8 blocks of 256: r = blockIdx>>3, j0 = (blockIdx&7)*256
__global__ void build_m4conv_k(const float* __restrict__ W4, const int* __restrict__ tl,
                               const float* __restrict__ w3v, const float* __restrict__ bl3v,
                               const float* __restrict__ bu3v, const float* __restrict__ b3v,
                               __half* __restrict__ A0, float* __restrict__ bias4) {
    int t = *tl;
    int r = blockIdx.x >> 3;
    int j = (blockIdx.x & 7) * 256 + threadIdx.x;
    if (r >= OUTR) {
        A0[(size_t)r * KTOT + j] = __float2half_rn(0.f);
        return;
    }
    int c = (r < t) ? r : r + 1;
    float v = W4[(size_t)c * H + j] - W4[(size_t)t * H + j];
    float m = v * w3v[j];
    A0[(size_t)r * KTOT + j] = __float2half_rn(m);
    float au = fmaxf(v, 0.f) * bu3v[j] + fminf(v, 0.f) * bl3v[j] + m * b3v[j];
    float dummy = 0.f;
    blk_reduce2(au, dummy);
    if (threadIdx.x == 0) atomicAdd(&bias4[r], au);
}

// ---------------- stage-4 skinny GEMM: 16 x 64 tile ----------------------------
template <int MODE>
__global__ __launch_bounds__(128)
void gemm16_k(const __half* __restrict__ A, const __half* __restrict__ Bt,
              __half* __restrict__ Aout,
              const float* __restrict__ scale, const float* __restrict__ bvec,
              const float* __restrict__ blv, const float* __restrict__ buv,
              float* __restrict__ bias4,
              const float* __restrict__ lin, const float* __restrict__ uin,
              float* __restrict__ out) {
    extern __shared__ char dsm[];
    uint32_t raw = smem_u32(dsm);
    uint32_t dbase = (raw + 1023) & ~1023u;

    int tid = threadIdx.x, wid = tid >> 5, lane = tid & 31;
    int bcol = blockIdx.x * 64;
    int wn = wid * 16;

    const __half* gsrc[5];
    uint32_t sdst[5];
    #pragma unroll
    for (int i = 0; i < 5; i++) {
        int s = i * 128 + tid;          // 0..639
        if (s < 128) {
            int row = s >> 3, sg = s & 7;
            gsrc[i] = A + (size_t)row * KTOT + sg * 8;
            sdst[i] = SWZ128((uint32_t)(row * 128 + sg * 16));
        } else {
            int ss = s - 128;
            int row = ss >> 3, sg = ss & 7;
            gsrc[i] = Bt + (size_t)(bcol + row) * KTOT + sg * 8;
            sdst[i] = (uint32_t)A16TILE + SWZ128((uint32_t)(row * 128 + sg * 16));
        }
    }

    float acc[2][4];
    #pragma unroll
    for (int nt = 0; nt < 2; nt++)
        #pragma unroll
        for (int q = 0; q < 4; q++) acc[nt][q] = 0.f;

    int l15 = lane & 15, lhi = lane >> 4;

    #pragma unroll
    for (int st = 0; st < 2; st++) {
        uint32_t sb = dbase + st * S16STAGE;
        int k0 = st * KC16;
        #pragma unroll
        for (int i = 0; i < 5; i++) CP_ASYNC16(sb + sdst[i], gsrc[i] + k0);
        CP_COMMIT();
    }

    int stage = 0;
    for (int chunk = 0; chunk < NCHUNK16; chunk++) {
        if (chunk + 1 < NCHUNK16) CP_WAIT(1); else CP_WAIT(0);
        __syncthreads();
        if (chunk + 2 < NCHUNK16) {
            int ns = stage + 2; if (ns >= NSTAGE) ns -= NSTAGE;
            uint32_t sb = dbase + ns * S16STAGE;
            int k0 = (chunk + 2) * KC16;
            #pragma unroll
            for (int i = 0; i < 5; i++) CP_ASYNC16(sb + sdst[i], gsrc[i] + k0);
            CP_COMMIT();
        }
        uint32_t a_b = dbase + stage * S16STAGE;
        uint32_t b_b = a_b + A16TILE;
        #pragma unroll
        for (int kb = 0; kb < 4; kb++) {
            uint32_t kbyte = (uint32_t)(kb * 32 + lhi * 16);
            uint32_t a_f[4];
            {
                uint32_t off = SWZ128((uint32_t)(l15 * 128) + kbyte);
                LDSM_X4(a_f[0], a_f[1], a_f[2], a_f[3], a_b + off);
            }
            uint32_t off = SWZ128((uint32_t)((wn + l15) * 128) + kbyte);
            uint32_t r0, r1, r2, r3;
            uint32_t bhi0[2], bhi1[2];
            LDSM_X4(r0, r1, r2, r3, b_b + off);
            bhi0[0] = r0; bhi0[1] = r2; bhi1[0] = r1; bhi1[1] = r3;
            MMA16816(acc[0], a_f, bhi0);
            MMA16816(acc[1], a_f, bhi1);
        }
        stage++; if (stage >= NSTAGE) stage -= NSTAGE;
    }

    int r0 = lane >> 2, r1 = r0 + 8;
    float s0 = 0.f, s1 = 0.f;
    #pragma unroll
    for (int nt = 0; nt < 2; nt++) {
        int gc = bcol + wn + nt * 8 + (lane & 3) * 2;
        float v0 = acc[nt][0], v1 = acc[nt][1];
        float v2 = acc[nt][2], v3 = acc[nt][3];
        if (MODE == 0) {
            float sc0 = scale[gc], sc1 = scale[gc + 1];
            float m0 = v0 * sc0, m1 = v1 * sc1;
            float m2 = v2 * sc0, m3 = v3 * sc1;
            __half2 h0; h0.x = __float2half_rn(m0); h0.y = __float2half_rn(m1);
            __half2 h1; h1.x = __float2half_rn(m2); h1.y = __float2half_rn(m3);
            *(__half2*)(Aout + (size_t)r0 * KTOT + gc) = h0;
            *(__half2*)(Aout + (size_t)r1 * KTOT + gc) = h1;
            float b0 = bvec[gc], b1 = bvec[gc + 1];
            float bl0 = blv[gc], bl1 = blv[gc + 1];
            float bu0 = buv[gc], bu1 = buv[gc + 1];
            s0 += fmaxf(v0, 0.f) * bu0 + fminf(v0, 0.f) * bl0 + m0 * b0
                + fmaxf(v1, 0.f) * bu1 + fminf(v1, 0.f) * bl1 + m1 * b1;
            s1 += fmaxf(v2, 0.f) * bu0 + fminf(v2, 0.f) * bl0 + m2 * b0
                + fmaxf(v3, 0.f) * bu1 + fminf(v3, 0.f) * bl1 + m3 * b1;
        } else {
            if (gc < DIN) {
                float l0 = lin[gc], u0 = uin[gc];
                float l1 = lin[gc + 1], u1 = uin[gc + 1];
                s0 += fmaxf(v0, 0.f) * u0 + fminf(v0, 0.f) * l0
                    + fmaxf(v1, 0.f) * u1 + fminf(v1, 0.f) * l1;
                s1 += fmaxf(v2, 0.f) * u0 + fminf(v2, 0.f) * l0
                    + fmaxf(v3, 0.f) * u1 + fminf(v3, 0.f) * l1;
            }
        }
    }
    s0 += __shfl_xor_sync(0xffffffffu, s0, 1);
    s0 += __shfl_xor_sync(0xffffffffu, s0, 2);
    s1 += __shfl_xor_sync(0xffffffffu, s1, 1);
    s1 += __shfl_xor_sync(0xffffffffu, s1, 2);
    if ((lane & 3) == 0) {
        if (MODE == 0) {
            if (r0 < OUTR) atomicAdd(&bias4[r0], s0);
            if (r1 < OUTR) atomicAdd(&bias4[r1], s1);
        } else {
            if (r0 < OUTR) atomicAdd(&out[r0], s0);
            if (r1 < OUTR) atomicAdd(&out[r1], s1);
        }
    }
}

__global__ void final_add_k(const float* __restrict__ bias4,
                            const float* __restrict__ b4, const int* __restrict__ tl,
                            float* __restrict__ out) {
    int t = *tl;
    int r = threadIdx.x;
    if (r < OUTR) {
        int c = (r < t) ? r : r + 1;
        out[r] += bias4[r] + b4[c] - b4[t];
    }
}

// ---------------- launch ------------------------------------------------------
extern "C" void kernel_launch(void* const* d_in, const int* in_sizes, int n_in,
                              void* d_out, int out_size) {
    const float* W1 = (const float*)d_in[0];
    const float* b1 = (const float*)d_in[1];
    const float* W2 = (const float*)d_in[2];
    const float* b2 = (const float*)d_in[3];
    const float* W3 = (const float*)d_in[4];
    const float* b3 = (const float*)d_in[5];
    const float* W4 = (const float*)d_in[6];
    const float* b4 = (const float*)d_in[7];
    const float* l_in = (const float*)d_in[8];
    const float* u_in = (const float*)d_in[9];
    const float* p_l1 = (const float*)d_in[10];
    const float* p_u1 = (const float*)d_in[11];
    const float* p_l2 = (const float*)d_in[12];
    const float* p_u2 = (const float*)d_in[13];
    const float* p_l3 = (const float*)d_in[14];
    const float* p_u3 = (const float*)d_in[15];
    const int* tl = (const int*)d_in[16];
    float* out = (float*)d_out;

    cudaFuncSetAttribute(gemm_mma_k, cudaFuncAttributeMaxDynamicSharedMemorySize, DSMEM);
    cudaFuncSetAttribute(gemm_mid_mma_k, cudaFuncAttributeMaxDynamicSharedMemorySize, MDSMEM);
    cudaFuncSetAttribute(gemm16_k<0>, cudaFuncAttributeMaxDynamicSharedMemorySize, DSMEM16);
    cudaFuncSetAttribute(gemm16_k<1>, cudaFuncAttributeMaxDynamicSharedMemorySize, DSMEM16);

    float *T, *w1, *bl1, *bu1, *w2, *bl2, *bu2, *w3, *bl3, *bu3, *cl, *cu, *bias4;
    __half *Ahi, *W1th, *W2th, *W3th, *s4a, *s4b;
    cudaGetSymbolAddress((void**)&T, g_T);
    cudaGetSymbolAddress((void**)&Ahi, g_Ahi);
    cudaGetSymbolAddress((void**)&W1th, g_W1t_hi);
    cudaGetSymbolAddress((void**)&W2th, g_W2t_hi);
    cudaGetSymbolAddress((void**)&W3th, g_W3t_hi);
    cudaGetSymbolAddress((void**)&s4a, g_s4a);  cudaGetSymbolAddress((void**)&s4b, g_s4b);
    cudaGetSymbolAddress((void**)&w1, g_w1);   cudaGetSymbolAddress((void**)&bl1, g_bl1);
    cudaGetSymbolAddress((void**)&bu1, g_bu1);
    cudaGetSymbolAddress((void**)&w2, g_w2);   cudaGetSymbolAddress((void**)&bl2, g_bl2);
    cudaGetSymbolAddress((void**)&bu2, g_bu2);
    cudaGetSymbolAddress((void**)&w3, g_w3);   cudaGetSymbolAddress((void**)&bl3, g_bl3);
    cudaGetSymbolAddress((void**)&bu3, g_bu3);
    cudaGetSymbolAddress((void**)&cl, g_cl);   cudaGetSymbolAddress((void**)&cu, g_cu);
    cudaGetSymbolAddress((void**)&bias4, g_bias4);

    __half* Thi = (__half*)T;

    // upfront: merged transpose (W1/W2/W3 -> fp16 [N x K])
    transp3_k<<<dim3(KTOT / 64, H / 32, 3), dim3(32, 8)>>>(W1, W2, W3, W1th, W2th, W3th);

    dim3 gmid(NPAD1 / 128, H / 64);          // 7 x 32
    dim3 gbig(H / 128, H / 128);             // 16 x 16

    // ---- stage 1 (fused concretize + spu + stage-4 accumulator init) ----
    concretize_spu_k<<<H, 256>>>(W1, l_in, u_in, b1, p_l1, p_u1, w1, bl1, bu1, bias4, out);

    // ---- stage 2 ----
    bias2conv_k<<<H, 512>>>(W2, w1, bl1, bu1, b2, b1, cl, cu, Ahi);
    gemm_mid_mma_k<<<gmid, 256, MDSMEM>>>(Ahi, W1th, cl, cu, l_in, u_in);
    spu_params_k<<<(H + 63) / 64, 64>>>(cl, cu, p_l2, p_u2, w2, bl2, bu2, H);

    // ---- stage 3 ----
    bias2conv_k<<<H, 512>>>(W3, w2, bl2, bu2, b3, b2, cl, cu, Ahi);
    gemm_mma_k<<<gbig, 256, DSMEM>>>(Ahi, W2th, Thi, w1, b1, bl1, bu1, cl, cu);
    gemm_mid_mma_k<<<gmid, 256, MDSMEM>>>(Thi, W1th, cl, cu, l_in, u_in);
    spu_params_k<<<(H + 63) / 64, 64>>>(cl, cu, p_l3, p_u3, w3, bl3, bu3, H);

    // ---- stage 4: tensor-core chain, fused bias epilogues ----
    build_m4conv_k<<<16 * 8, 256>>>(W4, tl, w3, bl3, bu3, b3, s4a, bias4);
    gemm16_k<0><<<H / 64, 128, DSMEM16>>>(s4a, W3th, s4b,
                                          w2, b2, bl2, bu2, bias4, nullptr, nullptr, nullptr);
    gemm16_k<0><<<H / 64, 128, DSMEM16>>>(s4b, W2th, s4a,
                                          w1, b1, bl1, bu1, bias4, nullptr, nullptr, nullptr);
    gemm16_k<1><<<NPAD1 / 64, 128, DSMEM16>>>(s4a, W1th, nullptr,
                                              nullptr, nullptr, nullptr, nullptr, nullptr,
                                              l_in, u_in, out);
    final_add_k<<<1, 32>>>(bias4, b4, tl, out);
}